// round 10
// baseline (speedup 1.0000x reference)
#include <cuda_runtime.h>
#include <cuda_bf16.h>
#include <cstdint>
#include <math.h>

#define TLEN   2048
#define FDIM   256
#define NHEAD  8
#define NBATCH 4
#define NBH    32

typedef __nv_bfloat16 bf16;

// ---------------- scratch (__device__ globals; no allocation allowed) ----------------
__device__ __align__(16) bf16 g_xh [(size_t)NBATCH * TLEN * FDIM];
__device__ __align__(16) bf16 g_xl [(size_t)NBATCH * TLEN * FDIM];
__device__ __align__(16) bf16 g_Wqh[(size_t)(NHEAD * FDIM * 3) * FDIM];   // permuted WqkvT hi [6144][256]
__device__ __align__(16) bf16 g_Wql[(size_t)(NHEAD * FDIM * 3) * FDIM];
__device__ __align__(16) bf16 g_Wph[(size_t)FDIM * (NHEAD * FDIM)];       // WprojT hi [256][2048]
__device__ __align__(16) bf16 g_Wpl[(size_t)FDIM * (NHEAD * FDIM)];
__device__ __align__(16) bf16 g_Qh [(size_t)NBH * TLEN * FDIM];           // [bh][t][f]  (hi only)
__device__ __align__(16) bf16 g_Kh [(size_t)NBH * TLEN * FDIM];           // (hi only)
__device__ __align__(16) bf16 g_Vnh[(size_t)NBH * TLEN * FDIM];           // V natural [bh][t][f]
__device__ __align__(16) bf16 g_Vnl[(size_t)NBH * TLEN * FDIM];
__device__ __align__(16) bf16 g_Vth[(size_t)NBH * FDIM * TLEN];           // V transposed [bh][f][t]
__device__ __align__(16) bf16 g_Vtl[(size_t)NBH * FDIM * TLEN];
__device__ __align__(16) float g_S [(size_t)NBH * TLEN * TLEN];           // fp32 scores
__device__ __align__(16) bf16 g_Ph [(size_t)NBH * TLEN * TLEN];           // probs hi
__device__ __align__(16) bf16 g_Pl [(size_t)NBH * TLEN * TLEN];           // probs lo
__device__ __align__(16) bf16 g_ah [(size_t)NBATCH * TLEN * NHEAD * FDIM];// attn hi [b][t][h*f]
__device__ __align__(16) bf16 g_al [(size_t)NBATCH * TLEN * NHEAD * FDIM];

// ---------------- helpers ----------------
__device__ __forceinline__ uint32_t smem_u32(const void* p) {
    uint32_t a;
    asm("{ .reg .u64 t; cvta.to.shared.u64 t, %1; cvt.u32.u64 %0, t; }" : "=r"(a) : "l"(p));
    return a;
}
__device__ __forceinline__ void cp_async16(uint32_t dst, const void* src) {
    asm volatile("cp.async.cg.shared.global [%0], [%1], 16;" :: "r"(dst), "l"(src) : "memory");
}
__device__ __forceinline__ void cp_commit() {
    asm volatile("cp.async.commit_group;" ::: "memory");
}
template<int N> __device__ __forceinline__ void cp_wait() {
    asm volatile("cp.async.wait_group %0;" :: "n"(N) : "memory");
}
__device__ __forceinline__ void mma_bf16(float* c, const uint32_t* a, const uint32_t* b) {
    asm volatile(
        "mma.sync.aligned.m16n8k16.row.col.f32.bf16.bf16.f32 "
        "{%0,%1,%2,%3}, {%4,%5,%6,%7}, {%8,%9}, {%0,%1,%2,%3};"
        : "+f"(c[0]), "+f"(c[1]), "+f"(c[2]), "+f"(c[3])
        : "r"(a[0]), "r"(a[1]), "r"(a[2]), "r"(a[3]), "r"(b[0]), "r"(b[1]));
}
__device__ __forceinline__ void ldmx4(uint32_t& r0, uint32_t& r1, uint32_t& r2, uint32_t& r3,
                                      uint32_t addr) {
    asm volatile("ldmatrix.sync.aligned.m8n8.x4.shared.b16 {%0,%1,%2,%3}, [%4];"
                 : "=r"(r0), "=r"(r1), "=r"(r2), "=r"(r3) : "r"(addr));
}
__device__ __forceinline__ uint32_t pack_hi(float lo, float hi) {
    uint32_t h;
    asm("cvt.rn.bf16x2.f32 %0, %1, %2;" : "=r"(h) : "f"(hi), "f"(lo));
    return h;
}
// split fp32 pair -> packed bf16x2 hi + bf16x2 lo residual (.x in low half)
__device__ __forceinline__ void split_pair(float2 f, uint32_t& hi, uint32_t& lo) {
    uint32_t h;
    asm("cvt.rn.bf16x2.f32 %0, %1, %2;" : "=r"(h) : "f"(f.y), "f"(f.x));
    const float h0 = __uint_as_float(h << 16);
    const float h1 = __uint_as_float(h & 0xffff0000u);
    asm("cvt.rn.bf16x2.f32 %0, %1, %2;" : "=r"(lo) : "f"(f.y - h1), "f"(f.x - h0));
    hi = h;
}
__device__ __forceinline__ void split1(float v, bf16& h, bf16& l) {
    h = __float2bfloat16(v);
    l = __float2bfloat16(v - __bfloat162float(h));
}

// ---------------- GEMM config ----------------
constexpr int BM = 128, BN = 128, BK = 32;
constexpr int SROWW = 20;                              // words/row (16 data + 4 pad): conflict-free
constexpr int TILE_WORDS = BM * SROWW;                 // 2560
constexpr int TILE_BYTES = TILE_WORDS * 4;             // 10240
constexpr int SMEM_FULL  = 2 * 4 * TILE_BYTES;         // 81920 (Ah,Al,Bh,Bl x 2 stages)
constexpr int SMEM_HI    = 2 * 2 * TILE_BYTES;         // 40960 (Ah,Bh x 2 stages)

// MODE 0: C[8192,6144] = x @ WqkvT'^T   (K=256)  -> Q/K hi (+bias,*1/16), V split natural
// MODE 1: C[2048,2048] = Qh @ Kh^T      (K=256)  -> g_S fp32  (hi-only, 1 MMA)
// MODE 2: C[2048, 256] = P @ Vt^T       (K=2048) -> split g_ah/g_al
// MODE 3: C[8192, 256] = attn @ WprojT^T(K=2048) -> d_out fp32 (+bias)
template<int MODE>
__global__ void __launch_bounds__(256, 2)
mma_gemm(const float* __restrict__ bias, float* __restrict__ Cgp)
{
    constexpr int NTERMS = (MODE == 1) ? 1 : 3;
    constexpr int TILES  = (NTERMS == 1) ? 2 : 4;
    constexpr int K  = (MODE == 0 || MODE == 1) ? 256 : 2048;
    constexpr int KT = K / BK;
    constexpr int STAGE_BYTES = TILES * TILE_BYTES;
    // tile slots: NTERMS==3: Ah=0, Al=1, Bh=2, Bl=3 ; NTERMS==1: Ah=0, Bh=1
    constexpr int SLOT_BH = (NTERMS == 1) ? 1 : 2;

    extern __shared__ uint32_t smem_w[];
    const uint32_t sbase = smem_u32(smem_w);

    const int tid = threadIdx.x;
    const int wid = tid >> 5, lid = tid & 31;
    const int z = blockIdx.z;
    const int rowBase = blockIdx.y * BM;
    const int colBase = blockIdx.x * BN;

    const bf16 *Ah, *Al = nullptr, *Bh, *Bl = nullptr;
    if (MODE == 0) {
        Ah = g_xh;  Al = g_xl;  Bh = g_Wqh; Bl = g_Wql;
    } else if (MODE == 1) {
        const size_t o = (size_t)z * TLEN * FDIM;
        Ah = g_Qh + o; Bh = g_Kh + o;
    } else if (MODE == 2) {
        const size_t oa = (size_t)z * TLEN * TLEN;
        const size_t ob = (size_t)z * FDIM * TLEN;
        Ah = g_Ph + oa; Al = g_Pl + oa; Bh = g_Vth + ob; Bl = g_Vtl + ob;
    } else {
        Ah = g_ah;  Al = g_al;  Bh = g_Wph; Bl = g_Wpl;
    }
    Ah += (size_t)rowBase * K;
    Bh += (size_t)colBase * K;
    if (NTERMS == 3) { Al += (size_t)rowBase * K; Bl += (size_t)colBase * K; }

    // loader: per tile 512 chunks of 16B; 256 threads x 2
    auto load_tile = [&](int kt, int s) {
        const uint32_t base = sbase + s * STAGE_BYTES;
        const int kofs = kt * BK;
        #pragma unroll
        for (int i = 0; i < 2; ++i) {
            const int f   = tid + 256 * i;
            const int row = f >> 2;
            const int c16 = f & 3;
            const uint32_t so = (uint32_t)(row * SROWW + c16 * 4) * 4;
            const size_t go = (size_t)row * K + kofs + c16 * 8;
            cp_async16(base + so,                         Ah + go);
            cp_async16(base + SLOT_BH * TILE_BYTES + so,  Bh + go);
            if (NTERMS == 3) {
                cp_async16(base + 1 * TILE_BYTES + so,    Al + go);
                cp_async16(base + 3 * TILE_BYTES + so,    Bl + go);
            }
        }
        cp_commit();
    };

    const int warp_m = wid & 3;   // 4 warps x 32 rows
    const int warp_n = wid >> 2;  // 2 warps x 64 cols
    const int gid = lid >> 2;     // 0..7
    const int tig = lid & 3;      // 0..3

    // ldmatrix per-lane offsets (in words, within a tile)
    //  A x4: m0 rows+0 k+0 | m1 rows+8 k+0 | m2 rows+0 k+4w | m3 rows+8 k+4w
    const int a_lane = ((lid & 7) + ((lid >> 3) & 1) * 8) * SROWW + (lid >> 4) * 4;
    //  B x4: m0 cols+0 k+0 | m1 cols+0 k+4w | m2 cols+8 k+0 | m3 cols+8 k+4w
    const int b_lane = ((lid & 7) + ((lid >> 4) & 1) * 8) * SROWW + ((lid >> 3) & 1) * 4;

    const uint32_t aAh0 = sbase + (uint32_t)(32 * warp_m * SROWW + a_lane) * 4;
    const uint32_t aBh0 = sbase + SLOT_BH * TILE_BYTES + (uint32_t)(64 * warp_n * SROWW + b_lane) * 4;

    float acc[2][8][4];
    #pragma unroll
    for (int i = 0; i < 2; ++i)
        #pragma unroll
        for (int j = 0; j < 8; ++j)
            #pragma unroll
            for (int c = 0; c < 4; ++c) acc[i][j][c] = 0.f;

    load_tile(0, 0);

    #pragma unroll 1
    for (int kt = 0; kt < KT; ++kt) {
        const int s = kt & 1;
        cp_wait<0>();
        __syncthreads();                       // publish tile kt; all done computing kt-1
        if (kt + 1 < KT) load_tile(kt + 1, s ^ 1);

        const uint32_t aAh = aAh0 + s * STAGE_BYTES;
        const uint32_t aBh = aBh0 + s * STAGE_BYTES;

        #pragma unroll
        for (int ks = 0; ks < 2; ++ks) {             // two m16n8k16 K-steps per BK=32
            const uint32_t kadd = (uint32_t)(ks * 8) * 4;

            uint32_t ah[2][4], al[2][4];
            #pragma unroll
            for (int i = 0; i < 2; ++i) {
                const uint32_t a0 = aAh + (uint32_t)(16 * i * SROWW) * 4 + kadd;
                ldmx4(ah[i][0], ah[i][1], ah[i][2], ah[i][3], a0);
                if (NTERMS == 3)
                    ldmx4(al[i][0], al[i][1], al[i][2], al[i][3], a0 + TILE_BYTES);
            }

            #pragma unroll
            for (int jh = 0; jh < 2; ++jh) {         // halves of 4 columns (reg pressure)
                uint32_t bh[4][2], bl[4][2];
                #pragma unroll
                for (int jp = 0; jp < 2; ++jp) {     // j-pairs: cols 8J..8J+15
                    const int J = jh * 4 + jp * 2;
                    const uint32_t b0 = aBh + (uint32_t)(8 * J * SROWW) * 4 + kadd;
                    ldmx4(bh[2*jp][0], bh[2*jp][1], bh[2*jp+1][0], bh[2*jp+1][1], b0);
                    if (NTERMS == 3)
                        ldmx4(bl[2*jp][0], bl[2*jp][1], bl[2*jp+1][0], bl[2*jp+1][1],
                              b0 + TILE_BYTES);
                }
                #pragma unroll
                for (int i = 0; i < 2; ++i)
                    #pragma unroll
                    for (int j = 0; j < 4; ++j) {
                        float* c = acc[i][jh * 4 + j];
                        mma_bf16(c, ah[i], bh[j]);           // hi*hi
                        if (NTERMS == 3) {
                            mma_bf16(c, ah[i], bl[j]);       // hi*lo
                            mma_bf16(c, al[i], bh[j]);       // lo*hi
                        }
                    }
            }
        }
    }

    // ---------------- epilogue ----------------
    const int gm = rowBase + 32 * warp_m;
    const int gn = colBase + 64 * warp_n + 2 * tig;

    if (MODE == 0) {
        // permuted columns: jj = part*2048 + h*256 + f ; part & head uniform per CTA
        const int part  = colBase >> 11;
        const int hh    = (colBase >> 8) & 7;
        const int fwarp = (colBase & 255) + 64 * warp_n + 2 * tig;
        const float scl = (part == 2) ? 1.0f : 0.0625f;

        #pragma unroll
        for (int i = 0; i < 2; ++i) {
            #pragma unroll
            for (int h = 0; h < 2; ++h) {
                const int m = gm + 16 * i + gid + 8 * h;
                const int b = m >> 11, t = m & (TLEN - 1);
                const size_t rowO = ((size_t)(b * NHEAD + hh) * TLEN + t) * FDIM;
                #pragma unroll
                for (int j = 0; j < 8; ++j) {
                    const int f0 = fwarp + 8 * j;
                    const int borig = hh * (FDIM * 3) + f0 * 3 + part;
                    float v0 = (acc[i][j][2 * h]     + bias[borig])     * scl;
                    float v1 = (acc[i][j][2 * h + 1] + bias[borig + 3]) * scl;
                    if (part == 0) {
                        *(uint32_t*)(g_Qh + rowO + f0) = pack_hi(v0, v1);
                    } else if (part == 1) {
                        *(uint32_t*)(g_Kh + rowO + f0) = pack_hi(v0, v1);
                    } else {
                        uint32_t hw, lw;
                        split_pair(make_float2(v0, v1), hw, lw);
                        *(uint32_t*)(g_Vnh + rowO + f0) = hw;
                        *(uint32_t*)(g_Vnl + rowO + f0) = lw;
                    }
                }
            }
        }
        return;
    }

    #pragma unroll
    for (int i = 0; i < 2; ++i) {
        #pragma unroll
        for (int h = 0; h < 2; ++h) {
            const int m = gm + 16 * i + gid + 8 * h;

            if (MODE == 1) {
                float* p = g_S + (size_t)z * TLEN * TLEN + (size_t)m * TLEN + gn;
                #pragma unroll
                for (int j = 0; j < 8; ++j)
                    *(float2*)(p + 8 * j) = make_float2(acc[i][j][2 * h], acc[i][j][2 * h + 1]);
            } else if (MODE == 2) {
                const int b = z >> 3, hh = z & 7;
                const size_t base = ((size_t)(b * TLEN + m)) * (NHEAD * FDIM) + hh * FDIM + gn;
                #pragma unroll
                for (int j = 0; j < 8; ++j) {
                    uint32_t hw, lw;
                    split_pair(make_float2(acc[i][j][2 * h], acc[i][j][2 * h + 1]), hw, lw);
                    *(uint32_t*)(g_ah + base + 8 * j) = hw;
                    *(uint32_t*)(g_al + base + 8 * j) = lw;
                }
            } else {
                float* p = Cgp + (size_t)m * FDIM + gn;
                #pragma unroll
                for (int j = 0; j < 8; ++j)
                    *(float2*)(p + 8 * j) = make_float2(acc[i][j][2 * h]     + bias[gn + 8 * j],
                                                        acc[i][j][2 * h + 1] + bias[gn + 8 * j + 1]);
            }
        }
    }
}

// ---------------- input split: x -> g_xh/g_xl ----------------
__global__ void __launch_bounds__(256) split_x_kernel(const float* __restrict__ x)
{
    const size_t i = ((size_t)blockIdx.x * 256 + threadIdx.x) * 4;
    const float4 v = *(const float4*)(x + i);
    uint32_t h0, l0, h1, l1;
    split_pair(make_float2(v.x, v.y), h0, l0);
    split_pair(make_float2(v.z, v.w), h1, l1);
    *(uint32_t*)(g_xh + i)     = h0;
    *(uint32_t*)(g_xh + i + 2) = h1;
    *(uint32_t*)(g_xl + i)     = l0;
    *(uint32_t*)(g_xl + i + 2) = l1;
}

// ---------------- W_qkv transpose + column permutation + split ----------------
// in:  W_qkv [256][6144], col_orig = h*768 + f*3 + part
// out: g_Wqh/g_Wql [6144][256], row (col_new) = part*2048 + h*256 + f
__global__ void __launch_bounds__(256) wqkv_prep_kernel(const float* __restrict__ in)
{
    __shared__ float t[32][33];
    const int c0 = blockIdx.x * 32;
    const int r0 = blockIdx.y * 32;
    const int tx = threadIdx.x, ty = threadIdx.y;
    #pragma unroll
    for (int i = 0; i < 32; i += 8)
        t[ty + i][tx] = in[(size_t)(r0 + ty + i) * (NHEAD * FDIM * 3) + c0 + tx];
    __syncthreads();
    #pragma unroll
    for (int i = 0; i < 32; i += 8) {
        const int corig = c0 + ty + i;
        const int hh  = corig / (FDIM * 3);
        const int rem = corig - hh * (FDIM * 3);
        const int f   = rem / 3;
        const int prt = rem - f * 3;
        const int cnew = prt * (NHEAD * FDIM) + hh * FDIM + f;
        bf16 vh, vl;
        split1(t[tx][ty + i], vh, vl);
        g_Wqh[(size_t)cnew * FDIM + r0 + tx] = vh;
        g_Wql[(size_t)cnew * FDIM + r0 + tx] = vl;
    }
}

// ---------------- W_proj transpose + split: [2048][256] -> [256][2048] ----------------
__global__ void __launch_bounds__(256) wproj_prep_kernel(const float* __restrict__ in)
{
    __shared__ float t[32][33];
    const int c0 = blockIdx.x * 32;   // cols of in (256)
    const int r0 = blockIdx.y * 32;   // rows of in (2048)
    const int tx = threadIdx.x, ty = threadIdx.y;
    #pragma unroll
    for (int i = 0; i < 32; i += 8)
        t[ty + i][tx] = in[(size_t)(r0 + ty + i) * FDIM + c0 + tx];
    __syncthreads();
    #pragma unroll
    for (int i = 0; i < 32; i += 8) {
        bf16 vh, vl;
        split1(t[tx][ty + i], vh, vl);
        g_Wph[(size_t)(c0 + ty + i) * (NHEAD * FDIM) + r0 + tx] = vh;
        g_Wpl[(size_t)(c0 + ty + i) * (NHEAD * FDIM) + r0 + tx] = vl;
    }
}

// ---------------- V transpose: [bh][t][f] -> [bh][f][t] (hi & lo) ----------------
__global__ void __launch_bounds__(256) vtrans_kernel()
{
    __shared__ bf16 th[32][33], tl[32][33];
    const int bh = blockIdx.z;
    const int f0 = blockIdx.x * 32;
    const int t0 = blockIdx.y * 32;
    const int tx = threadIdx.x, ty = threadIdx.y;
    const size_t inb = ((size_t)bh * TLEN + t0) * FDIM + f0;
    #pragma unroll
    for (int i = 0; i < 32; i += 8) {
        th[ty + i][tx] = g_Vnh[inb + (size_t)(ty + i) * FDIM + tx];
        tl[ty + i][tx] = g_Vnl[inb + (size_t)(ty + i) * FDIM + tx];
    }
    __syncthreads();
    const size_t outb = ((size_t)bh * FDIM + f0) * TLEN + t0;
    #pragma unroll
    for (int i = 0; i < 32; i += 8) {
        g_Vth[outb + (size_t)(ty + i) * TLEN + tx] = th[tx][ty + i];
        g_Vtl[outb + (size_t)(ty + i) * TLEN + tx] = tl[tx][ty + i];
    }
}

// ---------------- softmax: 65536 rows of 2048; write split bf16 probs ----------------
__global__ void __launch_bounds__(256) softmax_kernel()
{
    const size_t row = blockIdx.x;
    const float* p = g_S + row * (size_t)TLEN;
    const int t = threadIdx.x;

    float4 v0 = ((const float4*)p)[t];
    float4 v1 = ((const float4*)p)[t + 256];

    float m = fmaxf(fmaxf(fmaxf(v0.x, v0.y), fmaxf(v0.z, v0.w)),
                    fmaxf(fmaxf(v1.x, v1.y), fmaxf(v1.z, v1.w)));
    #pragma unroll
    for (int o = 16; o; o >>= 1) m = fmaxf(m, __shfl_xor_sync(0xffffffffu, m, o));

    __shared__ float red[8];
    const int warp = t >> 5, lane = t & 31;
    if (lane == 0) red[warp] = m;
    __syncthreads();
    float bm = red[0];
    #pragma unroll
    for (int i = 1; i < 8; ++i) bm = fmaxf(bm, red[i]);
    __syncthreads();

    v0.x = __expf(v0.x - bm); v0.y = __expf(v0.y - bm);
    v0.z = __expf(v0.z - bm); v0.w = __expf(v0.w - bm);
    v1.x = __expf(v1.x - bm); v1.y = __expf(v1.y - bm);
    v1.z = __expf(v1.z - bm); v1.w = __expf(v1.w - bm);

    float s = v0.x + v0.y + v0.z + v0.w + v1.x + v1.y + v1.z + v1.w;
    #pragma unroll
    for (int o = 16; o; o >>= 1) s += __shfl_xor_sync(0xffffffffu, s, o);
    if (lane == 0) red[warp] = s;
    __syncthreads();
    float bs = 0.f;
    #pragma unroll
    for (int i = 0; i < 8; ++i) bs += red[i];

    const float inv = 1.0f / bs;
    v0.x *= inv; v0.y *= inv; v0.z *= inv; v0.w *= inv;
    v1.x *= inv; v1.y *= inv; v1.z *= inv; v1.w *= inv;

    uint32_t* ph = (uint32_t*)(g_Ph + row * (size_t)TLEN);
    uint32_t* pl = (uint32_t*)(g_Pl + row * (size_t)TLEN);
    uint32_t hw, lw;
    split_pair(make_float2(v0.x, v0.y), hw, lw); ph[2 * t]       = hw; pl[2 * t]       = lw;
    split_pair(make_float2(v0.z, v0.w), hw, lw); ph[2 * t + 1]   = hw; pl[2 * t + 1]   = lw;
    split_pair(make_float2(v1.x, v1.y), hw, lw); ph[2 * t + 512] = hw; pl[2 * t + 512] = lw;
    split_pair(make_float2(v1.z, v1.w), hw, lw); ph[2 * t + 513] = hw; pl[2 * t + 513] = lw;
}

// ---------------- launch ----------------
extern "C" void kernel_launch(void* const* d_in, const int* in_sizes, int n_in,
                              void* d_out, int out_size)
{
    const float* x     = (const float*)d_in[0];
    const float* Wqkv  = (const float*)d_in[1];
    const float* bqkv  = (const float*)d_in[2];
    const float* Wproj = (const float*)d_in[3];
    const float* bproj = (const float*)d_in[4];
    float* out = (float*)d_out;

    cudaFuncSetAttribute(mma_gemm<0>, cudaFuncAttributeMaxDynamicSharedMemorySize, SMEM_FULL);
    cudaFuncSetAttribute(mma_gemm<1>, cudaFuncAttributeMaxDynamicSharedMemorySize, SMEM_HI);
    cudaFuncSetAttribute(mma_gemm<2>, cudaFuncAttributeMaxDynamicSharedMemorySize, SMEM_FULL);
    cudaFuncSetAttribute(mma_gemm<3>, cudaFuncAttributeMaxDynamicSharedMemorySize, SMEM_FULL);

    // prep: split x; transpose(+permute)+split weights
    split_x_kernel<<<(NBATCH * TLEN * FDIM) / 1024, 256>>>(x);
    wqkv_prep_kernel<<<dim3(6144 / 32, 256 / 32), dim3(32, 8)>>>(Wqkv);
    wproj_prep_kernel<<<dim3(256 / 32, 2048 / 32), dim3(32, 8)>>>(Wproj);

    // 1) QKV GEMM (+bias, scale) -> Qh/Kh hi, V split natural
    mma_gemm<0><<<dim3(6144 / BN, 8192 / BM, 1), 256, SMEM_FULL>>>(bqkv, nullptr);
    // 1b) V transpose -> Vth/Vtl
    vtrans_kernel<<<dim3(FDIM / 32, TLEN / 32, NBH), dim3(32, 8)>>>();
    // 2) scores = Qh Kh^T (hi-only, batched over 32 bh) -> fp32 S
    mma_gemm<1><<<dim3(TLEN / BN, TLEN / BM, NBH), 256, SMEM_HI>>>(nullptr, nullptr);
    // 3) softmax -> split bf16 P
    softmax_kernel<<<NBH * TLEN, 256>>>();
    // 4) out = P V (batched, NT against Vt) -> split bf16 attn
    mma_gemm<2><<<dim3(FDIM / BN, TLEN / BM, NBH), 256, SMEM_FULL>>>(nullptr, nullptr);
    // 5) proj (+bias) -> fp32 out
    mma_gemm<3><<<dim3(FDIM / BN, 8192 / BM, 1), 256, SMEM_FULL>>>(bproj, out);
}

// round 11
// speedup vs baseline: 1.4611x; 1.4611x over previous
#include <cuda_runtime.h>
#include <cuda_bf16.h>
#include <cstdint>
#include <math.h>

#define TLEN   2048
#define FDIM   256
#define NHEAD  8
#define NBATCH 4
#define NBH    32

typedef __nv_bfloat16 bf16;

// ---------------- scratch (__device__ globals; no allocation allowed) ----------------
__device__ __align__(16) bf16 g_xh [(size_t)NBATCH * TLEN * FDIM];
__device__ __align__(16) bf16 g_xl [(size_t)NBATCH * TLEN * FDIM];
__device__ __align__(16) bf16 g_Wqh[(size_t)(NHEAD * FDIM * 3) * FDIM];   // permuted WqkvT hi [6144][256]
__device__ __align__(16) bf16 g_Wql[(size_t)(NHEAD * FDIM * 3) * FDIM];
__device__ __align__(16) bf16 g_Wph[(size_t)FDIM * (NHEAD * FDIM)];       // WprojT hi [256][2048]
__device__ __align__(16) bf16 g_Wpl[(size_t)FDIM * (NHEAD * FDIM)];
__device__ __align__(16) bf16 g_Qh [(size_t)NBH * TLEN * FDIM];           // [bh][t][f]  (hi only)
__device__ __align__(16) bf16 g_Kh [(size_t)NBH * TLEN * FDIM];           // (hi only)
__device__ __align__(16) bf16 g_Vnh[(size_t)NBH * TLEN * FDIM];           // V natural [bh][t][f]
__device__ __align__(16) bf16 g_Vnl[(size_t)NBH * TLEN * FDIM];
__device__ __align__(16) bf16 g_Vth[(size_t)NBH * FDIM * TLEN];           // V transposed [bh][f][t]
__device__ __align__(16) bf16 g_Vtl[(size_t)NBH * FDIM * TLEN];
__device__ __align__(16) float g_S [(size_t)NBH * TLEN * TLEN];           // fp32 scores
__device__ __align__(16) bf16 g_Ph [(size_t)NBH * TLEN * TLEN];           // probs hi
__device__ __align__(16) bf16 g_Pl [(size_t)NBH * TLEN * TLEN];           // probs lo
__device__ __align__(16) bf16 g_ah [(size_t)NBATCH * TLEN * NHEAD * FDIM];// attn hi [b][t][h*f]
__device__ __align__(16) bf16 g_al [(size_t)NBATCH * TLEN * NHEAD * FDIM];

// ---------------- helpers ----------------
__device__ __forceinline__ uint32_t smem_u32(const void* p) {
    uint32_t a;
    asm("{ .reg .u64 t; cvta.to.shared.u64 t, %1; cvt.u32.u64 %0, t; }" : "=r"(a) : "l"(p));
    return a;
}
__device__ __forceinline__ void cp_async16(uint32_t dst, const void* src) {
    asm volatile("cp.async.cg.shared.global [%0], [%1], 16;" :: "r"(dst), "l"(src) : "memory");
}
__device__ __forceinline__ void cp_commit() {
    asm volatile("cp.async.commit_group;" ::: "memory");
}
template<int N> __device__ __forceinline__ void cp_wait() {
    asm volatile("cp.async.wait_group %0;" :: "n"(N) : "memory");
}
__device__ __forceinline__ void mma_bf16(float* c, const uint32_t* a, const uint32_t* b) {
    asm volatile(
        "mma.sync.aligned.m16n8k16.row.col.f32.bf16.bf16.f32 "
        "{%0,%1,%2,%3}, {%4,%5,%6,%7}, {%8,%9}, {%0,%1,%2,%3};"
        : "+f"(c[0]), "+f"(c[1]), "+f"(c[2]), "+f"(c[3])
        : "r"(a[0]), "r"(a[1]), "r"(a[2]), "r"(a[3]), "r"(b[0]), "r"(b[1]));
}
__device__ __forceinline__ void ldmx4(uint32_t& r0, uint32_t& r1, uint32_t& r2, uint32_t& r3,
                                      uint32_t addr) {
    asm volatile("ldmatrix.sync.aligned.m8n8.x4.shared.b16 {%0,%1,%2,%3}, [%4];"
                 : "=r"(r0), "=r"(r1), "=r"(r2), "=r"(r3) : "r"(addr));
}
__device__ __forceinline__ uint32_t pack_hi(float lo, float hi) {
    uint32_t h;
    asm("cvt.rn.bf16x2.f32 %0, %1, %2;" : "=r"(h) : "f"(hi), "f"(lo));
    return h;
}
// split fp32 pair -> packed bf16x2 hi + bf16x2 lo residual (.x in low half)
__device__ __forceinline__ void split_pair(float2 f, uint32_t& hi, uint32_t& lo) {
    uint32_t h;
    asm("cvt.rn.bf16x2.f32 %0, %1, %2;" : "=r"(h) : "f"(f.y), "f"(f.x));
    const float h0 = __uint_as_float(h << 16);
    const float h1 = __uint_as_float(h & 0xffff0000u);
    asm("cvt.rn.bf16x2.f32 %0, %1, %2;" : "=r"(lo) : "f"(f.y - h1), "f"(f.x - h0));
    hi = h;
}
__device__ __forceinline__ void split1(float v, bf16& h, bf16& l) {
    h = __float2bfloat16(v);
    l = __float2bfloat16(v - __bfloat162float(h));
}

// ---------------- GEMM config ----------------
constexpr int BM = 128, BN = 128, BK = 32;
constexpr int SROWW = 20;                              // words/row (16 data + 4 pad): conflict-free, 16B-aligned rows
constexpr int TILE_WORDS = BM * SROWW;                 // 2560
constexpr int TILE_BYTES = TILE_WORDS * 4;             // 10240
constexpr int SMEM_FULL  = 2 * 4 * TILE_BYTES;         // 81920 (Ah,Al,Bh,Bl x 2 stages)
constexpr int SMEM_HI    = 2 * 2 * TILE_BYTES;         // 40960 (Ah,Bh x 2 stages)

// MODE 0: C[8192,6144] = x @ WqkvT'^T   (K=256)  -> Q/K hi (+bias,*1/16), V split natural
// MODE 1: C[2048,2048] = Qh @ Kh^T      (K=256)  -> g_S fp32  (hi-only, 1 MMA)
// MODE 2: C[2048, 256] = P @ Vt^T       (K=2048) -> split g_ah/g_al
// MODE 3: C[8192, 256] = attn @ WprojT^T(K=2048) -> d_out fp32 (+bias)
template<int MODE>
__global__ void __launch_bounds__(256, 2)
mma_gemm(const float* __restrict__ bias, float* __restrict__ Cgp)
{
    constexpr int NTERMS = (MODE == 1) ? 1 : 3;
    constexpr int TILES  = (NTERMS == 1) ? 2 : 4;
    constexpr int K  = (MODE == 0 || MODE == 1) ? 256 : 2048;
    constexpr int KT = K / BK;
    constexpr int STAGE_BYTES = TILES * TILE_BYTES;
    // tile slots: NTERMS==3: Ah=0, Al=1, Bh=2, Bl=3 ; NTERMS==1: Ah=0, Bh=1
    constexpr int SLOT_BH = (NTERMS == 1) ? 1 : 2;

    extern __shared__ uint32_t smem_w[];
    const uint32_t sbase = smem_u32(smem_w);

    const int tid = threadIdx.x;
    const int wid = tid >> 5, lid = tid & 31;
    const int z = blockIdx.z;
    const int rowBase = blockIdx.y * BM;
    const int colBase = blockIdx.x * BN;

    const bf16 *Ah, *Al = nullptr, *Bh, *Bl = nullptr;
    if (MODE == 0) {
        Ah = g_xh;  Al = g_xl;  Bh = g_Wqh; Bl = g_Wql;
    } else if (MODE == 1) {
        const size_t o = (size_t)z * TLEN * FDIM;
        Ah = g_Qh + o; Bh = g_Kh + o;
    } else if (MODE == 2) {
        const size_t oa = (size_t)z * TLEN * TLEN;
        const size_t ob = (size_t)z * FDIM * TLEN;
        Ah = g_Ph + oa; Al = g_Pl + oa; Bh = g_Vth + ob; Bl = g_Vtl + ob;
    } else {
        Ah = g_ah;  Al = g_al;  Bh = g_Wph; Bl = g_Wpl;
    }
    Ah += (size_t)rowBase * K;
    Bh += (size_t)colBase * K;
    if (NTERMS == 3) { Al += (size_t)rowBase * K; Bl += (size_t)colBase * K; }

    // loader: per tile 512 chunks of 16B; 256 threads x 2
    auto load_tile = [&](int kt, int s) {
        const uint32_t base = sbase + s * STAGE_BYTES;
        const int kofs = kt * BK;
        #pragma unroll
        for (int i = 0; i < 2; ++i) {
            const int f   = tid + 256 * i;
            const int row = f >> 2;
            const int c16 = f & 3;
            const uint32_t so = (uint32_t)(row * SROWW + c16 * 4) * 4;
            const size_t go = (size_t)row * K + kofs + c16 * 8;
            cp_async16(base + so,                         Ah + go);
            cp_async16(base + SLOT_BH * TILE_BYTES + so,  Bh + go);
            if (NTERMS == 3) {
                cp_async16(base + 1 * TILE_BYTES + so,    Al + go);
                cp_async16(base + 3 * TILE_BYTES + so,    Bl + go);
            }
        }
        cp_commit();
    };

    const int warp_m = wid & 3;   // 4 warps x 32 rows
    const int warp_n = wid >> 2;  // 2 warps x 64 cols
    const int gid = lid >> 2;     // 0..7
    const int tig = lid & 3;      // 0..3

    // ldmatrix per-lane offsets (in words, within a tile)
    //  A x4: m0 rows+0 k+0 | m1 rows+8 k+0 | m2 rows+0 k+4w | m3 rows+8 k+4w
    const int a_lane = ((lid & 7) + ((lid >> 3) & 1) * 8) * SROWW + (lid >> 4) * 4;
    //  B x4: m0 cols+0 k+0 | m1 cols+0 k+4w | m2 cols+8 k+0 | m3 cols+8 k+4w
    const int b_lane = ((lid & 7) + ((lid >> 4) & 1) * 8) * SROWW + ((lid >> 3) & 1) * 4;

    const uint32_t aAh0 = sbase + (uint32_t)(32 * warp_m * SROWW + a_lane) * 4;
    const uint32_t aBh0 = sbase + SLOT_BH * TILE_BYTES + (uint32_t)(64 * warp_n * SROWW + b_lane) * 4;

    float acc[2][8][4];
    #pragma unroll
    for (int i = 0; i < 2; ++i)
        #pragma unroll
        for (int j = 0; j < 8; ++j)
            #pragma unroll
            for (int c = 0; c < 4; ++c) acc[i][j][c] = 0.f;

    load_tile(0, 0);

    #pragma unroll 1
    for (int kt = 0; kt < KT; ++kt) {
        const int s = kt & 1;
        // R9-proven schedule: issue next-tile loads FIRST (hidden under the wait),
        // keep one group in flight with cp_wait<1>, publish with barrier.
        if (kt + 1 < KT) { load_tile(kt + 1, s ^ 1); cp_wait<1>(); }
        else             { cp_wait<0>(); }
        __syncthreads();

        const uint32_t aAh = aAh0 + s * STAGE_BYTES;
        const uint32_t aBh = aBh0 + s * STAGE_BYTES;

        #pragma unroll
        for (int ks = 0; ks < 2; ++ks) {             // two m16n8k16 K-steps per BK=32
            const uint32_t kadd = (uint32_t)(ks * 8) * 4;

            uint32_t ah[2][4], al[2][4];
            #pragma unroll
            for (int i = 0; i < 2; ++i) {
                const uint32_t a0 = aAh + (uint32_t)(16 * i * SROWW) * 4 + kadd;
                ldmx4(ah[i][0], ah[i][1], ah[i][2], ah[i][3], a0);
                if (NTERMS == 3)
                    ldmx4(al[i][0], al[i][1], al[i][2], al[i][3], a0 + TILE_BYTES);
            }

            #pragma unroll
            for (int jh = 0; jh < 2; ++jh) {         // halves of 4 columns (reg pressure)
                uint32_t bh[4][2], bl[4][2];
                #pragma unroll
                for (int jp = 0; jp < 2; ++jp) {     // j-pairs: cols 8J..8J+15
                    const int J = jh * 4 + jp * 2;
                    const uint32_t b0 = aBh + (uint32_t)(8 * J * SROWW) * 4 + kadd;
                    ldmx4(bh[2*jp][0], bh[2*jp][1], bh[2*jp+1][0], bh[2*jp+1][1], b0);
                    if (NTERMS == 3)
                        ldmx4(bl[2*jp][0], bl[2*jp][1], bl[2*jp+1][0], bl[2*jp+1][1],
                              b0 + TILE_BYTES);
                }
                #pragma unroll
                for (int i = 0; i < 2; ++i)
                    #pragma unroll
                    for (int j = 0; j < 4; ++j) {
                        float* c = acc[i][jh * 4 + j];
                        mma_bf16(c, ah[i], bh[j]);           // hi*hi
                        if (NTERMS == 3) {
                            mma_bf16(c, ah[i], bl[j]);       // hi*lo
                            mma_bf16(c, al[i], bh[j]);       // lo*hi
                        }
                    }
            }
        }
        __syncthreads();   // all warps done with stage s before next iteration's loads reuse it
    }

    // ---------------- epilogue ----------------
    const int gm = rowBase + 32 * warp_m;
    const int gn = colBase + 64 * warp_n + 2 * tig;

    if (MODE == 0) {
        // permuted columns: jj = part*2048 + h*256 + f ; part & head uniform per CTA
        const int part  = colBase >> 11;
        const int hh    = (colBase >> 8) & 7;
        const int fwarp = (colBase & 255) + 64 * warp_n + 2 * tig;
        const float scl = (part == 2) ? 1.0f : 0.0625f;

        #pragma unroll
        for (int i = 0; i < 2; ++i) {
            #pragma unroll
            for (int h = 0; h < 2; ++h) {
                const int m = gm + 16 * i + gid + 8 * h;
                const int b = m >> 11, t = m & (TLEN - 1);
                const size_t rowO = ((size_t)(b * NHEAD + hh) * TLEN + t) * FDIM;
                #pragma unroll
                for (int j = 0; j < 8; ++j) {
                    const int f0 = fwarp + 8 * j;
                    const int borig = hh * (FDIM * 3) + f0 * 3 + part;
                    float v0 = (acc[i][j][2 * h]     + bias[borig])     * scl;
                    float v1 = (acc[i][j][2 * h + 1] + bias[borig + 3]) * scl;
                    if (part == 0) {
                        *(uint32_t*)(g_Qh + rowO + f0) = pack_hi(v0, v1);
                    } else if (part == 1) {
                        *(uint32_t*)(g_Kh + rowO + f0) = pack_hi(v0, v1);
                    } else {
                        uint32_t hw, lw;
                        split_pair(make_float2(v0, v1), hw, lw);
                        *(uint32_t*)(g_Vnh + rowO + f0) = hw;
                        *(uint32_t*)(g_Vnl + rowO + f0) = lw;
                    }
                }
            }
        }
        return;
    }

    #pragma unroll
    for (int i = 0; i < 2; ++i) {
        #pragma unroll
        for (int h = 0; h < 2; ++h) {
            const int m = gm + 16 * i + gid + 8 * h;

            if (MODE == 1) {
                float* p = g_S + (size_t)z * TLEN * TLEN + (size_t)m * TLEN + gn;
                #pragma unroll
                for (int j = 0; j < 8; ++j)
                    *(float2*)(p + 8 * j) = make_float2(acc[i][j][2 * h], acc[i][j][2 * h + 1]);
            } else if (MODE == 2) {
                const int b = z >> 3, hh = z & 7;
                const size_t base = ((size_t)(b * TLEN + m)) * (NHEAD * FDIM) + hh * FDIM + gn;
                #pragma unroll
                for (int j = 0; j < 8; ++j) {
                    uint32_t hw, lw;
                    split_pair(make_float2(acc[i][j][2 * h], acc[i][j][2 * h + 1]), hw, lw);
                    *(uint32_t*)(g_ah + base + 8 * j) = hw;
                    *(uint32_t*)(g_al + base + 8 * j) = lw;
                }
            } else {
                float* p = Cgp + (size_t)m * FDIM + gn;
                #pragma unroll
                for (int j = 0; j < 8; ++j)
                    *(float2*)(p + 8 * j) = make_float2(acc[i][j][2 * h]     + bias[gn + 8 * j],
                                                        acc[i][j][2 * h + 1] + bias[gn + 8 * j + 1]);
            }
        }
    }
}

// ---------------- input split: x -> g_xh/g_xl ----------------
__global__ void __launch_bounds__(256) split_x_kernel(const float* __restrict__ x)
{
    const size_t i = ((size_t)blockIdx.x * 256 + threadIdx.x) * 4;
    const float4 v = *(const float4*)(x + i);
    uint32_t h0, l0, h1, l1;
    split_pair(make_float2(v.x, v.y), h0, l0);
    split_pair(make_float2(v.z, v.w), h1, l1);
    *(uint32_t*)(g_xh + i)     = h0;
    *(uint32_t*)(g_xh + i + 2) = h1;
    *(uint32_t*)(g_xl + i)     = l0;
    *(uint32_t*)(g_xl + i + 2) = l1;
}

// ---------------- W_qkv transpose + column permutation + split ----------------
// in:  W_qkv [256][6144], col_orig = h*768 + f*3 + part
// out: g_Wqh/g_Wql [6144][256], row (col_new) = part*2048 + h*256 + f
__global__ void __launch_bounds__(256) wqkv_prep_kernel(const float* __restrict__ in)
{
    __shared__ float t[32][33];
    const int c0 = blockIdx.x * 32;
    const int r0 = blockIdx.y * 32;
    const int tx = threadIdx.x, ty = threadIdx.y;
    #pragma unroll
    for (int i = 0; i < 32; i += 8)
        t[ty + i][tx] = in[(size_t)(r0 + ty + i) * (NHEAD * FDIM * 3) + c0 + tx];
    __syncthreads();
    #pragma unroll
    for (int i = 0; i < 32; i += 8) {
        const int corig = c0 + ty + i;
        const int hh  = corig / (FDIM * 3);
        const int rem = corig - hh * (FDIM * 3);
        const int f   = rem / 3;
        const int prt = rem - f * 3;
        const int cnew = prt * (NHEAD * FDIM) + hh * FDIM + f;
        bf16 vh, vl;
        split1(t[tx][ty + i], vh, vl);
        g_Wqh[(size_t)cnew * FDIM + r0 + tx] = vh;
        g_Wql[(size_t)cnew * FDIM + r0 + tx] = vl;
    }
}

// ---------------- W_proj transpose + split: [2048][256] -> [256][2048] ----------------
__global__ void __launch_bounds__(256) wproj_prep_kernel(const float* __restrict__ in)
{
    __shared__ float t[32][33];
    const int c0 = blockIdx.x * 32;   // cols of in (256)
    const int r0 = blockIdx.y * 32;   // rows of in (2048)
    const int tx = threadIdx.x, ty = threadIdx.y;
    #pragma unroll
    for (int i = 0; i < 32; i += 8)
        t[ty + i][tx] = in[(size_t)(r0 + ty + i) * FDIM + c0 + tx];
    __syncthreads();
    #pragma unroll
    for (int i = 0; i < 32; i += 8) {
        bf16 vh, vl;
        split1(t[tx][ty + i], vh, vl);
        g_Wph[(size_t)(c0 + ty + i) * (NHEAD * FDIM) + r0 + tx] = vh;
        g_Wpl[(size_t)(c0 + ty + i) * (NHEAD * FDIM) + r0 + tx] = vl;
    }
}

// ---------------- V transpose: [bh][t][f] -> [bh][f][t] (hi & lo) ----------------
__global__ void __launch_bounds__(256) vtrans_kernel()
{
    __shared__ bf16 th[32][33], tl[32][33];
    const int bh = blockIdx.z;
    const int f0 = blockIdx.x * 32;
    const int t0 = blockIdx.y * 32;
    const int tx = threadIdx.x, ty = threadIdx.y;
    const size_t inb = ((size_t)bh * TLEN + t0) * FDIM + f0;
    #pragma unroll
    for (int i = 0; i < 32; i += 8) {
        th[ty + i][tx] = g_Vnh[inb + (size_t)(ty + i) * FDIM + tx];
        tl[ty + i][tx] = g_Vnl[inb + (size_t)(ty + i) * FDIM + tx];
    }
    __syncthreads();
    const size_t outb = ((size_t)bh * FDIM + f0) * TLEN + t0;
    #pragma unroll
    for (int i = 0; i < 32; i += 8) {
        g_Vth[outb + (size_t)(ty + i) * TLEN + tx] = th[tx][ty + i];
        g_Vtl[outb + (size_t)(ty + i) * TLEN + tx] = tl[tx][ty + i];
    }
}

// ---------------- softmax: 65536 rows of 2048; write split bf16 probs ----------------
__global__ void __launch_bounds__(256) softmax_kernel()
{
    const size_t row = blockIdx.x;
    const float* p = g_S + row * (size_t)TLEN;
    const int t = threadIdx.x;

    float4 v0 = ((const float4*)p)[t];
    float4 v1 = ((const float4*)p)[t + 256];

    float m = fmaxf(fmaxf(fmaxf(v0.x, v0.y), fmaxf(v0.z, v0.w)),
                    fmaxf(fmaxf(v1.x, v1.y), fmaxf(v1.z, v1.w)));
    #pragma unroll
    for (int o = 16; o; o >>= 1) m = fmaxf(m, __shfl_xor_sync(0xffffffffu, m, o));

    __shared__ float red[8];
    const int warp = t >> 5, lane = t & 31;
    if (lane == 0) red[warp] = m;
    __syncthreads();
    float bm = red[0];
    #pragma unroll
    for (int i = 1; i < 8; ++i) bm = fmaxf(bm, red[i]);
    __syncthreads();

    v0.x = __expf(v0.x - bm); v0.y = __expf(v0.y - bm);
    v0.z = __expf(v0.z - bm); v0.w = __expf(v0.w - bm);
    v1.x = __expf(v1.x - bm); v1.y = __expf(v1.y - bm);
    v1.z = __expf(v1.z - bm); v1.w = __expf(v1.w - bm);

    float s = v0.x + v0.y + v0.z + v0.w + v1.x + v1.y + v1.z + v1.w;
    #pragma unroll
    for (int o = 16; o; o >>= 1) s += __shfl_xor_sync(0xffffffffu, s, o);
    if (lane == 0) red[warp] = s;
    __syncthreads();
    float bs = 0.f;
    #pragma unroll
    for (int i = 0; i < 8; ++i) bs += red[i];

    const float inv = 1.0f / bs;
    v0.x *= inv; v0.y *= inv; v0.z *= inv; v0.w *= inv;
    v1.x *= inv; v1.y *= inv; v1.z *= inv; v1.w *= inv;

    uint32_t* ph = (uint32_t*)(g_Ph + row * (size_t)TLEN);
    uint32_t* pl = (uint32_t*)(g_Pl + row * (size_t)TLEN);
    uint32_t hw, lw;
    split_pair(make_float2(v0.x, v0.y), hw, lw); ph[2 * t]       = hw; pl[2 * t]       = lw;
    split_pair(make_float2(v0.z, v0.w), hw, lw); ph[2 * t + 1]   = hw; pl[2 * t + 1]   = lw;
    split_pair(make_float2(v1.x, v1.y), hw, lw); ph[2 * t + 512] = hw; pl[2 * t + 512] = lw;
    split_pair(make_float2(v1.z, v1.w), hw, lw); ph[2 * t + 513] = hw; pl[2 * t + 513] = lw;
}

// ---------------- launch ----------------
extern "C" void kernel_launch(void* const* d_in, const int* in_sizes, int n_in,
                              void* d_out, int out_size)
{
    const float* x     = (const float*)d_in[0];
    const float* Wqkv  = (const float*)d_in[1];
    const float* bqkv  = (const float*)d_in[2];
    const float* Wproj = (const float*)d_in[3];
    const float* bproj = (const float*)d_in[4];
    float* out = (float*)d_out;

    cudaFuncSetAttribute(mma_gemm<0>, cudaFuncAttributeMaxDynamicSharedMemorySize, SMEM_FULL);
    cudaFuncSetAttribute(mma_gemm<1>, cudaFuncAttributeMaxDynamicSharedMemorySize, SMEM_HI);
    cudaFuncSetAttribute(mma_gemm<2>, cudaFuncAttributeMaxDynamicSharedMemorySize, SMEM_FULL);
    cudaFuncSetAttribute(mma_gemm<3>, cudaFuncAttributeMaxDynamicSharedMemorySize, SMEM_FULL);

    // prep: split x; transpose(+permute)+split weights
    split_x_kernel<<<(NBATCH * TLEN * FDIM) / 1024, 256>>>(x);
    wqkv_prep_kernel<<<dim3(6144 / 32, 256 / 32), dim3(32, 8)>>>(Wqkv);
    wproj_prep_kernel<<<dim3(256 / 32, 2048 / 32), dim3(32, 8)>>>(Wproj);

    // 1) QKV GEMM (+bias, scale) -> Qh/Kh hi, V split natural
    mma_gemm<0><<<dim3(6144 / BN, 8192 / BM, 1), 256, SMEM_FULL>>>(bqkv, nullptr);
    // 1b) V transpose -> Vth/Vtl
    vtrans_kernel<<<dim3(FDIM / 32, TLEN / 32, NBH), dim3(32, 8)>>>();
    // 2) scores = Qh Kh^T (hi-only, batched over 32 bh) -> fp32 S
    mma_gemm<1><<<dim3(TLEN / BN, TLEN / BM, NBH), 256, SMEM_HI>>>(nullptr, nullptr);
    // 3) softmax -> split bf16 P
    softmax_kernel<<<NBH * TLEN, 256>>>();
    // 4) out = P V (batched, NT against Vt) -> split bf16 attn
    mma_gemm<2><<<dim3(FDIM / BN, TLEN / BM, NBH), 256, SMEM_FULL>>>(nullptr, nullptr);
    // 5) proj (+bias) -> fp32 out
    mma_gemm<3><<<dim3(FDIM / BN, 8192 / BM, 1), 256, SMEM_FULL>>>(bproj, out);
}

// round 12
// speedup vs baseline: 1.6907x; 1.1571x over previous
#include <cuda_runtime.h>
#include <cuda_bf16.h>
#include <cstdint>
#include <math.h>

#define TLEN   2048
#define FDIM   256
#define NHEAD  8
#define NBATCH 4
#define NBH    32

typedef __nv_bfloat16 bf16;

// ---------------- scratch (__device__ globals; no allocation allowed) ----------------
__device__ __align__(16) bf16 g_xh [(size_t)NBATCH * TLEN * FDIM];
__device__ __align__(16) bf16 g_xl [(size_t)NBATCH * TLEN * FDIM];
__device__ __align__(16) bf16 g_Wqh[(size_t)(NHEAD * FDIM * 3) * FDIM];   // permuted WqkvT hi [6144][256]
__device__ __align__(16) bf16 g_Wql[(size_t)(NHEAD * FDIM * 3) * FDIM];
__device__ __align__(16) bf16 g_Wph[(size_t)FDIM * (NHEAD * FDIM)];       // WprojT hi [256][2048]
__device__ __align__(16) bf16 g_Wpl[(size_t)FDIM * (NHEAD * FDIM)];
__device__ __align__(16) bf16 g_Qh [(size_t)NBH * TLEN * FDIM];           // [bh][t][f]  (hi only)
__device__ __align__(16) bf16 g_Kh [(size_t)NBH * TLEN * FDIM];           // (hi only)
__device__ __align__(16) bf16 g_Vnh[(size_t)NBH * TLEN * FDIM];           // V natural [bh][t][f]
__device__ __align__(16) bf16 g_Vnl[(size_t)NBH * TLEN * FDIM];
__device__ __align__(16) bf16 g_Vth[(size_t)NBH * FDIM * TLEN];           // V transposed [bh][f][t]
__device__ __align__(16) bf16 g_Vtl[(size_t)NBH * FDIM * TLEN];
__device__ __align__(16) bf16 g_Sh [(size_t)NBH * TLEN * TLEN];           // bf16 scores
__device__ __align__(16) bf16 g_Ph [(size_t)NBH * TLEN * TLEN];           // probs hi
__device__ __align__(16) bf16 g_Pl [(size_t)NBH * TLEN * TLEN];           // probs lo
__device__ __align__(16) bf16 g_ah [(size_t)NBATCH * TLEN * NHEAD * FDIM];// attn hi [b][t][h*f]
__device__ __align__(16) bf16 g_al [(size_t)NBATCH * TLEN * NHEAD * FDIM];

// ---------------- helpers ----------------
__device__ __forceinline__ uint32_t smem_u32(const void* p) {
    uint32_t a;
    asm("{ .reg .u64 t; cvta.to.shared.u64 t, %1; cvt.u32.u64 %0, t; }" : "=r"(a) : "l"(p));
    return a;
}
__device__ __forceinline__ void cp_async16(uint32_t dst, const void* src) {
    asm volatile("cp.async.cg.shared.global [%0], [%1], 16;" :: "r"(dst), "l"(src) : "memory");
}
__device__ __forceinline__ void cp_commit() {
    asm volatile("cp.async.commit_group;" ::: "memory");
}
template<int N> __device__ __forceinline__ void cp_wait() {
    asm volatile("cp.async.wait_group %0;" :: "n"(N) : "memory");
}
__device__ __forceinline__ void mma_bf16(float* c, const uint32_t* a, const uint32_t* b) {
    asm volatile(
        "mma.sync.aligned.m16n8k16.row.col.f32.bf16.bf16.f32 "
        "{%0,%1,%2,%3}, {%4,%5,%6,%7}, {%8,%9}, {%0,%1,%2,%3};"
        : "+f"(c[0]), "+f"(c[1]), "+f"(c[2]), "+f"(c[3])
        : "r"(a[0]), "r"(a[1]), "r"(a[2]), "r"(a[3]), "r"(b[0]), "r"(b[1]));
}
__device__ __forceinline__ void ldmx4(uint32_t& r0, uint32_t& r1, uint32_t& r2, uint32_t& r3,
                                      uint32_t addr) {
    asm volatile("ldmatrix.sync.aligned.m8n8.x4.shared.b16 {%0,%1,%2,%3}, [%4];"
                 : "=r"(r0), "=r"(r1), "=r"(r2), "=r"(r3) : "r"(addr));
}
__device__ __forceinline__ uint32_t pack_hi(float lo, float hi) {
    uint32_t h;
    asm("cvt.rn.bf16x2.f32 %0, %1, %2;" : "=r"(h) : "f"(hi), "f"(lo));
    return h;
}
// split fp32 pair -> packed bf16x2 hi + bf16x2 lo residual (.x in low half)
__device__ __forceinline__ void split_pair(float2 f, uint32_t& hi, uint32_t& lo) {
    uint32_t h;
    asm("cvt.rn.bf16x2.f32 %0, %1, %2;" : "=r"(h) : "f"(f.y), "f"(f.x));
    const float h0 = __uint_as_float(h << 16);
    const float h1 = __uint_as_float(h & 0xffff0000u);
    asm("cvt.rn.bf16x2.f32 %0, %1, %2;" : "=r"(lo) : "f"(f.y - h1), "f"(f.x - h0));
    hi = h;
}
__device__ __forceinline__ void split1(float v, bf16& h, bf16& l) {
    h = __float2bfloat16(v);
    l = __float2bfloat16(v - __bfloat162float(h));
}

// ---------------- GEMM config ----------------
// Swizzled tile: 128 rows x 64B (32 bf16). chunk' = chunk ^ ((row>>1)&3); no padding.
constexpr int BM = 128, BN = 128, BK = 32;
constexpr int TILE_BYTES = BM * 64;                    // 8192
constexpr int STAGES = 3;
constexpr int SMEM_FULL = STAGES * 4 * TILE_BYTES + 128;  // 98432 (Ah,Al,Bh,Bl)
constexpr int SMEM_HI   = STAGES * 2 * TILE_BYTES + 128;  // 49280 (Ah,Bh)

// MODE 0: C[8192,6144] = x @ WqkvT'^T   (K=256)  -> Q/K hi (+bias,*1/16), V split natural
// MODE 1: C[2048,2048] = Qh @ Kh^T      (K=256)  -> g_Sh bf16 (hi-only, 1 MMA)
// MODE 2: C[2048, 256] = P @ Vt^T       (K=2048) -> split g_ah/g_al
// MODE 3: C[8192, 256] = attn @ WprojT^T(K=2048) -> d_out fp32 (+bias)
template<int MODE>
__global__ void __launch_bounds__(256, 2)
mma_gemm(const float* __restrict__ bias, float* __restrict__ Cgp)
{
    constexpr int NTERMS = (MODE == 1) ? 1 : 3;
    constexpr int TILES  = (NTERMS == 1) ? 2 : 4;
    constexpr int K  = (MODE == 0 || MODE == 1) ? 256 : 2048;
    constexpr int KT = K / BK;
    constexpr int STAGE_BYTES = TILES * TILE_BYTES;
    constexpr int SLOT_BH = (NTERMS == 1) ? 1 : 2;

    extern __shared__ uint32_t smem_w[];
    const uint32_t sbase = (smem_u32(smem_w) + 127u) & ~127u;

    const int tid = threadIdx.x;
    const int wid = tid >> 5, lid = tid & 31;
    const int z = blockIdx.z;
    const int rowBase = blockIdx.y * BM;
    const int colBase = blockIdx.x * BN;

    const bf16 *Ah, *Al = nullptr, *Bh, *Bl = nullptr;
    if (MODE == 0) {
        Ah = g_xh;  Al = g_xl;  Bh = g_Wqh; Bl = g_Wql;
    } else if (MODE == 1) {
        const size_t o = (size_t)z * TLEN * FDIM;
        Ah = g_Qh + o; Bh = g_Kh + o;
    } else if (MODE == 2) {
        const size_t oa = (size_t)z * TLEN * TLEN;
        const size_t ob = (size_t)z * FDIM * TLEN;
        Ah = g_Ph + oa; Al = g_Pl + oa; Bh = g_Vth + ob; Bl = g_Vtl + ob;
    } else {
        Ah = g_ah;  Al = g_al;  Bh = g_Wph; Bl = g_Wpl;
    }
    Ah += (size_t)rowBase * K;
    Bh += (size_t)colBase * K;
    if (NTERMS == 3) { Al += (size_t)rowBase * K; Bl += (size_t)colBase * K; }

    // loader: per tile 512 chunks of 16B; 256 threads x 2; swizzled placement
    auto load_tile = [&](int kt, int s) {
        const uint32_t base = sbase + s * STAGE_BYTES;
        const int kofs = kt * BK;
        #pragma unroll
        for (int i = 0; i < 2; ++i) {
            const int f   = tid + 256 * i;
            const int row = f >> 2;
            const int c   = f & 3;
            const uint32_t so = (uint32_t)(row * 64) + (uint32_t)((c ^ ((row >> 1) & 3)) << 4);
            const size_t go = (size_t)row * K + kofs + c * 8;
            cp_async16(base + so,                         Ah + go);
            cp_async16(base + SLOT_BH * TILE_BYTES + so,  Bh + go);
            if (NTERMS == 3) {
                cp_async16(base + 1 * TILE_BYTES + so,    Al + go);
                cp_async16(base + 3 * TILE_BYTES + so,    Bl + go);
            }
        }
        cp_commit();
    };

    const int warp_m = wid & 3;   // 4 warps x 32 rows
    const int warp_n = wid >> 2;  // 2 warps x 64 cols
    const int gid = lid >> 2;     // 0..7
    const int tig = lid & 3;      // 0..3

    // ldmatrix lane addresses (swizzled), ks=0; ks=1 is addr^32
    const int R_A = 32 * warp_m + (lid & 7) + ((lid >> 3) & 1) * 8;
    const int c_A = (lid >> 4) & 1;
    const uint32_t aA0 = sbase + (uint32_t)(R_A * 64) +
                         (uint32_t)((c_A ^ ((R_A >> 1) & 3)) << 4);
    const int R_B = 64 * warp_n + (lid & 7) + ((lid >> 4) & 1) * 8;
    const int c_B = (lid >> 3) & 1;
    const uint32_t aB0 = sbase + SLOT_BH * TILE_BYTES + (uint32_t)(R_B * 64) +
                         (uint32_t)((c_B ^ ((R_B >> 1) & 3)) << 4);

    float acc[2][8][4];
    #pragma unroll
    for (int i = 0; i < 2; ++i)
        #pragma unroll
        for (int j = 0; j < 8; ++j)
            #pragma unroll
            for (int c = 0; c < 4; ++c) acc[i][j][c] = 0.f;

    load_tile(0, 0);
    if (KT > 1) load_tile(1, 1);

    int s = 0;
    #pragma unroll 1
    for (int kt = 0; kt < KT; ++kt) {
        const int rem = KT - 1 - kt;
        if (rem >= 2) {
            int sp2 = s - 1; if (sp2 < 0) sp2 = 2;     // (s+2)%3
            load_tile(kt + 2, sp2);
            cp_wait<2>();
        } else if (rem == 1) {
            cp_wait<1>();
        } else {
            cp_wait<0>();
        }
        __syncthreads();

        const uint32_t aAh = aA0 + s * STAGE_BYTES;
        const uint32_t aBh = aB0 + s * STAGE_BYTES;

        #pragma unroll
        for (int ks = 0; ks < 2; ++ks) {             // two m16n8k16 K-steps per BK=32
            const uint32_t kx = (uint32_t)(ks * 32);  // ks=1: flip bit5

            uint32_t ah[2][4], al[2][4];
            #pragma unroll
            for (int i = 0; i < 2; ++i) {
                const uint32_t a0 = (aAh + (uint32_t)(i * 1024)) ^ kx;
                ldmx4(ah[i][0], ah[i][1], ah[i][2], ah[i][3], a0);
                if (NTERMS == 3)
                    ldmx4(al[i][0], al[i][1], al[i][2], al[i][3], a0 + TILE_BYTES);
            }

            #pragma unroll
            for (int jh = 0; jh < 2; ++jh) {         // halves of 4 columns (reg pressure)
                uint32_t bh[4][2], bl[4][2];
                #pragma unroll
                for (int jp = 0; jp < 2; ++jp) {     // j-pairs: cols 8J..8J+15
                    const int J = jh * 4 + jp * 2;
                    const uint32_t b0 = (aBh + (uint32_t)(J * 512)) ^ kx;
                    ldmx4(bh[2*jp][0], bh[2*jp][1], bh[2*jp+1][0], bh[2*jp+1][1], b0);
                    if (NTERMS == 3)
                        ldmx4(bl[2*jp][0], bl[2*jp][1], bl[2*jp+1][0], bl[2*jp+1][1],
                              b0 + TILE_BYTES);
                }
                #pragma unroll
                for (int i = 0; i < 2; ++i)
                    #pragma unroll
                    for (int j = 0; j < 4; ++j) {
                        float* c = acc[i][jh * 4 + j];
                        mma_bf16(c, ah[i], bh[j]);           // hi*hi
                        if (NTERMS == 3) {
                            mma_bf16(c, ah[i], bl[j]);       // hi*lo
                            mma_bf16(c, al[i], bh[j]);       // lo*hi
                        }
                    }
            }
        }
        __syncthreads();   // all warps done with stage s before loads reuse it
        s = (s == 2) ? 0 : s + 1;
    }

    // ---------------- epilogue ----------------
    const int gm = rowBase + 32 * warp_m;
    const int gn = colBase + 64 * warp_n + 2 * tig;

    if (MODE == 0) {
        // permuted columns: jj = part*2048 + h*256 + f ; part & head uniform per CTA
        const int part  = colBase >> 11;
        const int hh    = (colBase >> 8) & 7;
        const int fwarp = (colBase & 255) + 64 * warp_n + 2 * tig;
        const float scl = (part == 2) ? 1.0f : 0.0625f;

        #pragma unroll
        for (int i = 0; i < 2; ++i) {
            #pragma unroll
            for (int h = 0; h < 2; ++h) {
                const int m = gm + 16 * i + gid + 8 * h;
                const int b = m >> 11, t = m & (TLEN - 1);
                const size_t rowO = ((size_t)(b * NHEAD + hh) * TLEN + t) * FDIM;
                #pragma unroll
                for (int j = 0; j < 8; ++j) {
                    const int f0 = fwarp + 8 * j;
                    const int borig = hh * (FDIM * 3) + f0 * 3 + part;
                    float v0 = (acc[i][j][2 * h]     + bias[borig])     * scl;
                    float v1 = (acc[i][j][2 * h + 1] + bias[borig + 3]) * scl;
                    if (part == 0) {
                        *(uint32_t*)(g_Qh + rowO + f0) = pack_hi(v0, v1);
                    } else if (part == 1) {
                        *(uint32_t*)(g_Kh + rowO + f0) = pack_hi(v0, v1);
                    } else {
                        uint32_t hw, lw;
                        split_pair(make_float2(v0, v1), hw, lw);
                        *(uint32_t*)(g_Vnh + rowO + f0) = hw;
                        *(uint32_t*)(g_Vnl + rowO + f0) = lw;
                    }
                }
            }
        }
        return;
    }

    #pragma unroll
    for (int i = 0; i < 2; ++i) {
        #pragma unroll
        for (int h = 0; h < 2; ++h) {
            const int m = gm + 16 * i + gid + 8 * h;

            if (MODE == 1) {
                uint32_t* p = (uint32_t*)(g_Sh + (size_t)z * TLEN * TLEN + (size_t)m * TLEN + gn);
                #pragma unroll
                for (int j = 0; j < 8; ++j)
                    p[4 * j] = pack_hi(acc[i][j][2 * h], acc[i][j][2 * h + 1]);
            } else if (MODE == 2) {
                const int b = z >> 3, hh = z & 7;
                const size_t base = ((size_t)(b * TLEN + m)) * (NHEAD * FDIM) + hh * FDIM + gn;
                #pragma unroll
                for (int j = 0; j < 8; ++j) {
                    uint32_t hw, lw;
                    split_pair(make_float2(acc[i][j][2 * h], acc[i][j][2 * h + 1]), hw, lw);
                    *(uint32_t*)(g_ah + base + 8 * j) = hw;
                    *(uint32_t*)(g_al + base + 8 * j) = lw;
                }
            } else {
                float* p = Cgp + (size_t)m * FDIM + gn;
                #pragma unroll
                for (int j = 0; j < 8; ++j)
                    *(float2*)(p + 8 * j) = make_float2(acc[i][j][2 * h]     + bias[gn + 8 * j],
                                                        acc[i][j][2 * h + 1] + bias[gn + 8 * j + 1]);
            }
        }
    }
}

// ---------------- input split: x -> g_xh/g_xl ----------------
__global__ void __launch_bounds__(256) split_x_kernel(const float* __restrict__ x)
{
    const size_t i = ((size_t)blockIdx.x * 256 + threadIdx.x) * 4;
    const float4 v = *(const float4*)(x + i);
    uint32_t h0, l0, h1, l1;
    split_pair(make_float2(v.x, v.y), h0, l0);
    split_pair(make_float2(v.z, v.w), h1, l1);
    *(uint32_t*)(g_xh + i)     = h0;
    *(uint32_t*)(g_xh + i + 2) = h1;
    *(uint32_t*)(g_xl + i)     = l0;
    *(uint32_t*)(g_xl + i + 2) = l1;
}

// ---------------- W_qkv transpose + column permutation + split ----------------
__global__ void __launch_bounds__(256) wqkv_prep_kernel(const float* __restrict__ in)
{
    __shared__ float t[32][33];
    const int c0 = blockIdx.x * 32;
    const int r0 = blockIdx.y * 32;
    const int tx = threadIdx.x, ty = threadIdx.y;
    #pragma unroll
    for (int i = 0; i < 32; i += 8)
        t[ty + i][tx] = in[(size_t)(r0 + ty + i) * (NHEAD * FDIM * 3) + c0 + tx];
    __syncthreads();
    #pragma unroll
    for (int i = 0; i < 32; i += 8) {
        const int corig = c0 + ty + i;
        const int hh  = corig / (FDIM * 3);
        const int rem = corig - hh * (FDIM * 3);
        const int f   = rem / 3;
        const int prt = rem - f * 3;
        const int cnew = prt * (NHEAD * FDIM) + hh * FDIM + f;
        bf16 vh, vl;
        split1(t[tx][ty + i], vh, vl);
        g_Wqh[(size_t)cnew * FDIM + r0 + tx] = vh;
        g_Wql[(size_t)cnew * FDIM + r0 + tx] = vl;
    }
}

// ---------------- W_proj transpose + split: [2048][256] -> [256][2048] ----------------
__global__ void __launch_bounds__(256) wproj_prep_kernel(const float* __restrict__ in)
{
    __shared__ float t[32][33];
    const int c0 = blockIdx.x * 32;
    const int r0 = blockIdx.y * 32;
    const int tx = threadIdx.x, ty = threadIdx.y;
    #pragma unroll
    for (int i = 0; i < 32; i += 8)
        t[ty + i][tx] = in[(size_t)(r0 + ty + i) * FDIM + c0 + tx];
    __syncthreads();
    #pragma unroll
    for (int i = 0; i < 32; i += 8) {
        bf16 vh, vl;
        split1(t[tx][ty + i], vh, vl);
        g_Wph[(size_t)(c0 + ty + i) * (NHEAD * FDIM) + r0 + tx] = vh;
        g_Wpl[(size_t)(c0 + ty + i) * (NHEAD * FDIM) + r0 + tx] = vl;
    }
}

// ---------------- V transpose: [bh][t][f] -> [bh][f][t] (hi & lo) ----------------
__global__ void __launch_bounds__(256) vtrans_kernel()
{
    __shared__ bf16 th[32][33], tl[32][33];
    const int bh = blockIdx.z;
    const int f0 = blockIdx.x * 32;
    const int t0 = blockIdx.y * 32;
    const int tx = threadIdx.x, ty = threadIdx.y;
    const size_t inb = ((size_t)bh * TLEN + t0) * FDIM + f0;
    #pragma unroll
    for (int i = 0; i < 32; i += 8) {
        th[ty + i][tx] = g_Vnh[inb + (size_t)(ty + i) * FDIM + tx];
        tl[ty + i][tx] = g_Vnl[inb + (size_t)(ty + i) * FDIM + tx];
    }
    __syncthreads();
    const size_t outb = ((size_t)bh * FDIM + f0) * TLEN + t0;
    #pragma unroll
    for (int i = 0; i < 32; i += 8) {
        g_Vth[outb + (size_t)(ty + i) * TLEN + tx] = th[tx][ty + i];
        g_Vtl[outb + (size_t)(ty + i) * TLEN + tx] = tl[tx][ty + i];
    }
}

// ---------------- softmax: 65536 rows of 2048 bf16; write split bf16 probs ----------------
__global__ void __launch_bounds__(256) softmax_kernel()
{
    const size_t row = blockIdx.x;
    const int t = threadIdx.x;

    const uint4 w = ((const uint4*)(g_Sh + row * (size_t)TLEN))[t];   // 8 bf16
    float f[8];
    f[0] = __uint_as_float(w.x << 16); f[1] = __uint_as_float(w.x & 0xffff0000u);
    f[2] = __uint_as_float(w.y << 16); f[3] = __uint_as_float(w.y & 0xffff0000u);
    f[4] = __uint_as_float(w.z << 16); f[5] = __uint_as_float(w.z & 0xffff0000u);
    f[6] = __uint_as_float(w.w << 16); f[7] = __uint_as_float(w.w & 0xffff0000u);

    float m = f[0];
    #pragma unroll
    for (int i = 1; i < 8; ++i) m = fmaxf(m, f[i]);
    #pragma unroll
    for (int o = 16; o; o >>= 1) m = fmaxf(m, __shfl_xor_sync(0xffffffffu, m, o));

    __shared__ float red[8];
    const int warp = t >> 5, lane = t & 31;
    if (lane == 0) red[warp] = m;
    __syncthreads();
    float bm = red[0];
    #pragma unroll
    for (int i = 1; i < 8; ++i) bm = fmaxf(bm, red[i]);
    __syncthreads();

    float s = 0.f;
    #pragma unroll
    for (int i = 0; i < 8; ++i) { f[i] = __expf(f[i] - bm); s += f[i]; }
    #pragma unroll
    for (int o = 16; o; o >>= 1) s += __shfl_xor_sync(0xffffffffu, s, o);
    if (lane == 0) red[warp] = s;
    __syncthreads();
    float bs = 0.f;
    #pragma unroll
    for (int i = 0; i < 8; ++i) bs += red[i];

    const float inv = 1.0f / bs;
    #pragma unroll
    for (int i = 0; i < 8; ++i) f[i] *= inv;

    uint4 ph, pl;
    split_pair(make_float2(f[0], f[1]), ph.x, pl.x);
    split_pair(make_float2(f[2], f[3]), ph.y, pl.y);
    split_pair(make_float2(f[4], f[5]), ph.z, pl.z);
    split_pair(make_float2(f[6], f[7]), ph.w, pl.w);
    ((uint4*)(g_Ph + row * (size_t)TLEN))[t] = ph;
    ((uint4*)(g_Pl + row * (size_t)TLEN))[t] = pl;
}

// ---------------- launch ----------------
extern "C" void kernel_launch(void* const* d_in, const int* in_sizes, int n_in,
                              void* d_out, int out_size)
{
    const float* x     = (const float*)d_in[0];
    const float* Wqkv  = (const float*)d_in[1];
    const float* bqkv  = (const float*)d_in[2];
    const float* Wproj = (const float*)d_in[3];
    const float* bproj = (const float*)d_in[4];
    float* out = (float*)d_out;

    cudaFuncSetAttribute(mma_gemm<0>, cudaFuncAttributeMaxDynamicSharedMemorySize, SMEM_FULL);
    cudaFuncSetAttribute(mma_gemm<1>, cudaFuncAttributeMaxDynamicSharedMemorySize, SMEM_HI);
    cudaFuncSetAttribute(mma_gemm<2>, cudaFuncAttributeMaxDynamicSharedMemorySize, SMEM_FULL);
    cudaFuncSetAttribute(mma_gemm<3>, cudaFuncAttributeMaxDynamicSharedMemorySize, SMEM_FULL);

    // prep: split x; transpose(+permute)+split weights
    split_x_kernel<<<(NBATCH * TLEN * FDIM) / 1024, 256>>>(x);
    wqkv_prep_kernel<<<dim3(6144 / 32, 256 / 32), dim3(32, 8)>>>(Wqkv);
    wproj_prep_kernel<<<dim3(256 / 32, 2048 / 32), dim3(32, 8)>>>(Wproj);

    // 1) QKV GEMM (+bias, scale) -> Qh/Kh hi, V split natural
    mma_gemm<0><<<dim3(6144 / BN, 8192 / BM, 1), 256, SMEM_FULL>>>(bqkv, nullptr);
    // 1b) V transpose -> Vth/Vtl
    vtrans_kernel<<<dim3(FDIM / 32, TLEN / 32, NBH), dim3(32, 8)>>>();
    // 2) scores = Qh Kh^T (hi-only, batched over 32 bh) -> bf16 S
    mma_gemm<1><<<dim3(TLEN / BN, TLEN / BM, NBH), 256, SMEM_HI>>>(nullptr, nullptr);
    // 3) softmax -> split bf16 P
    softmax_kernel<<<NBH * TLEN, 256>>>();
    // 4) out = P V (batched, NT against Vt) -> split bf16 attn
    mma_gemm<2><<<dim3(FDIM / BN, TLEN / BM, NBH), 256, SMEM_FULL>>>(nullptr, nullptr);
    // 5) proj (+bias) -> fp32 out
    mma_gemm<3><<<dim3(FDIM / BN, 8192 / BM, 1), 256, SMEM_FULL>>>(bproj, out);
}

// round 13
// speedup vs baseline: 1.7150x; 1.0144x over previous
#include <cuda_runtime.h>
#include <cuda_bf16.h>
#include <cstdint>
#include <math.h>

#define TLEN   2048
#define FDIM   256
#define NHEAD  8
#define NBATCH 4
#define NBH    32

typedef __nv_bfloat16 bf16;

// ---------------- scratch (__device__ globals; no allocation allowed) ----------------
__device__ __align__(16) bf16 g_xh [(size_t)NBATCH * TLEN * FDIM];
__device__ __align__(16) bf16 g_xl [(size_t)NBATCH * TLEN * FDIM];
__device__ __align__(16) bf16 g_Wqh[(size_t)(NHEAD * FDIM * 3) * FDIM];   // permuted WqkvT hi [6144][256]
__device__ __align__(16) bf16 g_Wql[(size_t)(NHEAD * FDIM * 3) * FDIM];
__device__ __align__(16) bf16 g_Wph[(size_t)FDIM * (NHEAD * FDIM)];       // WprojT hi [256][2048]
__device__ __align__(16) bf16 g_Wpl[(size_t)FDIM * (NHEAD * FDIM)];
__device__ __align__(16) bf16 g_Qh [(size_t)NBH * TLEN * FDIM];           // [bh][t][f]  (hi only)
__device__ __align__(16) bf16 g_Kh [(size_t)NBH * TLEN * FDIM];           // (hi only)
__device__ __align__(16) bf16 g_Vnh[(size_t)NBH * TLEN * FDIM];           // V natural [bh][t][f]
__device__ __align__(16) bf16 g_Vnl[(size_t)NBH * TLEN * FDIM];
__device__ __align__(16) bf16 g_Vth[(size_t)NBH * FDIM * TLEN];           // V transposed [bh][f][t]
__device__ __align__(16) bf16 g_Vtl[(size_t)NBH * FDIM * TLEN];
__device__ __align__(16) bf16 g_Ph [(size_t)NBH * TLEN * TLEN];           // unnorm probs e=exp(s) hi
__device__ __align__(16) bf16 g_Pl [(size_t)NBH * TLEN * TLEN];           // unnorm probs lo
__device__ __align__(16) bf16 g_ah [(size_t)NBATCH * TLEN * NHEAD * FDIM];// attn hi [b][t][h*f]
__device__ __align__(16) bf16 g_al [(size_t)NBATCH * TLEN * NHEAD * FDIM];
__device__ __align__(16) float g_rsum[(size_t)NBH * TLEN * 32];           // per-row partial sums
__device__ __align__(16) float g_rinv[(size_t)NBH * TLEN];                // 1/rowsum
__device__ __align__(16) float g_p3  [(size_t)2 * NBATCH * TLEN * FDIM];  // mode-3 split-K partials

// ---------------- helpers ----------------
__device__ __forceinline__ uint32_t smem_u32(const void* p) {
    uint32_t a;
    asm("{ .reg .u64 t; cvta.to.shared.u64 t, %1; cvt.u32.u64 %0, t; }" : "=r"(a) : "l"(p));
    return a;
}
__device__ __forceinline__ void cp_async16(uint32_t dst, const void* src) {
    asm volatile("cp.async.cg.shared.global [%0], [%1], 16;" :: "r"(dst), "l"(src) : "memory");
}
__device__ __forceinline__ void cp_commit() {
    asm volatile("cp.async.commit_group;" ::: "memory");
}
template<int N> __device__ __forceinline__ void cp_wait() {
    asm volatile("cp.async.wait_group %0;" :: "n"(N) : "memory");
}
__device__ __forceinline__ void mma_bf16(float* c, const uint32_t* a, const uint32_t* b) {
    asm volatile(
        "mma.sync.aligned.m16n8k16.row.col.f32.bf16.bf16.f32 "
        "{%0,%1,%2,%3}, {%4,%5,%6,%7}, {%8,%9}, {%0,%1,%2,%3};"
        : "+f"(c[0]), "+f"(c[1]), "+f"(c[2]), "+f"(c[3])
        : "r"(a[0]), "r"(a[1]), "r"(a[2]), "r"(a[3]), "r"(b[0]), "r"(b[1]));
}
__device__ __forceinline__ void ldmx4(uint32_t& r0, uint32_t& r1, uint32_t& r2, uint32_t& r3,
                                      uint32_t addr) {
    asm volatile("ldmatrix.sync.aligned.m8n8.x4.shared.b16 {%0,%1,%2,%3}, [%4];"
                 : "=r"(r0), "=r"(r1), "=r"(r2), "=r"(r3) : "r"(addr));
}
__device__ __forceinline__ uint32_t pack_hi(float lo, float hi) {
    uint32_t h;
    asm("cvt.rn.bf16x2.f32 %0, %1, %2;" : "=r"(h) : "f"(hi), "f"(lo));
    return h;
}
// split fp32 pair -> packed bf16x2 hi + bf16x2 lo residual (.x in low half)
__device__ __forceinline__ void split_pair(float2 f, uint32_t& hi, uint32_t& lo) {
    uint32_t h;
    asm("cvt.rn.bf16x2.f32 %0, %1, %2;" : "=r"(h) : "f"(f.y), "f"(f.x));
    const float h0 = __uint_as_float(h << 16);
    const float h1 = __uint_as_float(h & 0xffff0000u);
    asm("cvt.rn.bf16x2.f32 %0, %1, %2;" : "=r"(lo) : "f"(f.y - h1), "f"(f.x - h0));
    hi = h;
}
__device__ __forceinline__ void split1(float v, bf16& h, bf16& l) {
    h = __float2bfloat16(v);
    l = __float2bfloat16(v - __bfloat162float(h));
}

// ---------------- GEMM config ----------------
// Swizzled tile: 128 rows x 64B (32 bf16). chunk' = chunk ^ ((row>>1)&3); no padding.
constexpr int BM = 128, BN = 128, BK = 32;
constexpr int TILE_BYTES = BM * 64;                    // 8192
constexpr int STAGES = 3;
constexpr int SMEM_FULL = STAGES * 4 * TILE_BYTES + 128;  // 98432 (Ah,Al,Bh,Bl)
constexpr int SMEM_HI   = STAGES * 2 * TILE_BYTES + 128;  // 49280 (Ah,Bh)

// MODE 0: C[8192,6144] = x @ WqkvT'^T   (K=256)   -> Q/K hi (+bias,*1/16), V split natural
// MODE 1: C[2048,2048] = Qh @ Kh^T      (K=256)   -> e=exp(s) split -> g_Ph/g_Pl + row partial sums
// MODE 2: C[2048, 256] = E @ Vt^T       (K=2048)  -> *rinv[m] -> split g_ah/g_al
// MODE 3: C[8192, 256] = attn @ WprojT^T (split-K x2, z=K-half) -> g_p3 partials
template<int MODE>
__global__ void __launch_bounds__(256, 2)
mma_gemm(const float* __restrict__ bias, float* __restrict__ Cgp)
{
    constexpr int NTERMS = (MODE == 1) ? 1 : 3;
    constexpr int TILES  = (NTERMS == 1) ? 2 : 4;
    constexpr int K  = (MODE == 0 || MODE == 1) ? 256 : 2048;   // row stride
    constexpr int KT = (MODE == 3) ? 32 : K / BK;               // mode3: half K per CTA
    constexpr int STAGE_BYTES = TILES * TILE_BYTES;
    constexpr int SLOT_BH = (NTERMS == 1) ? 1 : 2;

    extern __shared__ uint32_t smem_w[];
    const uint32_t sbase = (smem_u32(smem_w) + 127u) & ~127u;

    const int tid = threadIdx.x;
    const int wid = tid >> 5, lid = tid & 31;
    const int z = blockIdx.z;
    const int rowBase = blockIdx.y * BM;
    const int colBase = blockIdx.x * BN;

    const bf16 *Ah, *Al = nullptr, *Bh, *Bl = nullptr;
    if (MODE == 0) {
        Ah = g_xh;  Al = g_xl;  Bh = g_Wqh; Bl = g_Wql;
    } else if (MODE == 1) {
        const size_t o = (size_t)z * TLEN * FDIM;
        Ah = g_Qh + o; Bh = g_Kh + o;
    } else if (MODE == 2) {
        const size_t oa = (size_t)z * TLEN * TLEN;
        const size_t ob = (size_t)z * FDIM * TLEN;
        Ah = g_Ph + oa; Al = g_Pl + oa; Bh = g_Vth + ob; Bl = g_Vtl + ob;
    } else {
        Ah = g_ah;  Al = g_al;  Bh = g_Wph; Bl = g_Wpl;
    }
    Ah += (size_t)rowBase * K;
    Bh += (size_t)colBase * K;
    if (NTERMS == 3) { Al += (size_t)rowBase * K; Bl += (size_t)colBase * K; }
    if (MODE == 3) {   // K-split: second half starts at k=1024
        const int ko = z * 1024;
        Ah += ko; Al += ko; Bh += ko; Bl += ko;
    }

    // loader: per tile 512 chunks of 16B; 256 threads x 2; swizzled placement
    auto load_tile = [&](int kt, int s) {
        const uint32_t base = sbase + s * STAGE_BYTES;
        const int kofs = kt * BK;
        #pragma unroll
        for (int i = 0; i < 2; ++i) {
            const int f   = tid + 256 * i;
            const int row = f >> 2;
            const int c   = f & 3;
            const uint32_t so = (uint32_t)(row * 64) + (uint32_t)((c ^ ((row >> 1) & 3)) << 4);
            const size_t go = (size_t)row * K + kofs + c * 8;
            cp_async16(base + so,                         Ah + go);
            cp_async16(base + SLOT_BH * TILE_BYTES + so,  Bh + go);
            if (NTERMS == 3) {
                cp_async16(base + 1 * TILE_BYTES + so,    Al + go);
                cp_async16(base + 3 * TILE_BYTES + so,    Bl + go);
            }
        }
        cp_commit();
    };

    const int warp_m = wid & 3;   // 4 warps x 32 rows
    const int warp_n = wid >> 2;  // 2 warps x 64 cols
    const int gid = lid >> 2;     // 0..7
    const int tig = lid & 3;      // 0..3

    // ldmatrix lane addresses (swizzled), ks=0; ks=1 is addr^32
    const int R_A = 32 * warp_m + (lid & 7) + ((lid >> 3) & 1) * 8;
    const int c_A = (lid >> 4) & 1;
    const uint32_t aA0 = sbase + (uint32_t)(R_A * 64) +
                         (uint32_t)((c_A ^ ((R_A >> 1) & 3)) << 4);
    const int R_B = 64 * warp_n + (lid & 7) + ((lid >> 4) & 1) * 8;
    const int c_B = (lid >> 3) & 1;
    const uint32_t aB0 = sbase + SLOT_BH * TILE_BYTES + (uint32_t)(R_B * 64) +
                         (uint32_t)((c_B ^ ((R_B >> 1) & 3)) << 4);

    float acc[2][8][4];
    #pragma unroll
    for (int i = 0; i < 2; ++i)
        #pragma unroll
        for (int j = 0; j < 8; ++j)
            #pragma unroll
            for (int c = 0; c < 4; ++c) acc[i][j][c] = 0.f;

    load_tile(0, 0);
    if (KT > 1) load_tile(1, 1);

    int s = 0;
    #pragma unroll 1
    for (int kt = 0; kt < KT; ++kt) {
        const int rem = KT - 1 - kt;
        if (rem >= 2) {
            int sp2 = s - 1; if (sp2 < 0) sp2 = 2;     // (s+2)%3
            load_tile(kt + 2, sp2);
            cp_wait<2>();
        } else if (rem == 1) {
            cp_wait<1>();
        } else {
            cp_wait<0>();
        }
        __syncthreads();

        const uint32_t aAh = aA0 + s * STAGE_BYTES;
        const uint32_t aBh = aB0 + s * STAGE_BYTES;

        #pragma unroll
        for (int ks = 0; ks < 2; ++ks) {             // two m16n8k16 K-steps per BK=32
            const uint32_t kx = (uint32_t)(ks * 32);  // ks=1: flip bit5

            uint32_t ah[2][4], al[2][4];
            #pragma unroll
            for (int i = 0; i < 2; ++i) {
                const uint32_t a0 = (aAh + (uint32_t)(i * 1024)) ^ kx;
                ldmx4(ah[i][0], ah[i][1], ah[i][2], ah[i][3], a0);
                if (NTERMS == 3)
                    ldmx4(al[i][0], al[i][1], al[i][2], al[i][3], a0 + TILE_BYTES);
            }

            #pragma unroll
            for (int jh = 0; jh < 2; ++jh) {         // halves of 4 columns (reg pressure)
                uint32_t bh[4][2], bl[4][2];
                #pragma unroll
                for (int jp = 0; jp < 2; ++jp) {     // j-pairs: cols 8J..8J+15
                    const int J = jh * 4 + jp * 2;
                    const uint32_t b0 = (aBh + (uint32_t)(J * 512)) ^ kx;
                    ldmx4(bh[2*jp][0], bh[2*jp][1], bh[2*jp+1][0], bh[2*jp+1][1], b0);
                    if (NTERMS == 3)
                        ldmx4(bl[2*jp][0], bl[2*jp][1], bl[2*jp+1][0], bl[2*jp+1][1],
                              b0 + TILE_BYTES);
                }
                #pragma unroll
                for (int i = 0; i < 2; ++i)
                    #pragma unroll
                    for (int j = 0; j < 4; ++j) {
                        float* c = acc[i][jh * 4 + j];
                        mma_bf16(c, ah[i], bh[j]);           // hi*hi
                        if (NTERMS == 3) {
                            mma_bf16(c, ah[i], bl[j]);       // hi*lo
                            mma_bf16(c, al[i], bh[j]);       // lo*hi
                        }
                    }
            }
        }
        __syncthreads();   // all warps done with stage s before loads reuse it
        s = (s == 2) ? 0 : s + 1;
    }

    // ---------------- epilogue ----------------
    const int gm = rowBase + 32 * warp_m;
    const int gn = colBase + 64 * warp_n + 2 * tig;

    if (MODE == 0) {
        // permuted columns: jj = part*2048 + h*256 + f ; part & head uniform per CTA
        const int part  = colBase >> 11;
        const int hh    = (colBase >> 8) & 7;
        const int fwarp = (colBase & 255) + 64 * warp_n + 2 * tig;
        const float scl = (part == 2) ? 1.0f : 0.0625f;

        #pragma unroll
        for (int i = 0; i < 2; ++i) {
            #pragma unroll
            for (int h = 0; h < 2; ++h) {
                const int m = gm + 16 * i + gid + 8 * h;
                const int b = m >> 11, t = m & (TLEN - 1);
                const size_t rowO = ((size_t)(b * NHEAD + hh) * TLEN + t) * FDIM;
                #pragma unroll
                for (int j = 0; j < 8; ++j) {
                    const int f0 = fwarp + 8 * j;
                    const int borig = hh * (FDIM * 3) + f0 * 3 + part;
                    float v0 = (acc[i][j][2 * h]     + bias[borig])     * scl;
                    float v1 = (acc[i][j][2 * h + 1] + bias[borig + 3]) * scl;
                    if (part == 0) {
                        *(uint32_t*)(g_Qh + rowO + f0) = pack_hi(v0, v1);
                    } else if (part == 1) {
                        *(uint32_t*)(g_Kh + rowO + f0) = pack_hi(v0, v1);
                    } else {
                        uint32_t hw, lw;
                        split_pair(make_float2(v0, v1), hw, lw);
                        *(uint32_t*)(g_Vnh + rowO + f0) = hw;
                        *(uint32_t*)(g_Vnl + rowO + f0) = lw;
                    }
                }
            }
        }
        return;
    }

    #pragma unroll
    for (int i = 0; i < 2; ++i) {
        #pragma unroll
        for (int h = 0; h < 2; ++h) {
            const int m = gm + 16 * i + gid + 8 * h;

            if (MODE == 1) {
                // e = exp(score); store split bf16; deterministic row partial sums
                const size_t ro = (size_t)z * TLEN * TLEN + (size_t)m * TLEN + gn;
                uint32_t* ph = (uint32_t*)(g_Ph + ro);
                uint32_t* pl = (uint32_t*)(g_Pl + ro);
                float rsum = 0.f;
                #pragma unroll
                for (int j = 0; j < 8; ++j) {
                    const float e0 = __expf(acc[i][j][2 * h]);
                    const float e1 = __expf(acc[i][j][2 * h + 1]);
                    rsum += e0 + e1;
                    uint32_t hw, lw;
                    split_pair(make_float2(e0, e1), hw, lw);
                    ph[4 * j] = hw;
                    pl[4 * j] = lw;
                }
                // reduce over the 4 col-lanes (tig) of this row
                rsum += __shfl_xor_sync(0xffffffffu, rsum, 1);
                rsum += __shfl_xor_sync(0xffffffffu, rsum, 2);
                if (tig == 0) {
                    const int px = (colBase >> 6) + warp_n;   // 0..31
                    g_rsum[((size_t)z * TLEN + m) * 32 + px] = rsum;
                }
            } else if (MODE == 2) {
                const float inv = __ldg(&g_rinv[(size_t)z * TLEN + m]);
                const int b = z >> 3, hh = z & 7;
                const size_t base = ((size_t)(b * TLEN + m)) * (NHEAD * FDIM) + hh * FDIM + gn;
                #pragma unroll
                for (int j = 0; j < 8; ++j) {
                    uint32_t hw, lw;
                    split_pair(make_float2(acc[i][j][2 * h] * inv,
                                           acc[i][j][2 * h + 1] * inv), hw, lw);
                    *(uint32_t*)(g_ah + base + 8 * j) = hw;
                    *(uint32_t*)(g_al + base + 8 * j) = lw;
                }
            } else {
                float* p = g_p3 + (size_t)z * (8192 * FDIM) + (size_t)m * FDIM + gn;
                #pragma unroll
                for (int j = 0; j < 8; ++j)
                    *(float2*)(p + 8 * j) = make_float2(acc[i][j][2 * h], acc[i][j][2 * h + 1]);
            }
        }
    }
}

// ---------------- row inverse-sum: 65536 rows x 32 partials ----------------
__global__ void __launch_bounds__(256) rinv_kernel()
{
    const int r = blockIdx.x * 256 + threadIdx.x;
    const float4* p = (const float4*)(g_rsum + (size_t)r * 32);
    float s = 0.f;
    #pragma unroll
    for (int i = 0; i < 8; ++i) {
        const float4 v = p[i];
        s += (v.x + v.y) + (v.z + v.w);
    }
    g_rinv[r] = 1.0f / s;
}

// ---------------- split-K combine: out = p3[0] + p3[1] + bias ----------------
__global__ void __launch_bounds__(256) combine_kernel(const float* __restrict__ bias,
                                                      float* __restrict__ out)
{
    const size_t i = ((size_t)blockIdx.x * 256 + threadIdx.x) * 4;
    const int col = (int)(i & (FDIM - 1));
    const float4 a = *(const float4*)(g_p3 + i);
    const float4 b = *(const float4*)(g_p3 + (size_t)8192 * FDIM + i);
    const float4 bv = *(const float4*)(bias + col);
    float4 o;
    o.x = a.x + b.x + bv.x;
    o.y = a.y + b.y + bv.y;
    o.z = a.z + b.z + bv.z;
    o.w = a.w + b.w + bv.w;
    *(float4*)(out + i) = o;
}

// ---------------- input split: x -> g_xh/g_xl ----------------
__global__ void __launch_bounds__(256) split_x_kernel(const float* __restrict__ x)
{
    const size_t i = ((size_t)blockIdx.x * 256 + threadIdx.x) * 4;
    const float4 v = *(const float4*)(x + i);
    uint32_t h0, l0, h1, l1;
    split_pair(make_float2(v.x, v.y), h0, l0);
    split_pair(make_float2(v.z, v.w), h1, l1);
    *(uint32_t*)(g_xh + i)     = h0;
    *(uint32_t*)(g_xh + i + 2) = h1;
    *(uint32_t*)(g_xl + i)     = l0;
    *(uint32_t*)(g_xl + i + 2) = l1;
}

// ---------------- W_qkv transpose + column permutation + split ----------------
__global__ void __launch_bounds__(256) wqkv_prep_kernel(const float* __restrict__ in)
{
    __shared__ float t[32][33];
    const int c0 = blockIdx.x * 32;
    const int r0 = blockIdx.y * 32;
    const int tx = threadIdx.x, ty = threadIdx.y;
    #pragma unroll
    for (int i = 0; i < 32; i += 8)
        t[ty + i][tx] = in[(size_t)(r0 + ty + i) * (NHEAD * FDIM * 3) + c0 + tx];
    __syncthreads();
    #pragma unroll
    for (int i = 0; i < 32; i += 8) {
        const int corig = c0 + ty + i;
        const int hh  = corig / (FDIM * 3);
        const int rem = corig - hh * (FDIM * 3);
        const int f   = rem / 3;
        const int prt = rem - f * 3;
        const int cnew = prt * (NHEAD * FDIM) + hh * FDIM + f;
        bf16 vh, vl;
        split1(t[tx][ty + i], vh, vl);
        g_Wqh[(size_t)cnew * FDIM + r0 + tx] = vh;
        g_Wql[(size_t)cnew * FDIM + r0 + tx] = vl;
    }
}

// ---------------- W_proj transpose + split: [2048][256] -> [256][2048] ----------------
__global__ void __launch_bounds__(256) wproj_prep_kernel(const float* __restrict__ in)
{
    __shared__ float t[32][33];
    const int c0 = blockIdx.x * 32;
    const int r0 = blockIdx.y * 32;
    const int tx = threadIdx.x, ty = threadIdx.y;
    #pragma unroll
    for (int i = 0; i < 32; i += 8)
        t[ty + i][tx] = in[(size_t)(r0 + ty + i) * FDIM + c0 + tx];
    __syncthreads();
    #pragma unroll
    for (int i = 0; i < 32; i += 8) {
        bf16 vh, vl;
        split1(t[tx][ty + i], vh, vl);
        g_Wph[(size_t)(c0 + ty + i) * (NHEAD * FDIM) + r0 + tx] = vh;
        g_Wpl[(size_t)(c0 + ty + i) * (NHEAD * FDIM) + r0 + tx] = vl;
    }
}

// ---------------- V transpose: [bh][t][f] -> [bh][f][t] (hi & lo) ----------------
__global__ void __launch_bounds__(256) vtrans_kernel()
{
    __shared__ bf16 th[32][33], tl[32][33];
    const int bh = blockIdx.z;
    const int f0 = blockIdx.x * 32;
    const int t0 = blockIdx.y * 32;
    const int tx = threadIdx.x, ty = threadIdx.y;
    const size_t inb = ((size_t)bh * TLEN + t0) * FDIM + f0;
    #pragma unroll
    for (int i = 0; i < 32; i += 8) {
        th[ty + i][tx] = g_Vnh[inb + (size_t)(ty + i) * FDIM + tx];
        tl[ty + i][tx] = g_Vnl[inb + (size_t)(ty + i) * FDIM + tx];
    }
    __syncthreads();
    const size_t outb = ((size_t)bh * FDIM + f0) * TLEN + t0;
    #pragma unroll
    for (int i = 0; i < 32; i += 8) {
        g_Vth[outb + (size_t)(ty + i) * TLEN + tx] = th[tx][ty + i];
        g_Vtl[outb + (size_t)(ty + i) * TLEN + tx] = tl[tx][ty + i];
    }
}

// ---------------- launch ----------------
extern "C" void kernel_launch(void* const* d_in, const int* in_sizes, int n_in,
                              void* d_out, int out_size)
{
    const float* x     = (const float*)d_in[0];
    const float* Wqkv  = (const float*)d_in[1];
    const float* bqkv  = (const float*)d_in[2];
    const float* Wproj = (const float*)d_in[3];
    const float* bproj = (const float*)d_in[4];
    float* out = (float*)d_out;

    cudaFuncSetAttribute(mma_gemm<0>, cudaFuncAttributeMaxDynamicSharedMemorySize, SMEM_FULL);
    cudaFuncSetAttribute(mma_gemm<1>, cudaFuncAttributeMaxDynamicSharedMemorySize, SMEM_HI);
    cudaFuncSetAttribute(mma_gemm<2>, cudaFuncAttributeMaxDynamicSharedMemorySize, SMEM_FULL);
    cudaFuncSetAttribute(mma_gemm<3>, cudaFuncAttributeMaxDynamicSharedMemorySize, SMEM_FULL);

    // prep: split x; transpose(+permute)+split weights
    split_x_kernel<<<(NBATCH * TLEN * FDIM) / 1024, 256>>>(x);
    wqkv_prep_kernel<<<dim3(6144 / 32, 256 / 32), dim3(32, 8)>>>(Wqkv);
    wproj_prep_kernel<<<dim3(256 / 32, 2048 / 32), dim3(32, 8)>>>(Wproj);

    // 1) QKV GEMM (+bias, scale) -> Qh/Kh hi, V split natural
    mma_gemm<0><<<dim3(6144 / BN, 8192 / BM, 1), 256, SMEM_FULL>>>(bqkv, nullptr);
    // 1b) V transpose -> Vth/Vtl
    vtrans_kernel<<<dim3(FDIM / 32, TLEN / 32, NBH), dim3(32, 8)>>>();
    // 2) E = exp(Qh Kh^T) (fused softmax numerator) -> split bf16 + row partial sums
    mma_gemm<1><<<dim3(TLEN / BN, TLEN / BM, NBH), 256, SMEM_HI>>>(nullptr, nullptr);
    // 2b) 1/rowsum
    rinv_kernel<<<(NBH * TLEN) / 256, 256>>>();
    // 3) out = (E V) * rinv (batched, NT against Vt) -> split bf16 attn
    mma_gemm<2><<<dim3(FDIM / BN, TLEN / BM, NBH), 256, SMEM_FULL>>>(nullptr, nullptr);
    // 4) proj split-K x2 -> partials
    mma_gemm<3><<<dim3(FDIM / BN, 8192 / BM, 2), 256, SMEM_FULL>>>(nullptr, nullptr);
    // 4b) combine + bias -> fp32 out
    combine_kernel<<<(8192 * FDIM) / 1024, 256>>>(bproj, out);
}

// round 14
// speedup vs baseline: 2.7398x; 1.5976x over previous
#include <cuda_runtime.h>
#include <cuda_bf16.h>
#include <cuda_fp16.h>
#include <cstdint>
#include <math.h>

#define TLEN   2048
#define FDIM   256
#define NHEAD  8
#define NBATCH 4
#define NBH    32

typedef __nv_bfloat16 bf16;
typedef __half fp16;

// ---------------- scratch (__device__ globals; no allocation allowed) ----------------
__device__ __align__(16) bf16 g_xh [(size_t)NBATCH * TLEN * FDIM];
__device__ __align__(16) bf16 g_xl [(size_t)NBATCH * TLEN * FDIM];
__device__ __align__(16) bf16 g_Wqh[(size_t)(NHEAD * FDIM * 3) * FDIM];   // permuted WqkvT hi [6144][256]
__device__ __align__(16) bf16 g_Wql[(size_t)(NHEAD * FDIM * 3) * FDIM];
__device__ __align__(16) fp16 g_Q  [(size_t)NBH * TLEN * FDIM];           // [bh][t][f] fp16
__device__ __align__(16) fp16 g_K  [(size_t)NBH * TLEN * FDIM];           // fp16
__device__ __align__(16) fp16 g_Vn [(size_t)NBH * TLEN * FDIM];           // V natural fp16
__device__ __align__(16) fp16 g_Vt [(size_t)NBH * FDIM * TLEN];           // V transposed fp16
__device__ __align__(16) fp16 g_P  [(size_t)NBH * TLEN * TLEN];           // e=exp(s) fp16
__device__ __align__(16) fp16 g_a  [(size_t)NBATCH * TLEN * NHEAD * FDIM];// attn fp16 [b][t][h*f]
__device__ __align__(16) fp16 g_Wp [(size_t)FDIM * (NHEAD * FDIM)];       // WprojT fp16 [256][2048]
__device__ __align__(16) float g_rsum[(size_t)NBH * TLEN * 32];           // per-row partial sums
__device__ __align__(16) float g_rinv[(size_t)NBH * TLEN];                // 1/rowsum
__device__ __align__(16) float g_p3  [(size_t)2 * NBATCH * TLEN * FDIM];  // mode-3 split-K partials

// ---------------- helpers ----------------
__device__ __forceinline__ uint32_t smem_u32(const void* p) {
    uint32_t a;
    asm("{ .reg .u64 t; cvta.to.shared.u64 t, %1; cvt.u32.u64 %0, t; }" : "=r"(a) : "l"(p));
    return a;
}
__device__ __forceinline__ void cp_async16(uint32_t dst, const void* src) {
    asm volatile("cp.async.cg.shared.global [%0], [%1], 16;" :: "r"(dst), "l"(src) : "memory");
}
__device__ __forceinline__ void cp_commit() {
    asm volatile("cp.async.commit_group;" ::: "memory");
}
template<int N> __device__ __forceinline__ void cp_wait() {
    asm volatile("cp.async.wait_group %0;" :: "n"(N) : "memory");
}
__device__ __forceinline__ void mma_bf16(float* c, const uint32_t* a, const uint32_t* b) {
    asm volatile(
        "mma.sync.aligned.m16n8k16.row.col.f32.bf16.bf16.f32 "
        "{%0,%1,%2,%3}, {%4,%5,%6,%7}, {%8,%9}, {%0,%1,%2,%3};"
        : "+f"(c[0]), "+f"(c[1]), "+f"(c[2]), "+f"(c[3])
        : "r"(a[0]), "r"(a[1]), "r"(a[2]), "r"(a[3]), "r"(b[0]), "r"(b[1]));
}
__device__ __forceinline__ void mma_f16(float* c, const uint32_t* a, const uint32_t* b) {
    asm volatile(
        "mma.sync.aligned.m16n8k16.row.col.f32.f16.f16.f32 "
        "{%0,%1,%2,%3}, {%4,%5,%6,%7}, {%8,%9}, {%0,%1,%2,%3};"
        : "+f"(c[0]), "+f"(c[1]), "+f"(c[2]), "+f"(c[3])
        : "r"(a[0]), "r"(a[1]), "r"(a[2]), "r"(a[3]), "r"(b[0]), "r"(b[1]));
}
__device__ __forceinline__ void ldmx4(uint32_t& r0, uint32_t& r1, uint32_t& r2, uint32_t& r3,
                                      uint32_t addr) {
    asm volatile("ldmatrix.sync.aligned.m8n8.x4.shared.b16 {%0,%1,%2,%3}, [%4];"
                 : "=r"(r0), "=r"(r1), "=r"(r2), "=r"(r3) : "r"(addr));
}
// pack two fp32 -> fp16x2 word (.x in low half)
__device__ __forceinline__ uint32_t pack_f16(float lo, float hi) {
    uint32_t h;
    asm("cvt.rn.f16x2.f32 %0, %1, %2;" : "=r"(h) : "f"(hi), "f"(lo));
    return h;
}
// split fp32 pair -> packed bf16x2 hi + bf16x2 lo residual (.x in low half)
__device__ __forceinline__ void split_pair(float2 f, uint32_t& hi, uint32_t& lo) {
    uint32_t h;
    asm("cvt.rn.bf16x2.f32 %0, %1, %2;" : "=r"(h) : "f"(f.y), "f"(f.x));
    const float h0 = __uint_as_float(h << 16);
    const float h1 = __uint_as_float(h & 0xffff0000u);
    asm("cvt.rn.bf16x2.f32 %0, %1, %2;" : "=r"(lo) : "f"(f.y - h1), "f"(f.x - h0));
    hi = h;
}
__device__ __forceinline__ void split1(float v, bf16& h, bf16& l) {
    h = __float2bfloat16(v);
    l = __float2bfloat16(v - __bfloat162float(h));
}

// ---------------- GEMM config ----------------
// Swizzled tile: 128 rows x 64B (32 elems of 2B). chunk' = chunk ^ ((row>>1)&3); no padding.
constexpr int BM = 128, BN = 128, BK = 32;
constexpr int TILE_BYTES = BM * 64;                    // 8192
constexpr int STAGES = 3;
constexpr int SMEM_FULL = STAGES * 4 * TILE_BYTES + 128;  // 98432 (Ah,Al,Bh,Bl)
constexpr int SMEM_HI   = STAGES * 2 * TILE_BYTES + 128;  // 49280 (A,B)

// MODE 0: C[8192,6144] = x @ WqkvT'^T  (K=256, bf16 3-term) -> Q/K/V fp16 (+bias,*1/16)
// MODE 1: C[2048,2048] = Q @ K^T       (K=256, fp16 1-term) -> P=exp(s) fp16 + row partial sums
// MODE 2: C[2048, 256] = P @ Vt^T      (K=2048, fp16 1-term) -> *rinv[m] -> g_a fp16
// MODE 3: C[8192, 256] = attn @ Wp^T   (fp16 1-term, split-K x2) -> g_p3 fp32 partials
template<int MODE>
__global__ void __launch_bounds__(256, 2)
mma_gemm(const float* __restrict__ bias, float* __restrict__ Cgp)
{
    constexpr int NTERMS = (MODE == 0) ? 3 : 1;
    constexpr int TILES  = (NTERMS == 1) ? 2 : 4;
    constexpr int K  = (MODE == 0 || MODE == 1) ? 256 : 2048;   // row stride (elements)
    constexpr int KT = (MODE == 3) ? 32 : K / BK;               // mode3: half K per CTA
    constexpr int STAGE_BYTES = TILES * TILE_BYTES;
    constexpr int SLOT_BH = (NTERMS == 1) ? 1 : 2;

    extern __shared__ uint32_t smem_w[];
    const uint32_t sbase = (smem_u32(smem_w) + 127u) & ~127u;

    const int tid = threadIdx.x;
    const int wid = tid >> 5, lid = tid & 31;
    const int z = blockIdx.z;
    const int rowBase = blockIdx.y * BM;
    const int colBase = blockIdx.x * BN;

    const uint16_t *Ah, *Al = nullptr, *Bh, *Bl = nullptr;
    if (MODE == 0) {
        Ah = (const uint16_t*)g_xh;  Al = (const uint16_t*)g_xl;
        Bh = (const uint16_t*)g_Wqh; Bl = (const uint16_t*)g_Wql;
    } else if (MODE == 1) {
        const size_t o = (size_t)z * TLEN * FDIM;
        Ah = (const uint16_t*)g_Q + o; Bh = (const uint16_t*)g_K + o;
    } else if (MODE == 2) {
        Ah = (const uint16_t*)g_P  + (size_t)z * TLEN * TLEN;
        Bh = (const uint16_t*)g_Vt + (size_t)z * FDIM * TLEN;
    } else {
        Ah = (const uint16_t*)g_a;  Bh = (const uint16_t*)g_Wp;
    }
    Ah += (size_t)rowBase * K;
    Bh += (size_t)colBase * K;
    if (NTERMS == 3) { Al += (size_t)rowBase * K; Bl += (size_t)colBase * K; }
    if (MODE == 3) {   // K-split: second half starts at k=1024
        const int ko = z * 1024;
        Ah += ko; Bh += ko;
    }

    // loader: per tile 512 chunks of 16B; 256 threads x 2; swizzled placement
    auto load_tile = [&](int kt, int s) {
        const uint32_t base = sbase + s * STAGE_BYTES;
        const int kofs = kt * BK;
        #pragma unroll
        for (int i = 0; i < 2; ++i) {
            const int f   = tid + 256 * i;
            const int row = f >> 2;
            const int c   = f & 3;
            const uint32_t so = (uint32_t)(row * 64) + (uint32_t)((c ^ ((row >> 1) & 3)) << 4);
            const size_t go = (size_t)row * K + kofs + c * 8;
            cp_async16(base + so,                         Ah + go);
            cp_async16(base + SLOT_BH * TILE_BYTES + so,  Bh + go);
            if (NTERMS == 3) {
                cp_async16(base + 1 * TILE_BYTES + so,    Al + go);
                cp_async16(base + 3 * TILE_BYTES + so,    Bl + go);
            }
        }
        cp_commit();
    };

    const int warp_m = wid & 3;   // 4 warps x 32 rows
    const int warp_n = wid >> 2;  // 2 warps x 64 cols
    const int gid = lid >> 2;     // 0..7
    const int tig = lid & 3;      // 0..3

    // ldmatrix lane addresses (swizzled), ks=0; ks=1 is addr^32
    const int R_A = 32 * warp_m + (lid & 7) + ((lid >> 3) & 1) * 8;
    const int c_A = (lid >> 4) & 1;
    const uint32_t aA0 = sbase + (uint32_t)(R_A * 64) +
                         (uint32_t)((c_A ^ ((R_A >> 1) & 3)) << 4);
    const int R_B = 64 * warp_n + (lid & 7) + ((lid >> 4) & 1) * 8;
    const int c_B = (lid >> 3) & 1;
    const uint32_t aB0 = sbase + SLOT_BH * TILE_BYTES + (uint32_t)(R_B * 64) +
                         (uint32_t)((c_B ^ ((R_B >> 1) & 3)) << 4);

    float acc[2][8][4];
    #pragma unroll
    for (int i = 0; i < 2; ++i)
        #pragma unroll
        for (int j = 0; j < 8; ++j)
            #pragma unroll
            for (int c = 0; c < 4; ++c) acc[i][j][c] = 0.f;

    load_tile(0, 0);
    if (KT > 1) load_tile(1, 1);

    int s = 0;
    #pragma unroll 1
    for (int kt = 0; kt < KT; ++kt) {
        const int rem = KT - 1 - kt;
        if (rem >= 2) {
            int sp2 = s - 1; if (sp2 < 0) sp2 = 2;     // (s+2)%3
            load_tile(kt + 2, sp2);
            cp_wait<2>();
        } else if (rem == 1) {
            cp_wait<1>();
        } else {
            cp_wait<0>();
        }
        __syncthreads();

        const uint32_t aAh = aA0 + s * STAGE_BYTES;
        const uint32_t aBh = aB0 + s * STAGE_BYTES;

        #pragma unroll
        for (int ks = 0; ks < 2; ++ks) {             // two m16n8k16 K-steps per BK=32
            const uint32_t kx = (uint32_t)(ks * 32);  // ks=1: flip bit5

            uint32_t ah[2][4], al[2][4];
            #pragma unroll
            for (int i = 0; i < 2; ++i) {
                const uint32_t a0 = (aAh + (uint32_t)(i * 1024)) ^ kx;
                ldmx4(ah[i][0], ah[i][1], ah[i][2], ah[i][3], a0);
                if (NTERMS == 3)
                    ldmx4(al[i][0], al[i][1], al[i][2], al[i][3], a0 + TILE_BYTES);
            }

            #pragma unroll
            for (int jh = 0; jh < 2; ++jh) {         // halves of 4 columns (reg pressure)
                uint32_t bh[4][2], bl[4][2];
                #pragma unroll
                for (int jp = 0; jp < 2; ++jp) {     // j-pairs: cols 8J..8J+15
                    const int J = jh * 4 + jp * 2;
                    const uint32_t b0 = (aBh + (uint32_t)(J * 512)) ^ kx;
                    ldmx4(bh[2*jp][0], bh[2*jp][1], bh[2*jp+1][0], bh[2*jp+1][1], b0);
                    if (NTERMS == 3)
                        ldmx4(bl[2*jp][0], bl[2*jp][1], bl[2*jp+1][0], bl[2*jp+1][1],
                              b0 + TILE_BYTES);
                }
                #pragma unroll
                for (int i = 0; i < 2; ++i)
                    #pragma unroll
                    for (int j = 0; j < 4; ++j) {
                        float* c = acc[i][jh * 4 + j];
                        if (MODE == 0) {
                            mma_bf16(c, ah[i], bh[j]);       // hi*hi
                            mma_bf16(c, ah[i], bl[j]);       // hi*lo
                            mma_bf16(c, al[i], bh[j]);       // lo*hi
                        } else {
                            mma_f16(c, ah[i], bh[j]);        // fp16 single term
                        }
                    }
            }
        }
        __syncthreads();   // all warps done with stage s before loads reuse it
        s = (s == 2) ? 0 : s + 1;
    }

    // ---------------- epilogue ----------------
    const int gm = rowBase + 32 * warp_m;
    const int gn = colBase + 64 * warp_n + 2 * tig;

    if (MODE == 0) {
        // permuted columns: jj = part*2048 + h*256 + f ; part & head uniform per CTA
        const int part  = colBase >> 11;
        const int hh    = (colBase >> 8) & 7;
        const int fwarp = (colBase & 255) + 64 * warp_n + 2 * tig;
        const float scl = (part == 2) ? 1.0f : 0.0625f;

        #pragma unroll
        for (int i = 0; i < 2; ++i) {
            #pragma unroll
            for (int h = 0; h < 2; ++h) {
                const int m = gm + 16 * i + gid + 8 * h;
                const int b = m >> 11, t = m & (TLEN - 1);
                const size_t rowO = ((size_t)(b * NHEAD + hh) * TLEN + t) * FDIM;
                #pragma unroll
                for (int j = 0; j < 8; ++j) {
                    const int f0 = fwarp + 8 * j;
                    const int borig = hh * (FDIM * 3) + f0 * 3 + part;
                    const float v0 = (acc[i][j][2 * h]     + bias[borig])     * scl;
                    const float v1 = (acc[i][j][2 * h + 1] + bias[borig + 3]) * scl;
                    const uint32_t w = pack_f16(v0, v1);
                    if      (part == 0) *(uint32_t*)(g_Q  + rowO + f0) = w;
                    else if (part == 1) *(uint32_t*)(g_K  + rowO + f0) = w;
                    else                *(uint32_t*)(g_Vn + rowO + f0) = w;
                }
            }
        }
        return;
    }

    #pragma unroll
    for (int i = 0; i < 2; ++i) {
        #pragma unroll
        for (int h = 0; h < 2; ++h) {
            const int m = gm + 16 * i + gid + 8 * h;

            if (MODE == 1) {
                // e = exp(score); store fp16; deterministic row partial sums
                const size_t ro = (size_t)z * TLEN * TLEN + (size_t)m * TLEN + gn;
                uint32_t* ph = (uint32_t*)(g_P + ro);
                float rsum = 0.f;
                #pragma unroll
                for (int j = 0; j < 8; ++j) {
                    const float e0 = __expf(acc[i][j][2 * h]);
                    const float e1 = __expf(acc[i][j][2 * h + 1]);
                    rsum += e0 + e1;
                    ph[4 * j] = pack_f16(e0, e1);
                }
                rsum += __shfl_xor_sync(0xffffffffu, rsum, 1);
                rsum += __shfl_xor_sync(0xffffffffu, rsum, 2);
                if (tig == 0) {
                    const int px = (colBase >> 6) + warp_n;   // 0..31
                    g_rsum[((size_t)z * TLEN + m) * 32 + px] = rsum;
                }
            } else if (MODE == 2) {
                const float inv = __ldg(&g_rinv[(size_t)z * TLEN + m]);
                const int b = z >> 3, hh = z & 7;
                const size_t base = ((size_t)(b * TLEN + m)) * (NHEAD * FDIM) + hh * FDIM + gn;
                #pragma unroll
                for (int j = 0; j < 8; ++j)
                    *(uint32_t*)(g_a + base + 8 * j) =
                        pack_f16(acc[i][j][2 * h] * inv, acc[i][j][2 * h + 1] * inv);
            } else {
                float* p = g_p3 + (size_t)z * (8192 * FDIM) + (size_t)m * FDIM + gn;
                #pragma unroll
                for (int j = 0; j < 8; ++j)
                    *(float2*)(p + 8 * j) = make_float2(acc[i][j][2 * h], acc[i][j][2 * h + 1]);
            }
        }
    }
}

// ---------------- row inverse-sum: 65536 rows x 32 partials ----------------
__global__ void __launch_bounds__(256) rinv_kernel()
{
    const int r = blockIdx.x * 256 + threadIdx.x;
    const float4* p = (const float4*)(g_rsum + (size_t)r * 32);
    float s = 0.f;
    #pragma unroll
    for (int i = 0; i < 8; ++i) {
        const float4 v = p[i];
        s += (v.x + v.y) + (v.z + v.w);
    }
    g_rinv[r] = 1.0f / s;
}

// ---------------- split-K combine: out = p3[0] + p3[1] + bias ----------------
__global__ void __launch_bounds__(256) combine_kernel(const float* __restrict__ bias,
                                                      float* __restrict__ out)
{
    const size_t i = ((size_t)blockIdx.x * 256 + threadIdx.x) * 4;
    const int col = (int)(i & (FDIM - 1));
    const float4 a = *(const float4*)(g_p3 + i);
    const float4 b = *(const float4*)(g_p3 + (size_t)8192 * FDIM + i);
    const float4 bv = *(const float4*)(bias + col);
    float4 o;
    o.x = a.x + b.x + bv.x;
    o.y = a.y + b.y + bv.y;
    o.z = a.z + b.z + bv.z;
    o.w = a.w + b.w + bv.w;
    *(float4*)(out + i) = o;
}

// ---------------- input split: x -> g_xh/g_xl (bf16 h+l) ----------------
__global__ void __launch_bounds__(256) split_x_kernel(const float* __restrict__ x)
{
    const size_t i = ((size_t)blockIdx.x * 256 + threadIdx.x) * 4;
    const float4 v = *(const float4*)(x + i);
    uint32_t h0, l0, h1, l1;
    split_pair(make_float2(v.x, v.y), h0, l0);
    split_pair(make_float2(v.z, v.w), h1, l1);
    *(uint32_t*)(g_xh + i)     = h0;
    *(uint32_t*)(g_xh + i + 2) = h1;
    *(uint32_t*)(g_xl + i)     = l0;
    *(uint32_t*)(g_xl + i + 2) = l1;
}

// ---------------- W_qkv transpose + column permutation + split (bf16 h+l) ----------------
__global__ void __launch_bounds__(256) wqkv_prep_kernel(const float* __restrict__ in)
{
    __shared__ float t[32][33];
    const int c0 = blockIdx.x * 32;
    const int r0 = blockIdx.y * 32;
    const int tx = threadIdx.x, ty = threadIdx.y;
    #pragma unroll
    for (int i = 0; i < 32; i += 8)
        t[ty + i][tx] = in[(size_t)(r0 + ty + i) * (NHEAD * FDIM * 3) + c0 + tx];
    __syncthreads();
    #pragma unroll
    for (int i = 0; i < 32; i += 8) {
        const int corig = c0 + ty + i;
        const int hh  = corig / (FDIM * 3);
        const int rem = corig - hh * (FDIM * 3);
        const int f   = rem / 3;
        const int prt = rem - f * 3;
        const int cnew = prt * (NHEAD * FDIM) + hh * FDIM + f;
        bf16 vh, vl;
        split1(t[tx][ty + i], vh, vl);
        g_Wqh[(size_t)cnew * FDIM + r0 + tx] = vh;
        g_Wql[(size_t)cnew * FDIM + r0 + tx] = vl;
    }
}

// ---------------- W_proj transpose -> fp16: [2048][256] -> [256][2048] ----------------
__global__ void __launch_bounds__(256) wproj_prep_kernel(const float* __restrict__ in)
{
    __shared__ float t[32][33];
    const int c0 = blockIdx.x * 32;
    const int r0 = blockIdx.y * 32;
    const int tx = threadIdx.x, ty = threadIdx.y;
    #pragma unroll
    for (int i = 0; i < 32; i += 8)
        t[ty + i][tx] = in[(size_t)(r0 + ty + i) * FDIM + c0 + tx];
    __syncthreads();
    #pragma unroll
    for (int i = 0; i < 32; i += 8)
        g_Wp[(size_t)(c0 + ty + i) * (NHEAD * FDIM) + r0 + tx] = __float2half(t[tx][ty + i]);
}

// ---------------- V transpose: [bh][t][f] -> [bh][f][t] (fp16) ----------------
__global__ void __launch_bounds__(256) vtrans_kernel()
{
    __shared__ fp16 th[32][33];
    const int bh = blockIdx.z;
    const int f0 = blockIdx.x * 32;
    const int t0 = blockIdx.y * 32;
    const int tx = threadIdx.x, ty = threadIdx.y;
    const size_t inb = ((size_t)bh * TLEN + t0) * FDIM + f0;
    #pragma unroll
    for (int i = 0; i < 32; i += 8)
        th[ty + i][tx] = g_Vn[inb + (size_t)(ty + i) * FDIM + tx];
    __syncthreads();
    const size_t outb = ((size_t)bh * FDIM + f0) * TLEN + t0;
    #pragma unroll
    for (int i = 0; i < 32; i += 8)
        g_Vt[outb + (size_t)(ty + i) * TLEN + tx] = th[tx][ty + i];
}

// ---------------- launch ----------------
extern "C" void kernel_launch(void* const* d_in, const int* in_sizes, int n_in,
                              void* d_out, int out_size)
{
    const float* x     = (const float*)d_in[0];
    const float* Wqkv  = (const float*)d_in[1];
    const float* bqkv  = (const float*)d_in[2];
    const float* Wproj = (const float*)d_in[3];
    const float* bproj = (const float*)d_in[4];
    float* out = (float*)d_out;

    cudaFuncSetAttribute(mma_gemm<0>, cudaFuncAttributeMaxDynamicSharedMemorySize, SMEM_FULL);
    cudaFuncSetAttribute(mma_gemm<1>, cudaFuncAttributeMaxDynamicSharedMemorySize, SMEM_HI);
    cudaFuncSetAttribute(mma_gemm<2>, cudaFuncAttributeMaxDynamicSharedMemorySize, SMEM_HI);
    cudaFuncSetAttribute(mma_gemm<3>, cudaFuncAttributeMaxDynamicSharedMemorySize, SMEM_HI);

    // prep: split x; transpose(+permute)+split weights
    split_x_kernel<<<(NBATCH * TLEN * FDIM) / 1024, 256>>>(x);
    wqkv_prep_kernel<<<dim3(6144 / 32, 256 / 32), dim3(32, 8)>>>(Wqkv);
    wproj_prep_kernel<<<dim3(256 / 32, 2048 / 32), dim3(32, 8)>>>(Wproj);

    // 1) QKV GEMM (+bias, scale) -> Q/K/V fp16
    mma_gemm<0><<<dim3(6144 / BN, 8192 / BM, 1), 256, SMEM_FULL>>>(bqkv, nullptr);
    // 1b) V transpose -> Vt
    vtrans_kernel<<<dim3(FDIM / 32, TLEN / 32, NBH), dim3(32, 8)>>>();
    // 2) P = exp(Q K^T) (fused softmax numerator) -> fp16 + row partial sums
    mma_gemm<1><<<dim3(TLEN / BN, TLEN / BM, NBH), 256, SMEM_HI>>>(nullptr, nullptr);
    // 2b) 1/rowsum
    rinv_kernel<<<(NBH * TLEN) / 256, 256>>>();
    // 3) attn = (P V) * rinv (batched, NT against Vt) -> fp16
    mma_gemm<2><<<dim3(FDIM / BN, TLEN / BM, NBH), 256, SMEM_HI>>>(nullptr, nullptr);
    // 4) proj split-K x2 -> fp32 partials
    mma_gemm<3><<<dim3(FDIM / BN, 8192 / BM, 2), 256, SMEM_HI>>>(nullptr, nullptr);
    // 4b) combine + bias -> fp32 out
    combine_kernel<<<(8192 * FDIM) / 1024, 256>>>(bproj, out);
}

// round 15
// speedup vs baseline: 2.9733x; 1.0852x over previous
#include <cuda_runtime.h>
#include <cuda_bf16.h>
#include <cuda_fp16.h>
#include <cstdint>
#include <math.h>

#define TLEN   2048
#define FDIM   256
#define NHEAD  8
#define NBATCH 4
#define NBH    32

typedef __nv_bfloat16 bf16;
typedef __half fp16;

// ---------------- scratch (__device__ globals; no allocation allowed) ----------------
__device__ __align__(16) bf16 g_xh [(size_t)NBATCH * TLEN * FDIM];        // x bf16 hi (V path)
__device__ __align__(16) bf16 g_xl [(size_t)NBATCH * TLEN * FDIM];        // x bf16 lo residual
__device__ __align__(16) fp16 g_xf [(size_t)NBATCH * TLEN * FDIM];        // x fp16 (QK path)
__device__ __align__(16) bf16 g_Wqh[(size_t)(NHEAD * FDIM * 3) * FDIM];   // permuted WqkvT hi [6144][256]
__device__ __align__(16) bf16 g_Wql[(size_t)(NHEAD * FDIM * 3) * FDIM];
__device__ __align__(16) fp16 g_Wqf[(size_t)(NHEAD * FDIM * 3) * FDIM];   // permuted WqkvT fp16
__device__ __align__(16) fp16 g_Q  [(size_t)NBH * TLEN * FDIM];           // [bh][t][f] fp16
__device__ __align__(16) fp16 g_K  [(size_t)NBH * TLEN * FDIM];           // fp16
__device__ __align__(16) fp16 g_Vn [(size_t)NBH * TLEN * FDIM];           // V natural fp16
__device__ __align__(16) fp16 g_Vt [(size_t)NBH * FDIM * TLEN];           // V transposed fp16
__device__ __align__(16) fp16 g_P  [(size_t)NBH * TLEN * TLEN];           // e=exp(s) fp16
__device__ __align__(16) fp16 g_a  [(size_t)NBATCH * TLEN * NHEAD * FDIM];// attn fp16 [b][t][h*f]
__device__ __align__(16) fp16 g_Wp [(size_t)FDIM * (NHEAD * FDIM)];       // WprojT fp16 [256][2048]
__device__ __align__(16) float g_rsum[(size_t)NBH * TLEN * 32];           // per-row partial sums
__device__ __align__(16) float g_rinv[(size_t)NBH * TLEN];                // 1/rowsum
__device__ __align__(16) float g_p3  [(size_t)2 * NBATCH * TLEN * FDIM];  // mode-3 split-K partials

// ---------------- helpers ----------------
__device__ __forceinline__ uint32_t smem_u32(const void* p) {
    uint32_t a;
    asm("{ .reg .u64 t; cvta.to.shared.u64 t, %1; cvt.u32.u64 %0, t; }" : "=r"(a) : "l"(p));
    return a;
}
__device__ __forceinline__ void cp_async16(uint32_t dst, const void* src) {
    asm volatile("cp.async.cg.shared.global [%0], [%1], 16;" :: "r"(dst), "l"(src) : "memory");
}
__device__ __forceinline__ void cp_commit() {
    asm volatile("cp.async.commit_group;" ::: "memory");
}
template<int N> __device__ __forceinline__ void cp_wait() {
    asm volatile("cp.async.wait_group %0;" :: "n"(N) : "memory");
}
__device__ __forceinline__ void mma_bf16(float* c, const uint32_t* a, const uint32_t* b) {
    asm volatile(
        "mma.sync.aligned.m16n8k16.row.col.f32.bf16.bf16.f32 "
        "{%0,%1,%2,%3}, {%4,%5,%6,%7}, {%8,%9}, {%0,%1,%2,%3};"
        : "+f"(c[0]), "+f"(c[1]), "+f"(c[2]), "+f"(c[3])
        : "r"(a[0]), "r"(a[1]), "r"(a[2]), "r"(a[3]), "r"(b[0]), "r"(b[1]));
}
__device__ __forceinline__ void mma_f16(float* c, const uint32_t* a, const uint32_t* b) {
    asm volatile(
        "mma.sync.aligned.m16n8k16.row.col.f32.f16.f16.f32 "
        "{%0,%1,%2,%3}, {%4,%5,%6,%7}, {%8,%9}, {%0,%1,%2,%3};"
        : "+f"(c[0]), "+f"(c[1]), "+f"(c[2]), "+f"(c[3])
        : "r"(a[0]), "r"(a[1]), "r"(a[2]), "r"(a[3]), "r"(b[0]), "r"(b[1]));
}
__device__ __forceinline__ void ldmx4(uint32_t& r0, uint32_t& r1, uint32_t& r2, uint32_t& r3,
                                      uint32_t addr) {
    asm volatile("ldmatrix.sync.aligned.m8n8.x4.shared.b16 {%0,%1,%2,%3}, [%4];"
                 : "=r"(r0), "=r"(r1), "=r"(r2), "=r"(r3) : "r"(addr));
}
// pack two fp32 -> fp16x2 word (.x in low half)
__device__ __forceinline__ uint32_t pack_f16(float lo, float hi) {
    uint32_t h;
    asm("cvt.rn.f16x2.f32 %0, %1, %2;" : "=r"(h) : "f"(hi), "f"(lo));
    return h;
}
// split fp32 pair -> packed bf16x2 hi + bf16x2 lo residual (.x in low half)
__device__ __forceinline__ void split_pair(float2 f, uint32_t& hi, uint32_t& lo) {
    uint32_t h;
    asm("cvt.rn.bf16x2.f32 %0, %1, %2;" : "=r"(h) : "f"(f.y), "f"(f.x));
    const float h0 = __uint_as_float(h << 16);
    const float h1 = __uint_as_float(h & 0xffff0000u);
    asm("cvt.rn.bf16x2.f32 %0, %1, %2;" : "=r"(lo) : "f"(f.y - h1), "f"(f.x - h0));
    hi = h;
}
__device__ __forceinline__ void split1(float v, bf16& h, bf16& l) {
    h = __float2bfloat16(v);
    l = __float2bfloat16(v - __bfloat162float(h));
}

// ---------------- GEMM config ----------------
// Swizzled tile: 128 rows x 64B (32 elems of 2B). chunk' = chunk ^ ((row>>1)&3); no padding.
constexpr int BM = 128, BN = 128, BK = 32;
constexpr int TILE_BYTES = BM * 64;                    // 8192
constexpr int STAGES = 3;
constexpr int SMEM_FULL = STAGES * 4 * TILE_BYTES + 128;  // 98432 (Ah,Al,Bh,Bl)
constexpr int SMEM_HI   = STAGES * 2 * TILE_BYTES + 128;  // 49280 (A,B)

// MODE 0: C = x @ WqkvT'^T (K=256). NTERMS=1: QK cols (fp16); NTERMS=3: V cols (bf16 split)
// MODE 1: C[2048,2048] = Q @ K^T       (K=256, fp16) -> P=exp(s) fp16 + row partial sums
// MODE 2: C[2048, 256] = P @ Vt^T      (K=2048, fp16) -> *rinv[m] -> g_a fp16
// MODE 3: C[8192, 256] = attn @ Wp^T   (fp16, split-K x2) -> g_p3 fp32 partials
template<int MODE, int NTERMS>
__global__ void __launch_bounds__(256, 2)
mma_gemm(const float* __restrict__ bias, float* __restrict__ Cgp, int colOfs)
{
    constexpr int TILES  = (NTERMS == 1) ? 2 : 4;
    constexpr int K  = (MODE == 0 || MODE == 1) ? 256 : 2048;   // row stride (elements)
    constexpr int KT = (MODE == 3) ? 32 : K / BK;               // mode3: half K per CTA
    constexpr int STAGE_BYTES = TILES * TILE_BYTES;
    constexpr int SLOT_BH = (NTERMS == 1) ? 1 : 2;

    extern __shared__ uint32_t smem_w[];
    const uint32_t sbase = (smem_u32(smem_w) + 127u) & ~127u;

    const int tid = threadIdx.x;
    const int wid = tid >> 5, lid = tid & 31;
    const int z = blockIdx.z;
    const int rowBase = blockIdx.y * BM;
    const int colBase = colOfs + blockIdx.x * BN;

    const uint16_t *Ah, *Al = nullptr, *Bh, *Bl = nullptr;
    if (MODE == 0) {
        if (NTERMS == 1) {
            Ah = (const uint16_t*)g_xf;  Bh = (const uint16_t*)g_Wqf;
        } else {
            Ah = (const uint16_t*)g_xh;  Al = (const uint16_t*)g_xl;
            Bh = (const uint16_t*)g_Wqh; Bl = (const uint16_t*)g_Wql;
        }
    } else if (MODE == 1) {
        const size_t o = (size_t)z * TLEN * FDIM;
        Ah = (const uint16_t*)g_Q + o; Bh = (const uint16_t*)g_K + o;
    } else if (MODE == 2) {
        Ah = (const uint16_t*)g_P  + (size_t)z * TLEN * TLEN;
        Bh = (const uint16_t*)g_Vt + (size_t)z * FDIM * TLEN;
    } else {
        Ah = (const uint16_t*)g_a;  Bh = (const uint16_t*)g_Wp;
    }
    Ah += (size_t)rowBase * K;
    Bh += (size_t)colBase * K;
    if (NTERMS == 3) { Al += (size_t)rowBase * K; Bl += (size_t)colBase * K; }
    if (MODE == 3) {   // K-split: second half starts at k=1024
        const int ko = z * 1024;
        Ah += ko; Bh += ko;
    }

    // loader: per tile 512 chunks of 16B; 256 threads x 2; swizzled placement
    auto load_tile = [&](int kt, int s) {
        const uint32_t base = sbase + s * STAGE_BYTES;
        const int kofs = kt * BK;
        #pragma unroll
        for (int i = 0; i < 2; ++i) {
            const int f   = tid + 256 * i;
            const int row = f >> 2;
            const int c   = f & 3;
            const uint32_t so = (uint32_t)(row * 64) + (uint32_t)((c ^ ((row >> 1) & 3)) << 4);
            const size_t go = (size_t)row * K + kofs + c * 8;
            cp_async16(base + so,                         Ah + go);
            cp_async16(base + SLOT_BH * TILE_BYTES + so,  Bh + go);
            if (NTERMS == 3) {
                cp_async16(base + 1 * TILE_BYTES + so,    Al + go);
                cp_async16(base + 3 * TILE_BYTES + so,    Bl + go);
            }
        }
        cp_commit();
    };

    const int warp_m = wid & 3;   // 4 warps x 32 rows
    const int warp_n = wid >> 2;  // 2 warps x 64 cols
    const int gid = lid >> 2;     // 0..7
    const int tig = lid & 3;      // 0..3

    // ldmatrix lane addresses (swizzled), ks=0; ks=1 is addr^32
    const int R_A = 32 * warp_m + (lid & 7) + ((lid >> 3) & 1) * 8;
    const int c_A = (lid >> 4) & 1;
    const uint32_t aA0 = sbase + (uint32_t)(R_A * 64) +
                         (uint32_t)((c_A ^ ((R_A >> 1) & 3)) << 4);
    const int R_B = 64 * warp_n + (lid & 7) + ((lid >> 4) & 1) * 8;
    const int c_B = (lid >> 3) & 1;
    const uint32_t aB0 = sbase + SLOT_BH * TILE_BYTES + (uint32_t)(R_B * 64) +
                         (uint32_t)((c_B ^ ((R_B >> 1) & 3)) << 4);

    float acc[2][8][4];
    #pragma unroll
    for (int i = 0; i < 2; ++i)
        #pragma unroll
        for (int j = 0; j < 8; ++j)
            #pragma unroll
            for (int c = 0; c < 4; ++c) acc[i][j][c] = 0.f;

    load_tile(0, 0);
    if (KT > 1) load_tile(1, 1);

    int s = 0;
    #pragma unroll 1
    for (int kt = 0; kt < KT; ++kt) {
        const int rem = KT - 1 - kt;
        if (rem >= 2) {
            int sp2 = s - 1; if (sp2 < 0) sp2 = 2;     // (s+2)%3
            load_tile(kt + 2, sp2);
            cp_wait<2>();
        } else if (rem == 1) {
            cp_wait<1>();
        } else {
            cp_wait<0>();
        }
        __syncthreads();

        const uint32_t aAh = aA0 + s * STAGE_BYTES;
        const uint32_t aBh = aB0 + s * STAGE_BYTES;

        #pragma unroll
        for (int ks = 0; ks < 2; ++ks) {             // two m16n8k16 K-steps per BK=32
            const uint32_t kx = (uint32_t)(ks * 32);  // ks=1: flip bit5

            uint32_t ah[2][4], al[2][4];
            #pragma unroll
            for (int i = 0; i < 2; ++i) {
                const uint32_t a0 = (aAh + (uint32_t)(i * 1024)) ^ kx;
                ldmx4(ah[i][0], ah[i][1], ah[i][2], ah[i][3], a0);
                if (NTERMS == 3)
                    ldmx4(al[i][0], al[i][1], al[i][2], al[i][3], a0 + TILE_BYTES);
            }

            #pragma unroll
            for (int jh = 0; jh < 2; ++jh) {         // halves of 4 columns (reg pressure)
                uint32_t bh[4][2], bl[4][2];
                #pragma unroll
                for (int jp = 0; jp < 2; ++jp) {     // j-pairs: cols 8J..8J+15
                    const int J = jh * 4 + jp * 2;
                    const uint32_t b0 = (aBh + (uint32_t)(J * 512)) ^ kx;
                    ldmx4(bh[2*jp][0], bh[2*jp][1], bh[2*jp+1][0], bh[2*jp+1][1], b0);
                    if (NTERMS == 3)
                        ldmx4(bl[2*jp][0], bl[2*jp][1], bl[2*jp+1][0], bl[2*jp+1][1],
                              b0 + TILE_BYTES);
                }
                #pragma unroll
                for (int i = 0; i < 2; ++i)
                    #pragma unroll
                    for (int j = 0; j < 4; ++j) {
                        float* c = acc[i][jh * 4 + j];
                        if (NTERMS == 3) {
                            mma_bf16(c, ah[i], bh[j]);       // hi*hi
                            mma_bf16(c, ah[i], bl[j]);       // hi*lo
                            mma_bf16(c, al[i], bh[j]);       // lo*hi
                        } else {
                            mma_f16(c, ah[i], bh[j]);        // fp16 single term
                        }
                    }
            }
        }
        __syncthreads();   // all warps done with stage s before loads reuse it
        s = (s == 2) ? 0 : s + 1;
    }

    // ---------------- epilogue ----------------
    const int gm = rowBase + 32 * warp_m;
    const int gn = colBase + 64 * warp_n + 2 * tig;

    if (MODE == 0) {
        // permuted columns: jj = part*2048 + h*256 + f ; part & head uniform per CTA
        const int part  = colBase >> 11;
        const int hh    = (colBase >> 8) & 7;
        const int fwarp = (colBase & 255) + 64 * warp_n + 2 * tig;
        const float scl = (part == 2) ? 1.0f : 0.0625f;

        #pragma unroll
        for (int i = 0; i < 2; ++i) {
            #pragma unroll
            for (int h = 0; h < 2; ++h) {
                const int m = gm + 16 * i + gid + 8 * h;
                const int b = m >> 11, t = m & (TLEN - 1);
                const size_t rowO = ((size_t)(b * NHEAD + hh) * TLEN + t) * FDIM;
                #pragma unroll
                for (int j = 0; j < 8; ++j) {
                    const int f0 = fwarp + 8 * j;
                    const int borig = hh * (FDIM * 3) + f0 * 3 + part;
                    const float v0 = (acc[i][j][2 * h]     + bias[borig])     * scl;
                    const float v1 = (acc[i][j][2 * h + 1] + bias[borig + 3]) * scl;
                    const uint32_t w = pack_f16(v0, v1);
                    if      (part == 0) *(uint32_t*)(g_Q  + rowO + f0) = w;
                    else if (part == 1) *(uint32_t*)(g_K  + rowO + f0) = w;
                    else                *(uint32_t*)(g_Vn + rowO + f0) = w;
                }
            }
        }
        return;
    }

    #pragma unroll
    for (int i = 0; i < 2; ++i) {
        #pragma unroll
        for (int h = 0; h < 2; ++h) {
            const int m = gm + 16 * i + gid + 8 * h;

            if (MODE == 1) {
                // e = exp(score); store fp16; deterministic row partial sums
                const size_t ro = (size_t)z * TLEN * TLEN + (size_t)m * TLEN + gn;
                uint32_t* ph = (uint32_t*)(g_P + ro);
                float rsum = 0.f;
                #pragma unroll
                for (int j = 0; j < 8; ++j) {
                    const float e0 = __expf(acc[i][j][2 * h]);
                    const float e1 = __expf(acc[i][j][2 * h + 1]);
                    rsum += e0 + e1;
                    ph[4 * j] = pack_f16(e0, e1);
                }
                rsum += __shfl_xor_sync(0xffffffffu, rsum, 1);
                rsum += __shfl_xor_sync(0xffffffffu, rsum, 2);
                if (tig == 0) {
                    const int px = (colBase >> 6) + warp_n;   // 0..31
                    g_rsum[((size_t)z * TLEN + m) * 32 + px] = rsum;
                }
            } else if (MODE == 2) {
                const float inv = __ldg(&g_rinv[(size_t)z * TLEN + m]);
                const int b = z >> 3, hh = z & 7;
                const size_t base = ((size_t)(b * TLEN + m)) * (NHEAD * FDIM) + hh * FDIM + gn;
                #pragma unroll
                for (int j = 0; j < 8; ++j)
                    *(uint32_t*)(g_a + base + 8 * j) =
                        pack_f16(acc[i][j][2 * h] * inv, acc[i][j][2 * h + 1] * inv);
            } else {
                float* p = g_p3 + (size_t)z * (8192 * FDIM) + (size_t)m * FDIM + gn;
                #pragma unroll
                for (int j = 0; j < 8; ++j)
                    *(float2*)(p + 8 * j) = make_float2(acc[i][j][2 * h], acc[i][j][2 * h + 1]);
            }
        }
    }
}

// ---------------- row inverse-sum: 65536 rows x 32 partials ----------------
__global__ void __launch_bounds__(256) rinv_kernel()
{
    const int r = blockIdx.x * 256 + threadIdx.x;
    const float4* p = (const float4*)(g_rsum + (size_t)r * 32);
    float s = 0.f;
    #pragma unroll
    for (int i = 0; i < 8; ++i) {
        const float4 v = p[i];
        s += (v.x + v.y) + (v.z + v.w);
    }
    g_rinv[r] = 1.0f / s;
}

// ---------------- split-K combine: out = p3[0] + p3[1] + bias ----------------
__global__ void __launch_bounds__(256) combine_kernel(const float* __restrict__ bias,
                                                      float* __restrict__ out)
{
    const size_t i = ((size_t)blockIdx.x * 256 + threadIdx.x) * 4;
    const int col = (int)(i & (FDIM - 1));
    const float4 a = *(const float4*)(g_p3 + i);
    const float4 b = *(const float4*)(g_p3 + (size_t)8192 * FDIM + i);
    const float4 bv = *(const float4*)(bias + col);
    float4 o;
    o.x = a.x + b.x + bv.x;
    o.y = a.y + b.y + bv.y;
    o.z = a.z + b.z + bv.z;
    o.w = a.w + b.w + bv.w;
    *(float4*)(out + i) = o;
}

// ---------------- input split: x -> bf16 h/l + fp16 ----------------
__global__ void __launch_bounds__(256) split_x_kernel(const float* __restrict__ x)
{
    const size_t i = ((size_t)blockIdx.x * 256 + threadIdx.x) * 4;
    const float4 v = *(const float4*)(x + i);
    uint32_t h0, l0, h1, l1;
    split_pair(make_float2(v.x, v.y), h0, l0);
    split_pair(make_float2(v.z, v.w), h1, l1);
    *(uint32_t*)(g_xh + i)     = h0;
    *(uint32_t*)(g_xh + i + 2) = h1;
    *(uint32_t*)(g_xl + i)     = l0;
    *(uint32_t*)(g_xl + i + 2) = l1;
    *(uint32_t*)(g_xf + i)     = pack_f16(v.x, v.y);
    *(uint32_t*)(g_xf + i + 2) = pack_f16(v.z, v.w);
}

// ---------------- W_qkv transpose + column permutation + split (bf16 h+l, fp16) ----------------
__global__ void __launch_bounds__(256) wqkv_prep_kernel(const float* __restrict__ in)
{
    __shared__ float t[32][33];
    const int c0 = blockIdx.x * 32;
    const int r0 = blockIdx.y * 32;
    const int tx = threadIdx.x, ty = threadIdx.y;
    #pragma unroll
    for (int i = 0; i < 32; i += 8)
        t[ty + i][tx] = in[(size_t)(r0 + ty + i) * (NHEAD * FDIM * 3) + c0 + tx];
    __syncthreads();
    #pragma unroll
    for (int i = 0; i < 32; i += 8) {
        const int corig = c0 + ty + i;
        const int hh  = corig / (FDIM * 3);
        const int rem = corig - hh * (FDIM * 3);
        const int f   = rem / 3;
        const int prt = rem - f * 3;
        const int cnew = prt * (NHEAD * FDIM) + hh * FDIM + f;
        const float val = t[tx][ty + i];
        bf16 vh, vl;
        split1(val, vh, vl);
        g_Wqh[(size_t)cnew * FDIM + r0 + tx] = vh;
        g_Wql[(size_t)cnew * FDIM + r0 + tx] = vl;
        g_Wqf[(size_t)cnew * FDIM + r0 + tx] = __float2half(val);
    }
}

// ---------------- W_proj transpose -> fp16: [2048][256] -> [256][2048] ----------------
__global__ void __launch_bounds__(256) wproj_prep_kernel(const float* __restrict__ in)
{
    __shared__ float t[32][33];
    const int c0 = blockIdx.x * 32;
    const int r0 = blockIdx.y * 32;
    const int tx = threadIdx.x, ty = threadIdx.y;
    #pragma unroll
    for (int i = 0; i < 32; i += 8)
        t[ty + i][tx] = in[(size_t)(r0 + ty + i) * FDIM + c0 + tx];
    __syncthreads();
    #pragma unroll
    for (int i = 0; i < 32; i += 8)
        g_Wp[(size_t)(c0 + ty + i) * (NHEAD * FDIM) + r0 + tx] = __float2half(t[tx][ty + i]);
}

// ---------------- V transpose: [bh][t][f] -> [bh][f][t] (fp16) ----------------
__global__ void __launch_bounds__(256) vtrans_kernel()
{
    __shared__ fp16 th[32][33];
    const int bh = blockIdx.z;
    const int f0 = blockIdx.x * 32;
    const int t0 = blockIdx.y * 32;
    const int tx = threadIdx.x, ty = threadIdx.y;
    const size_t inb = ((size_t)bh * TLEN + t0) * FDIM + f0;
    #pragma unroll
    for (int i = 0; i < 32; i += 8)
        th[ty + i][tx] = g_Vn[inb + (size_t)(ty + i) * FDIM + tx];
    __syncthreads();
    const size_t outb = ((size_t)bh * FDIM + f0) * TLEN + t0;
    #pragma unroll
    for (int i = 0; i < 32; i += 8)
        g_Vt[outb + (size_t)(ty + i) * TLEN + tx] = th[tx][ty + i];
}

// ---------------- launch ----------------
extern "C" void kernel_launch(void* const* d_in, const int* in_sizes, int n_in,
                              void* d_out, int out_size)
{
    const float* x     = (const float*)d_in[0];
    const float* Wqkv  = (const float*)d_in[1];
    const float* bqkv  = (const float*)d_in[2];
    const float* Wproj = (const float*)d_in[3];
    const float* bproj = (const float*)d_in[4];
    float* out = (float*)d_out;

    cudaFuncSetAttribute(mma_gemm<0,1>, cudaFuncAttributeMaxDynamicSharedMemorySize, SMEM_HI);
    cudaFuncSetAttribute(mma_gemm<0,3>, cudaFuncAttributeMaxDynamicSharedMemorySize, SMEM_FULL);
    cudaFuncSetAttribute(mma_gemm<1,1>, cudaFuncAttributeMaxDynamicSharedMemorySize, SMEM_HI);
    cudaFuncSetAttribute(mma_gemm<2,1>, cudaFuncAttributeMaxDynamicSharedMemorySize, SMEM_HI);
    cudaFuncSetAttribute(mma_gemm<3,1>, cudaFuncAttributeMaxDynamicSharedMemorySize, SMEM_HI);

    // prep: split x; transpose(+permute)+split weights
    split_x_kernel<<<(NBATCH * TLEN * FDIM) / 1024, 256>>>(x);
    wqkv_prep_kernel<<<dim3(6144 / 32, 256 / 32), dim3(32, 8)>>>(Wqkv);
    wproj_prep_kernel<<<dim3(256 / 32, 2048 / 32), dim3(32, 8)>>>(Wproj);

    // 1a) QK part of QKV GEMM (fp16 1-term, permuted cols 0..4095) -> Q/K fp16
    mma_gemm<0,1><<<dim3(4096 / BN, 8192 / BM, 1), 256, SMEM_HI>>>(bqkv, nullptr, 0);
    // 1b) V part (bf16 3-term, cols 4096..6143) -> Vn fp16
    mma_gemm<0,3><<<dim3(2048 / BN, 8192 / BM, 1), 256, SMEM_FULL>>>(bqkv, nullptr, 4096);
    // 1c) V transpose -> Vt
    vtrans_kernel<<<dim3(FDIM / 32, TLEN / 32, NBH), dim3(32, 8)>>>();
    // 2) P = exp(Q K^T) (fused softmax numerator) -> fp16 + row partial sums
    mma_gemm<1,1><<<dim3(TLEN / BN, TLEN / BM, NBH), 256, SMEM_HI>>>(nullptr, nullptr, 0);
    // 2b) 1/rowsum
    rinv_kernel<<<(NBH * TLEN) / 256, 256>>>();
    // 3) attn = (P V) * rinv (batched, NT against Vt) -> fp16
    mma_gemm<2,1><<<dim3(FDIM / BN, TLEN / BM, NBH), 256, SMEM_HI>>>(nullptr, nullptr, 0);
    // 4) proj split-K x2 -> fp32 partials
    mma_gemm<3,1><<<dim3(FDIM / BN, 8192 / BM, 2), 256, SMEM_HI>>>(nullptr, nullptr, 0);
    // 4b) combine + bias -> fp32 out
    combine_kernel<<<(8192 * FDIM) / 1024, 256>>>(bproj, out);
}

// round 16
// speedup vs baseline: 3.3058x; 1.1118x over previous
#include <cuda_runtime.h>
#include <cuda_bf16.h>
#include <cuda_fp16.h>
#include <cstdint>
#include <math.h>

#define TLEN   2048
#define FDIM   256
#define NHEAD  8
#define NBATCH 4
#define NBH    32

typedef __nv_bfloat16 bf16;
typedef __half fp16;

// ---------------- scratch (__device__ globals; no allocation allowed) ----------------
__device__ __align__(16) bf16 g_xh [(size_t)NBATCH * TLEN * FDIM];        // x bf16 hi (V path)
__device__ __align__(16) bf16 g_xl [(size_t)NBATCH * TLEN * FDIM];        // x bf16 lo residual
__device__ __align__(16) fp16 g_xf [(size_t)NBATCH * TLEN * FDIM];        // x fp16 (QK path)
__device__ __align__(16) bf16 g_Wqh[(size_t)(NHEAD * FDIM * 3) * FDIM];   // permuted WqkvT hi [6144][256]
__device__ __align__(16) bf16 g_Wql[(size_t)(NHEAD * FDIM * 3) * FDIM];
__device__ __align__(16) fp16 g_Wqf[(size_t)(NHEAD * FDIM * 3) * FDIM];   // permuted WqkvT fp16
__device__ __align__(16) fp16 g_Q  [(size_t)NBH * TLEN * FDIM];           // [bh][t][f] fp16
__device__ __align__(16) fp16 g_K  [(size_t)NBH * TLEN * FDIM];           // fp16
__device__ __align__(16) fp16 g_Vn [(size_t)NBH * TLEN * FDIM];           // V natural fp16
__device__ __align__(16) fp16 g_Vt [(size_t)NBH * FDIM * TLEN];           // V transposed fp16
__device__ __align__(16) fp16 g_P  [(size_t)NBH * TLEN * TLEN];           // e=exp(s) fp16
__device__ __align__(16) fp16 g_a  [(size_t)NBATCH * TLEN * NHEAD * FDIM];// attn fp16 [b][t][h*f]
__device__ __align__(16) fp16 g_Wp [(size_t)FDIM * (NHEAD * FDIM)];       // WprojT fp16 [256][2048]
__device__ __align__(16) float g_rsum[(size_t)NBH * TLEN * 32];           // per-row partial sums
__device__ __align__(16) float g_rinv[(size_t)NBH * TLEN];                // 1/rowsum
__device__ __align__(16) float g_p3  [(size_t)2 * NBATCH * TLEN * FDIM];  // mode-3 split-K partials

// ---------------- helpers ----------------
__device__ __forceinline__ uint32_t smem_u32(const void* p) {
    uint32_t a;
    asm("{ .reg .u64 t; cvta.to.shared.u64 t, %1; cvt.u32.u64 %0, t; }" : "=r"(a) : "l"(p));
    return a;
}
__device__ __forceinline__ void cp_async16(uint32_t dst, const void* src) {
    asm volatile("cp.async.cg.shared.global [%0], [%1], 16;" :: "r"(dst), "l"(src) : "memory");
}
__device__ __forceinline__ void cp_commit() {
    asm volatile("cp.async.commit_group;" ::: "memory");
}
template<int N> __device__ __forceinline__ void cp_wait() {
    asm volatile("cp.async.wait_group %0;" :: "n"(N) : "memory");
}
__device__ __forceinline__ void mma_bf16(float* c, const uint32_t* a, const uint32_t* b) {
    asm volatile(
        "mma.sync.aligned.m16n8k16.row.col.f32.bf16.bf16.f32 "
        "{%0,%1,%2,%3}, {%4,%5,%6,%7}, {%8,%9}, {%0,%1,%2,%3};"
        : "+f"(c[0]), "+f"(c[1]), "+f"(c[2]), "+f"(c[3])
        : "r"(a[0]), "r"(a[1]), "r"(a[2]), "r"(a[3]), "r"(b[0]), "r"(b[1]));
}
__device__ __forceinline__ void mma_f16(float* c, const uint32_t* a, const uint32_t* b) {
    asm volatile(
        "mma.sync.aligned.m16n8k16.row.col.f32.f16.f16.f32 "
        "{%0,%1,%2,%3}, {%4,%5,%6,%7}, {%8,%9}, {%0,%1,%2,%3};"
        : "+f"(c[0]), "+f"(c[1]), "+f"(c[2]), "+f"(c[3])
        : "r"(a[0]), "r"(a[1]), "r"(a[2]), "r"(a[3]), "r"(b[0]), "r"(b[1]));
}
__device__ __forceinline__ void ldmx4(uint32_t& r0, uint32_t& r1, uint32_t& r2, uint32_t& r3,
                                      uint32_t addr) {
    asm volatile("ldmatrix.sync.aligned.m8n8.x4.shared.b16 {%0,%1,%2,%3}, [%4];"
                 : "=r"(r0), "=r"(r1), "=r"(r2), "=r"(r3) : "r"(addr));
}
// pack two fp32 -> fp16x2 word (.x in low half)
__device__ __forceinline__ uint32_t pack_f16(float lo, float hi) {
    uint32_t h;
    asm("cvt.rn.f16x2.f32 %0, %1, %2;" : "=r"(h) : "f"(hi), "f"(lo));
    return h;
}
// split fp32 pair -> packed bf16x2 hi + bf16x2 lo residual (.x in low half)
__device__ __forceinline__ void split_pair(float2 f, uint32_t& hi, uint32_t& lo) {
    uint32_t h;
    asm("cvt.rn.bf16x2.f32 %0, %1, %2;" : "=r"(h) : "f"(f.y), "f"(f.x));
    const float h0 = __uint_as_float(h << 16);
    const float h1 = __uint_as_float(h & 0xffff0000u);
    asm("cvt.rn.bf16x2.f32 %0, %1, %2;" : "=r"(lo) : "f"(f.y - h1), "f"(f.x - h0));
    hi = h;
}
__device__ __forceinline__ void split1(float v, bf16& h, bf16& l) {
    h = __float2bfloat16(v);
    l = __float2bfloat16(v - __bfloat162float(h));
}

// ---------------- GEMM config ----------------
// NTERMS==1 (fp16): BK=64, tiles 128 rows x 128B, swizzle c^=(row&7)
// NTERMS==3 (bf16 split): BK=32, tiles 128 rows x 64B, swizzle c^=((row>>1)&3)
constexpr int BM = 128, BN = 128;
constexpr int STAGES = 3;
constexpr int SMEM_NEED = 98432;   // both variants: 3 stages x (2x16KB | 4x8KB) + 128

// MODE 0: C = x @ WqkvT'^T (K=256). NTERMS=1: QK cols (fp16); NTERMS=3: V cols (bf16 split)
// MODE 1: C[2048,2048] = Q @ K^T       (K=256, fp16) -> P=exp(s) fp16 + row partial sums
// MODE 2: C[2048, 256] = P @ Vt^T      (K=2048, fp16) -> *rinv[m] -> g_a fp16
// MODE 3: C[8192, 256] = attn @ Wp^T   (fp16, split-K x2) -> g_p3 fp32 partials
template<int MODE, int NTERMS>
__global__ void __launch_bounds__(256, 2)
mma_gemm(const float* __restrict__ bias, float* __restrict__ Cgp, int colOfs)
{
    constexpr int TILES = (NTERMS == 1) ? 2 : 4;
    constexpr int BKT   = (NTERMS == 1) ? 64 : 32;      // K elems per tile
    constexpr int ROWB  = BKT * 2;                      // bytes per row (128 | 64)
    constexpr int ROWC  = ROWB / 16;                    // 16B chunks per row (8 | 4)
    constexpr int KSN   = BKT / 16;                     // m16n8k16 steps per tile (4 | 2)
    constexpr int TILE_BYTES  = BM * ROWB;              // 16384 | 8192
    constexpr int STAGE_BYTES = TILES * TILE_BYTES;     // 32768 both
    constexpr int SLOT_BH = (NTERMS == 1) ? 1 : 2;
    constexpr int K  = (MODE == 0 || MODE == 1) ? 256 : 2048;    // row stride (elements)
    constexpr int KT = ((MODE == 3) ? 1024 : K) / BKT;           // k-tiles per CTA

    extern __shared__ uint32_t smem_w[];
    const uint32_t sbase = (smem_u32(smem_w) + 127u) & ~127u;

    const int tid = threadIdx.x;
    const int wid = tid >> 5, lid = tid & 31;
    const int z = blockIdx.z;
    const int rowBase = blockIdx.y * BM;
    const int colBase = colOfs + blockIdx.x * BN;

    const uint16_t *Ah, *Al = nullptr, *Bh, *Bl = nullptr;
    if (MODE == 0) {
        if (NTERMS == 1) {
            Ah = (const uint16_t*)g_xf;  Bh = (const uint16_t*)g_Wqf;
        } else {
            Ah = (const uint16_t*)g_xh;  Al = (const uint16_t*)g_xl;
            Bh = (const uint16_t*)g_Wqh; Bl = (const uint16_t*)g_Wql;
        }
    } else if (MODE == 1) {
        const size_t o = (size_t)z * TLEN * FDIM;
        Ah = (const uint16_t*)g_Q + o; Bh = (const uint16_t*)g_K + o;
    } else if (MODE == 2) {
        Ah = (const uint16_t*)g_P  + (size_t)z * TLEN * TLEN;
        Bh = (const uint16_t*)g_Vt + (size_t)z * FDIM * TLEN;
    } else {
        Ah = (const uint16_t*)g_a;  Bh = (const uint16_t*)g_Wp;
    }
    Ah += (size_t)rowBase * K;
    Bh += (size_t)colBase * K;
    if (NTERMS == 3) { Al += (size_t)rowBase * K; Bl += (size_t)colBase * K; }
    if (MODE == 3) {   // K-split: second half starts at k=1024
        const int ko = z * 1024;
        Ah += ko; Bh += ko;
    }

    // swizzle: chunk' = chunk ^ swz(row)
    auto swz = [](int row) -> int {
        return (NTERMS == 1) ? (row & 7) : ((row >> 1) & 3);
    };

    // loader: per tile TILE_BYTES/16 chunks; 256 threads x (ROWC/2) iterations
    auto load_tile = [&](int kt, int s) {
        const uint32_t base = sbase + s * STAGE_BYTES;
        const int kofs = kt * BKT;
        #pragma unroll
        for (int i = 0; i < ROWC / 2; ++i) {
            const int f   = tid + 256 * i;
            const int row = f / ROWC;
            const int c   = f % ROWC;
            const uint32_t so = (uint32_t)(row * ROWB) + (uint32_t)((c ^ swz(row)) << 4);
            const size_t go = (size_t)row * K + kofs + c * 8;
            cp_async16(base + so,                         Ah + go);
            cp_async16(base + SLOT_BH * TILE_BYTES + so,  Bh + go);
            if (NTERMS == 3) {
                cp_async16(base + 1 * TILE_BYTES + so,    Al + go);
                cp_async16(base + 3 * TILE_BYTES + so,    Bl + go);
            }
        }
        cp_commit();
    };

    const int warp_m = wid & 3;   // 4 warps x 32 rows
    const int warp_n = wid >> 2;  // 2 warps x 64 cols
    const int gid = lid >> 2;     // 0..7
    const int tig = lid & 3;      // 0..3

    // ldmatrix lane addresses (swizzled); k-step ks applies addr ^ (ks*32)
    const int R_A = 32 * warp_m + (lid & 7) + ((lid >> 3) & 1) * 8;
    const int c_A = (lid >> 4) & 1;
    const uint32_t aA0 = sbase + (uint32_t)(R_A * ROWB) +
                         (uint32_t)((c_A ^ swz(R_A)) << 4);
    const int R_B = 64 * warp_n + (lid & 7) + ((lid >> 4) & 1) * 8;
    const int c_B = (lid >> 3) & 1;
    const uint32_t aB0 = sbase + SLOT_BH * TILE_BYTES + (uint32_t)(R_B * ROWB) +
                         (uint32_t)((c_B ^ swz(R_B)) << 4);

    float acc[2][8][4];
    #pragma unroll
    for (int i = 0; i < 2; ++i)
        #pragma unroll
        for (int j = 0; j < 8; ++j)
            #pragma unroll
            for (int c = 0; c < 4; ++c) acc[i][j][c] = 0.f;

    load_tile(0, 0);
    if (KT > 1) load_tile(1, 1);

    int s = 0;
    #pragma unroll 1
    for (int kt = 0; kt < KT; ++kt) {
        const int rem = KT - 1 - kt;
        if (rem >= 2) {
            int sp2 = s - 1; if (sp2 < 0) sp2 = 2;     // (s+2)%3
            load_tile(kt + 2, sp2);
            cp_wait<2>();
        } else if (rem == 1) {
            cp_wait<1>();
        } else {
            cp_wait<0>();
        }
        __syncthreads();

        const uint32_t aAh = aA0 + s * STAGE_BYTES;
        const uint32_t aBh = aB0 + s * STAGE_BYTES;

        #pragma unroll
        for (int ks = 0; ks < KSN; ++ks) {           // m16n8k16 K-steps per tile
            const uint32_t kx = (uint32_t)(ks * 32);  // XOR-step within swizzled row

            uint32_t ah[2][4], al[2][4];
            #pragma unroll
            for (int i = 0; i < 2; ++i) {
                const uint32_t a0 = (aAh + (uint32_t)(i * 16 * ROWB)) ^ kx;
                ldmx4(ah[i][0], ah[i][1], ah[i][2], ah[i][3], a0);
                if (NTERMS == 3)
                    ldmx4(al[i][0], al[i][1], al[i][2], al[i][3], a0 + TILE_BYTES);
            }

            #pragma unroll
            for (int jh = 0; jh < 2; ++jh) {         // halves of 4 columns (reg pressure)
                uint32_t bh[4][2], bl[4][2];
                #pragma unroll
                for (int jp = 0; jp < 2; ++jp) {     // j-pairs: cols 8J..8J+15
                    const int J = jh * 4 + jp * 2;
                    const uint32_t b0 = (aBh + (uint32_t)(8 * J * ROWB)) ^ kx;
                    ldmx4(bh[2*jp][0], bh[2*jp][1], bh[2*jp+1][0], bh[2*jp+1][1], b0);
                    if (NTERMS == 3)
                        ldmx4(bl[2*jp][0], bl[2*jp][1], bl[2*jp+1][0], bl[2*jp+1][1],
                              b0 + TILE_BYTES);
                }
                #pragma unroll
                for (int i = 0; i < 2; ++i)
                    #pragma unroll
                    for (int j = 0; j < 4; ++j) {
                        float* c = acc[i][jh * 4 + j];
                        if (NTERMS == 3) {
                            mma_bf16(c, ah[i], bh[j]);       // hi*hi
                            mma_bf16(c, ah[i], bl[j]);       // hi*lo
                            mma_bf16(c, al[i], bh[j]);       // lo*hi
                        } else {
                            mma_f16(c, ah[i], bh[j]);        // fp16 single term
                        }
                    }
            }
        }
        __syncthreads();   // all warps done with stage s before loads reuse it
        s = (s == 2) ? 0 : s + 1;
    }

    // ---------------- epilogue ----------------
    const int gm = rowBase + 32 * warp_m;
    const int gn = colBase + 64 * warp_n + 2 * tig;

    if (MODE == 0) {
        // permuted columns: jj = part*2048 + h*256 + f ; part & head uniform per CTA
        const int part  = colBase >> 11;
        const int hh    = (colBase >> 8) & 7;
        const int fwarp = (colBase & 255) + 64 * warp_n + 2 * tig;
        const float scl = (part == 2) ? 1.0f : 0.0625f;

        #pragma unroll
        for (int i = 0; i < 2; ++i) {
            #pragma unroll
            for (int h = 0; h < 2; ++h) {
                const int m = gm + 16 * i + gid + 8 * h;
                const int b = m >> 11, t = m & (TLEN - 1);
                const size_t rowO = ((size_t)(b * NHEAD + hh) * TLEN + t) * FDIM;
                #pragma unroll
                for (int j = 0; j < 8; ++j) {
                    const int f0 = fwarp + 8 * j;
                    const int borig = hh * (FDIM * 3) + f0 * 3 + part;
                    const float v0 = (acc[i][j][2 * h]     + bias[borig])     * scl;
                    const float v1 = (acc[i][j][2 * h + 1] + bias[borig + 3]) * scl;
                    const uint32_t w = pack_f16(v0, v1);
                    if      (part == 0) *(uint32_t*)(g_Q  + rowO + f0) = w;
                    else if (part == 1) *(uint32_t*)(g_K  + rowO + f0) = w;
                    else                *(uint32_t*)(g_Vn + rowO + f0) = w;
                }
            }
        }
        return;
    }

    #pragma unroll
    for (int i = 0; i < 2; ++i) {
        #pragma unroll
        for (int h = 0; h < 2; ++h) {
            const int m = gm + 16 * i + gid + 8 * h;

            if (MODE == 1) {
                // e = exp(score); store fp16; deterministic row partial sums
                const size_t ro = (size_t)z * TLEN * TLEN + (size_t)m * TLEN + gn;
                uint32_t* ph = (uint32_t*)(g_P + ro);
                float rsum = 0.f;
                #pragma unroll
                for (int j = 0; j < 8; ++j) {
                    const float e0 = __expf(acc[i][j][2 * h]);
                    const float e1 = __expf(acc[i][j][2 * h + 1]);
                    rsum += e0 + e1;
                    ph[4 * j] = pack_f16(e0, e1);
                }
                rsum += __shfl_xor_sync(0xffffffffu, rsum, 1);
                rsum += __shfl_xor_sync(0xffffffffu, rsum, 2);
                if (tig == 0) {
                    const int px = (colBase >> 6) + warp_n;   // 0..31
                    g_rsum[((size_t)z * TLEN + m) * 32 + px] = rsum;
                }
            } else if (MODE == 2) {
                const float inv = __ldg(&g_rinv[(size_t)z * TLEN + m]);
                const int b = z >> 3, hh = z & 7;
                const size_t base = ((size_t)(b * TLEN + m)) * (NHEAD * FDIM) + hh * FDIM + gn;
                #pragma unroll
                for (int j = 0; j < 8; ++j)
                    *(uint32_t*)(g_a + base + 8 * j) =
                        pack_f16(acc[i][j][2 * h] * inv, acc[i][j][2 * h + 1] * inv);
            } else {
                float* p = g_p3 + (size_t)z * (8192 * FDIM) + (size_t)m * FDIM + gn;
                #pragma unroll
                for (int j = 0; j < 8; ++j)
                    *(float2*)(p + 8 * j) = make_float2(acc[i][j][2 * h], acc[i][j][2 * h + 1]);
            }
        }
    }
}

// ---------------- row inverse-sum: 65536 rows x 32 partials ----------------
__global__ void __launch_bounds__(256) rinv_kernel()
{
    const int r = blockIdx.x * 256 + threadIdx.x;
    const float4* p = (const float4*)(g_rsum + (size_t)r * 32);
    float s = 0.f;
    #pragma unroll
    for (int i = 0; i < 8; ++i) {
        const float4 v = p[i];
        s += (v.x + v.y) + (v.z + v.w);
    }
    g_rinv[r] = 1.0f / s;
}

// ---------------- split-K combine: out = p3[0] + p3[1] + bias ----------------
__global__ void __launch_bounds__(256) combine_kernel(const float* __restrict__ bias,
                                                      float* __restrict__ out)
{
    const size_t i = ((size_t)blockIdx.x * 256 + threadIdx.x) * 4;
    const int col = (int)(i & (FDIM - 1));
    const float4 a = *(const float4*)(g_p3 + i);
    const float4 b = *(const float4*)(g_p3 + (size_t)8192 * FDIM + i);
    const float4 bv = *(const float4*)(bias + col);
    float4 o;
    o.x = a.x + b.x + bv.x;
    o.y = a.y + b.y + bv.y;
    o.z = a.z + b.z + bv.z;
    o.w = a.w + b.w + bv.w;
    *(float4*)(out + i) = o;
}

// ---------------- input split: x -> bf16 h/l + fp16 ----------------
__global__ void __launch_bounds__(256) split_x_kernel(const float* __restrict__ x)
{
    const size_t i = ((size_t)blockIdx.x * 256 + threadIdx.x) * 4;
    const float4 v = *(const float4*)(x + i);
    uint32_t h0, l0, h1, l1;
    split_pair(make_float2(v.x, v.y), h0, l0);
    split_pair(make_float2(v.z, v.w), h1, l1);
    *(uint32_t*)(g_xh + i)     = h0;
    *(uint32_t*)(g_xh + i + 2) = h1;
    *(uint32_t*)(g_xl + i)     = l0;
    *(uint32_t*)(g_xl + i + 2) = l1;
    *(uint32_t*)(g_xf + i)     = pack_f16(v.x, v.y);
    *(uint32_t*)(g_xf + i + 2) = pack_f16(v.z, v.w);
}

// ---------------- W_qkv transpose + column permutation + split (bf16 h+l, fp16) ----------------
__global__ void __launch_bounds__(256) wqkv_prep_kernel(const float* __restrict__ in)
{
    __shared__ float t[32][33];
    const int c0 = blockIdx.x * 32;
    const int r0 = blockIdx.y * 32;
    const int tx = threadIdx.x, ty = threadIdx.y;
    #pragma unroll
    for (int i = 0; i < 32; i += 8)
        t[ty + i][tx] = in[(size_t)(r0 + ty + i) * (NHEAD * FDIM * 3) + c0 + tx];
    __syncthreads();
    #pragma unroll
    for (int i = 0; i < 32; i += 8) {
        const int corig = c0 + ty + i;
        const int hh  = corig / (FDIM * 3);
        const int rem = corig - hh * (FDIM * 3);
        const int f   = rem / 3;
        const int prt = rem - f * 3;
        const int cnew = prt * (NHEAD * FDIM) + hh * FDIM + f;
        const float val = t[tx][ty + i];
        bf16 vh, vl;
        split1(val, vh, vl);
        g_Wqh[(size_t)cnew * FDIM + r0 + tx] = vh;
        g_Wql[(size_t)cnew * FDIM + r0 + tx] = vl;
        g_Wqf[(size_t)cnew * FDIM + r0 + tx] = __float2half(val);
    }
}

// ---------------- W_proj transpose -> fp16: [2048][256] -> [256][2048] ----------------
__global__ void __launch_bounds__(256) wproj_prep_kernel(const float* __restrict__ in)
{
    __shared__ float t[32][33];
    const int c0 = blockIdx.x * 32;
    const int r0 = blockIdx.y * 32;
    const int tx = threadIdx.x, ty = threadIdx.y;
    #pragma unroll
    for (int i = 0; i < 32; i += 8)
        t[ty + i][tx] = in[(size_t)(r0 + ty + i) * FDIM + c0 + tx];
    __syncthreads();
    #pragma unroll
    for (int i = 0; i < 32; i += 8)
        g_Wp[(size_t)(c0 + ty + i) * (NHEAD * FDIM) + r0 + tx] = __float2half(t[tx][ty + i]);
}

// ---------------- V transpose: [bh][t][f] -> [bh][f][t] (fp16) ----------------
__global__ void __launch_bounds__(256) vtrans_kernel()
{
    __shared__ fp16 th[32][33];
    const int bh = blockIdx.z;
    const int f0 = blockIdx.x * 32;
    const int t0 = blockIdx.y * 32;
    const int tx = threadIdx.x, ty = threadIdx.y;
    const size_t inb = ((size_t)bh * TLEN + t0) * FDIM + f0;
    #pragma unroll
    for (int i = 0; i < 32; i += 8)
        th[ty + i][tx] = g_Vn[inb + (size_t)(ty + i) * FDIM + tx];
    __syncthreads();
    const size_t outb = ((size_t)bh * FDIM + f0) * TLEN + t0;
    #pragma unroll
    for (int i = 0; i < 32; i += 8)
        g_Vt[outb + (size_t)(ty + i) * TLEN + tx] = th[tx][ty + i];
}

// ---------------- launch ----------------
extern "C" void kernel_launch(void* const* d_in, const int* in_sizes, int n_in,
                              void* d_out, int out_size)
{
    const float* x     = (const float*)d_in[0];
    const float* Wqkv  = (const float*)d_in[1];
    const float* bqkv  = (const float*)d_in[2];
    const float* Wproj = (const float*)d_in[3];
    const float* bproj = (const float*)d_in[4];
    float* out = (float*)d_out;

    cudaFuncSetAttribute(mma_gemm<0,1>, cudaFuncAttributeMaxDynamicSharedMemorySize, SMEM_NEED);
    cudaFuncSetAttribute(mma_gemm<0,3>, cudaFuncAttributeMaxDynamicSharedMemorySize, SMEM_NEED);
    cudaFuncSetAttribute(mma_gemm<1,1>, cudaFuncAttributeMaxDynamicSharedMemorySize, SMEM_NEED);
    cudaFuncSetAttribute(mma_gemm<2,1>, cudaFuncAttributeMaxDynamicSharedMemorySize, SMEM_NEED);
    cudaFuncSetAttribute(mma_gemm<3,1>, cudaFuncAttributeMaxDynamicSharedMemorySize, SMEM_NEED);

    // prep: split x; transpose(+permute)+split weights
    split_x_kernel<<<(NBATCH * TLEN * FDIM) / 1024, 256>>>(x);
    wqkv_prep_kernel<<<dim3(6144 / 32, 256 / 32), dim3(32, 8)>>>(Wqkv);
    wproj_prep_kernel<<<dim3(256 / 32, 2048 / 32), dim3(32, 8)>>>(Wproj);

    // 1a) QK part of QKV GEMM (fp16 1-term, permuted cols 0..4095) -> Q/K fp16
    mma_gemm<0,1><<<dim3(4096 / BN, 8192 / BM, 1), 256, SMEM_NEED>>>(bqkv, nullptr, 0);
    // 1b) V part (bf16 3-term, cols 4096..6143) -> Vn fp16
    mma_gemm<0,3><<<dim3(2048 / BN, 8192 / BM, 1), 256, SMEM_NEED>>>(bqkv, nullptr, 4096);
    // 1c) V transpose -> Vt
    vtrans_kernel<<<dim3(FDIM / 32, TLEN / 32, NBH), dim3(32, 8)>>>();
    // 2) P = exp(Q K^T) (fused softmax numerator) -> fp16 + row partial sums
    mma_gemm<1,1><<<dim3(TLEN / BN, TLEN / BM, NBH), 256, SMEM_NEED>>>(nullptr, nullptr, 0);
    // 2b) 1/rowsum
    rinv_kernel<<<(NBH * TLEN) / 256, 256>>>();
    // 3) attn = (P V) * rinv (batched, NT against Vt) -> fp16
    mma_gemm<2,1><<<dim3(FDIM / BN, TLEN / BM, NBH), 256, SMEM_NEED>>>(nullptr, nullptr, 0);
    // 4) proj split-K x2 -> fp32 partials
    mma_gemm<3,1><<<dim3(FDIM / BN, 8192 / BM, 2), 256, SMEM_NEED>>>(nullptr, nullptr, 0);
    // 4b) combine + bias -> fp32 out
    combine_kernel<<<(8192 * FDIM) / 1024, 256>>>(bproj, out);
}

// round 17
// speedup vs baseline: 3.4107x; 1.0317x over previous
#include <cuda_runtime.h>
#include <cuda_bf16.h>
#include <cuda_fp16.h>
#include <cstdint>
#include <math.h>

#define TLEN   2048
#define FDIM   256
#define NHEAD  8
#define NBATCH 4
#define NBH    32

typedef __nv_bfloat16 bf16;
typedef __half fp16;

// ---------------- scratch (__device__ globals; no allocation allowed) ----------------
__device__ __align__(16) bf16 g_xh [(size_t)NBATCH * TLEN * FDIM];        // x bf16 hi (V path)
__device__ __align__(16) bf16 g_xl [(size_t)NBATCH * TLEN * FDIM];        // x bf16 lo residual
__device__ __align__(16) fp16 g_xf [(size_t)NBATCH * TLEN * FDIM];        // x fp16 (QK path)
__device__ __align__(16) bf16 g_Wqh[(size_t)(NHEAD * FDIM * 3) * FDIM];   // permuted WqkvT hi [6144][256]
__device__ __align__(16) bf16 g_Wql[(size_t)(NHEAD * FDIM * 3) * FDIM];
__device__ __align__(16) fp16 g_Wqf[(size_t)(NHEAD * FDIM * 3) * FDIM];   // permuted WqkvT fp16
__device__ __align__(16) fp16 g_Q  [(size_t)NBH * TLEN * FDIM];           // [bh][t][f] fp16
__device__ __align__(16) fp16 g_K  [(size_t)NBH * TLEN * FDIM];           // fp16
__device__ __align__(16) fp16 g_Vn [(size_t)NBH * TLEN * FDIM];           // V natural fp16
__device__ __align__(16) fp16 g_Vt [(size_t)NBH * FDIM * TLEN];           // V transposed fp16
__device__ __align__(16) fp16 g_P  [(size_t)NBH * TLEN * TLEN];           // e=exp(s) fp16
__device__ __align__(16) fp16 g_a  [(size_t)NBATCH * TLEN * NHEAD * FDIM];// attn fp16 [b][t][h*f]
__device__ __align__(16) fp16 g_Wp [(size_t)FDIM * (NHEAD * FDIM)];       // WprojT fp16 [256][2048]
__device__ __align__(16) float g_rsum[(size_t)NBH * TLEN * 32];           // per-row partial sums
__device__ __align__(16) float g_rinv[(size_t)NBH * TLEN];                // 1/rowsum
__device__ __align__(16) float g_p3  [(size_t)2 * NBATCH * TLEN * FDIM];  // mode-3 split-K partials

// ---------------- helpers ----------------
__device__ __forceinline__ uint32_t smem_u32(const void* p) {
    uint32_t a;
    asm("{ .reg .u64 t; cvta.to.shared.u64 t, %1; cvt.u32.u64 %0, t; }" : "=r"(a) : "l"(p));
    return a;
}
__device__ __forceinline__ void cp_async16(uint32_t dst, const void* src) {
    asm volatile("cp.async.cg.shared.global [%0], [%1], 16;" :: "r"(dst), "l"(src) : "memory");
}
__device__ __forceinline__ void cp_commit() {
    asm volatile("cp.async.commit_group;" ::: "memory");
}
template<int N> __device__ __forceinline__ void cp_wait() {
    asm volatile("cp.async.wait_group %0;" :: "n"(N) : "memory");
}
__device__ __forceinline__ void mma_bf16(float* c, const uint32_t* a, const uint32_t* b) {
    asm volatile(
        "mma.sync.aligned.m16n8k16.row.col.f32.bf16.bf16.f32 "
        "{%0,%1,%2,%3}, {%4,%5,%6,%7}, {%8,%9}, {%0,%1,%2,%3};"
        : "+f"(c[0]), "+f"(c[1]), "+f"(c[2]), "+f"(c[3])
        : "r"(a[0]), "r"(a[1]), "r"(a[2]), "r"(a[3]), "r"(b[0]), "r"(b[1]));
}
__device__ __forceinline__ void mma_f16(float* c, const uint32_t* a, const uint32_t* b) {
    asm volatile(
        "mma.sync.aligned.m16n8k16.row.col.f32.f16.f16.f32 "
        "{%0,%1,%2,%3}, {%4,%5,%6,%7}, {%8,%9}, {%0,%1,%2,%3};"
        : "+f"(c[0]), "+f"(c[1]), "+f"(c[2]), "+f"(c[3])
        : "r"(a[0]), "r"(a[1]), "r"(a[2]), "r"(a[3]), "r"(b[0]), "r"(b[1]));
}
__device__ __forceinline__ void ldmx4(uint32_t& r0, uint32_t& r1, uint32_t& r2, uint32_t& r3,
                                      uint32_t addr) {
    asm volatile("ldmatrix.sync.aligned.m8n8.x4.shared.b16 {%0,%1,%2,%3}, [%4];"
                 : "=r"(r0), "=r"(r1), "=r"(r2), "=r"(r3) : "r"(addr));
}
// pack two fp32 -> fp16x2 word (.x in low half)
__device__ __forceinline__ uint32_t pack_f16(float lo, float hi) {
    uint32_t h;
    asm("cvt.rn.f16x2.f32 %0, %1, %2;" : "=r"(h) : "f"(hi), "f"(lo));
    return h;
}
// split fp32 pair -> packed bf16x2 hi + bf16x2 lo residual (.x in low half)
__device__ __forceinline__ void split_pair(float2 f, uint32_t& hi, uint32_t& lo) {
    uint32_t h;
    asm("cvt.rn.bf16x2.f32 %0, %1, %2;" : "=r"(h) : "f"(f.y), "f"(f.x));
    const float h0 = __uint_as_float(h << 16);
    const float h1 = __uint_as_float(h & 0xffff0000u);
    asm("cvt.rn.bf16x2.f32 %0, %1, %2;" : "=r"(lo) : "f"(f.y - h1), "f"(f.x - h0));
    hi = h;
}
__device__ __forceinline__ void split1(float v, bf16& h, bf16& l) {
    h = __float2bfloat16(v);
    l = __float2bfloat16(v - __bfloat162float(h));
}

// ---------------- GEMM config ----------------
// NTERMS==1 (fp16): BK=64, tiles 128 rows x 128B, swizzle c^=(row&7)
// NTERMS==3 (bf16 split): BK=32, tiles 128 rows x 64B, swizzle c^=((row>>1)&3)
constexpr int BM = 128, BN = 128;
constexpr int STAGES = 3;
constexpr int SMEM_NEED = 98432;   // both variants: 3 stages x (2x16KB | 4x8KB) + 128

// MODE 0: C = x @ WqkvT'^T (K=256). NTERMS=1: QK cols (fp16); NTERMS=3: V cols (bf16 split)
// MODE 1: C[2048,2048] = Q @ K^T       (K=256, fp16) -> P=exp(s) fp16 + row partial sums
// MODE 2: C[2048, 256] = P @ Vt^T      (K=2048, fp16) -> *rinv[m] -> g_a fp16
// MODE 3: C[8192, 256] = attn @ Wp^T   (fp16, split-K x2) -> g_p3 fp32 partials
template<int MODE, int NTERMS>
__global__ void __launch_bounds__(256, 2)
mma_gemm(const float* __restrict__ bias, float* __restrict__ Cgp, int colOfs)
{
    constexpr int TILES = (NTERMS == 1) ? 2 : 4;
    constexpr int BKT   = (NTERMS == 1) ? 64 : 32;      // K elems per tile
    constexpr int ROWB  = BKT * 2;                      // bytes per row (128 | 64)
    constexpr int ROWC  = ROWB / 16;                    // 16B chunks per row (8 | 4)
    constexpr int KSN   = BKT / 16;                     // m16n8k16 steps per tile (4 | 2)
    constexpr int TILE_BYTES  = BM * ROWB;              // 16384 | 8192
    constexpr int STAGE_BYTES = TILES * TILE_BYTES;     // 32768 both
    constexpr int SLOT_BH = (NTERMS == 1) ? 1 : 2;
    constexpr int K  = (MODE == 0 || MODE == 1) ? 256 : 2048;    // row stride (elements)
    constexpr int KT = ((MODE == 3) ? 1024 : K) / BKT;           // k-tiles per CTA

    extern __shared__ uint32_t smem_w[];
    const uint32_t sbase = (smem_u32(smem_w) + 127u) & ~127u;

    const int tid = threadIdx.x;
    const int wid = tid >> 5, lid = tid & 31;
    const int z = blockIdx.z;
    const int rowBase = blockIdx.y * BM;
    const int colBase = colOfs + blockIdx.x * BN;

    const uint16_t *Ah, *Al = nullptr, *Bh, *Bl = nullptr;
    if (MODE == 0) {
        if (NTERMS == 1) {
            Ah = (const uint16_t*)g_xf;  Bh = (const uint16_t*)g_Wqf;
        } else {
            Ah = (const uint16_t*)g_xh;  Al = (const uint16_t*)g_xl;
            Bh = (const uint16_t*)g_Wqh; Bl = (const uint16_t*)g_Wql;
        }
    } else if (MODE == 1) {
        const size_t o = (size_t)z * TLEN * FDIM;
        Ah = (const uint16_t*)g_Q + o; Bh = (const uint16_t*)g_K + o;
    } else if (MODE == 2) {
        Ah = (const uint16_t*)g_P  + (size_t)z * TLEN * TLEN;
        Bh = (const uint16_t*)g_Vt + (size_t)z * FDIM * TLEN;
    } else {
        Ah = (const uint16_t*)g_a;  Bh = (const uint16_t*)g_Wp;
    }
    Ah += (size_t)rowBase * K;
    Bh += (size_t)colBase * K;
    if (NTERMS == 3) { Al += (size_t)rowBase * K; Bl += (size_t)colBase * K; }
    if (MODE == 3) {   // K-split: second half starts at k=1024
        const int ko = z * 1024;
        Ah += ko; Bh += ko;
    }

    // swizzle: chunk' = chunk ^ swz(row)
    auto swz = [](int row) -> int {
        return (NTERMS == 1) ? (row & 7) : ((row >> 1) & 3);
    };

    // loader: per tile TILE_BYTES/16 chunks; 256 threads x (ROWC/2) iterations
    auto load_tile = [&](int kt, int s) {
        const uint32_t base = sbase + s * STAGE_BYTES;
        const int kofs = kt * BKT;
        #pragma unroll
        for (int i = 0; i < ROWC / 2; ++i) {
            const int f   = tid + 256 * i;
            const int row = f / ROWC;
            const int c   = f % ROWC;
            const uint32_t so = (uint32_t)(row * ROWB) + (uint32_t)((c ^ swz(row)) << 4);
            const size_t go = (size_t)row * K + kofs + c * 8;
            cp_async16(base + so,                         Ah + go);
            cp_async16(base + SLOT_BH * TILE_BYTES + so,  Bh + go);
            if (NTERMS == 3) {
                cp_async16(base + 1 * TILE_BYTES + so,    Al + go);
                cp_async16(base + 3 * TILE_BYTES + so,    Bl + go);
            }
        }
        cp_commit();
    };

    const int warp_m = wid & 3;   // 4 warps x 32 rows
    const int warp_n = wid >> 2;  // 2 warps x 64 cols
    const int gid = lid >> 2;     // 0..7
    const int tig = lid & 3;      // 0..3

    // ldmatrix lane addresses (swizzled); k-step ks applies addr ^ (ks*32)
    const int R_A = 32 * warp_m + (lid & 7) + ((lid >> 3) & 1) * 8;
    const int c_A = (lid >> 4) & 1;
    const uint32_t aA0 = sbase + (uint32_t)(R_A * ROWB) +
                         (uint32_t)((c_A ^ swz(R_A)) << 4);
    const int R_B = 64 * warp_n + (lid & 7) + ((lid >> 4) & 1) * 8;
    const int c_B = (lid >> 3) & 1;
    const uint32_t aB0 = sbase + SLOT_BH * TILE_BYTES + (uint32_t)(R_B * ROWB) +
                         (uint32_t)((c_B ^ swz(R_B)) << 4);

    float acc[2][8][4];
    #pragma unroll
    for (int i = 0; i < 2; ++i)
        #pragma unroll
        for (int j = 0; j < 8; ++j)
            #pragma unroll
            for (int c = 0; c < 4; ++c) acc[i][j][c] = 0.f;

    load_tile(0, 0);
    if (KT > 1) load_tile(1, 1);

    int s = 0;
    #pragma unroll 1
    for (int kt = 0; kt < KT; ++kt) {
        const int rem = KT - 1 - kt;
        if (rem >= 2) {
            int sp2 = s - 1; if (sp2 < 0) sp2 = 2;     // (s+2)%3
            load_tile(kt + 2, sp2);
            cp_wait<2>();
        } else if (rem == 1) {
            cp_wait<1>();
        } else {
            cp_wait<0>();
        }
        __syncthreads();

        const uint32_t aAh = aA0 + s * STAGE_BYTES;
        const uint32_t aBh = aB0 + s * STAGE_BYTES;

        #pragma unroll
        for (int ks = 0; ks < KSN; ++ks) {           // m16n8k16 K-steps per tile
            const uint32_t kx = (uint32_t)(ks * 32);  // XOR-step within swizzled row

            uint32_t ah[2][4], al[2][4];
            #pragma unroll
            for (int i = 0; i < 2; ++i) {
                const uint32_t a0 = (aAh + (uint32_t)(i * 16 * ROWB)) ^ kx;
                ldmx4(ah[i][0], ah[i][1], ah[i][2], ah[i][3], a0);
                if (NTERMS == 3)
                    ldmx4(al[i][0], al[i][1], al[i][2], al[i][3], a0 + TILE_BYTES);
            }

            #pragma unroll
            for (int jh = 0; jh < 2; ++jh) {         // halves of 4 columns (reg pressure)
                uint32_t bh[4][2], bl[4][2];
                #pragma unroll
                for (int jp = 0; jp < 2; ++jp) {     // j-pairs: cols 8J..8J+15
                    const int J = jh * 4 + jp * 2;
                    const uint32_t b0 = (aBh + (uint32_t)(8 * J * ROWB)) ^ kx;
                    ldmx4(bh[2*jp][0], bh[2*jp][1], bh[2*jp+1][0], bh[2*jp+1][1], b0);
                    if (NTERMS == 3)
                        ldmx4(bl[2*jp][0], bl[2*jp][1], bl[2*jp+1][0], bl[2*jp+1][1],
                              b0 + TILE_BYTES);
                }
                #pragma unroll
                for (int i = 0; i < 2; ++i)
                    #pragma unroll
                    for (int j = 0; j < 4; ++j) {
                        float* c = acc[i][jh * 4 + j];
                        if (NTERMS == 3) {
                            mma_bf16(c, ah[i], bh[j]);       // hi*hi
                            mma_bf16(c, ah[i], bl[j]);       // hi*lo
                            mma_bf16(c, al[i], bh[j]);       // lo*hi
                        } else {
                            mma_f16(c, ah[i], bh[j]);        // fp16 single term
                        }
                    }
            }
        }
        __syncthreads();   // all warps done with stage s before loads reuse it
        s = (s == 2) ? 0 : s + 1;
    }

    // ---------------- epilogue ----------------
    const int gm = rowBase + 32 * warp_m;
    const int gn = colBase + 64 * warp_n + 2 * tig;

    if (MODE == 0) {
        // permuted columns: jj = part*2048 + h*256 + f ; part & head uniform per CTA
        const int part  = colBase >> 11;
        const int hh    = (colBase >> 8) & 7;
        const int fwarp = (colBase & 255) + 64 * warp_n + 2 * tig;
        const float scl = (part == 2) ? 1.0f : 0.0625f;

        #pragma unroll
        for (int i = 0; i < 2; ++i) {
            #pragma unroll
            for (int h = 0; h < 2; ++h) {
                const int m = gm + 16 * i + gid + 8 * h;
                const int b = m >> 11, t = m & (TLEN - 1);
                const size_t rowO = ((size_t)(b * NHEAD + hh) * TLEN + t) * FDIM;
                #pragma unroll
                for (int j = 0; j < 8; ++j) {
                    const int f0 = fwarp + 8 * j;
                    const int borig = hh * (FDIM * 3) + f0 * 3 + part;
                    const float v0 = (acc[i][j][2 * h]     + bias[borig])     * scl;
                    const float v1 = (acc[i][j][2 * h + 1] + bias[borig + 3]) * scl;
                    const uint32_t w = pack_f16(v0, v1);
                    if      (part == 0) *(uint32_t*)(g_Q  + rowO + f0) = w;
                    else if (part == 1) *(uint32_t*)(g_K  + rowO + f0) = w;
                    else                *(uint32_t*)(g_Vn + rowO + f0) = w;
                }
            }
        }
        return;
    }

    #pragma unroll
    for (int i = 0; i < 2; ++i) {
        #pragma unroll
        for (int h = 0; h < 2; ++h) {
            const int m = gm + 16 * i + gid + 8 * h;

            if (MODE == 1) {
                // e = exp(score) via ex2.approx.f16x2; store fp16; row partial sums
                const size_t ro = (size_t)z * TLEN * TLEN + (size_t)m * TLEN + gn;
                uint32_t* ph = (uint32_t*)(g_P + ro);
                const float l2e = 1.44269504089f;
                float rsum = 0.f;
                #pragma unroll
                for (int j = 0; j < 8; ++j) {
                    const uint32_t pe = pack_f16(acc[i][j][2 * h] * l2e,
                                                 acc[i][j][2 * h + 1] * l2e);
                    uint32_t e;
                    asm("ex2.approx.f16x2 %0, %1;" : "=r"(e) : "r"(pe));
                    ph[4 * j] = e;
                    const __half2 he = *(const __half2*)&e;
                    rsum += __half2float(he.x) + __half2float(he.y);
                }
                rsum += __shfl_xor_sync(0xffffffffu, rsum, 1);
                rsum += __shfl_xor_sync(0xffffffffu, rsum, 2);
                if (tig == 0) {
                    const int px = (colBase >> 6) + warp_n;   // 0..31
                    g_rsum[((size_t)z * TLEN + m) * 32 + px] = rsum;
                }
            } else if (MODE == 2) {
                const float inv = __ldg(&g_rinv[(size_t)z * TLEN + m]);
                const int b = z >> 3, hh = z & 7;
                const size_t base = ((size_t)(b * TLEN + m)) * (NHEAD * FDIM) + hh * FDIM + gn;
                #pragma unroll
                for (int j = 0; j < 8; ++j)
                    *(uint32_t*)(g_a + base + 8 * j) =
                        pack_f16(acc[i][j][2 * h] * inv, acc[i][j][2 * h + 1] * inv);
            } else {
                float* p = g_p3 + (size_t)z * (8192 * FDIM) + (size_t)m * FDIM + gn;
                #pragma unroll
                for (int j = 0; j < 8; ++j)
                    *(float2*)(p + 8 * j) = make_float2(acc[i][j][2 * h], acc[i][j][2 * h + 1]);
            }
        }
    }
}

// ---------------- row inverse-sum: 65536 rows x 32 partials ----------------
__global__ void __launch_bounds__(256) rinv_kernel()
{
    const int r = blockIdx.x * 256 + threadIdx.x;
    const float4* p = (const float4*)(g_rsum + (size_t)r * 32);
    float s = 0.f;
    #pragma unroll
    for (int i = 0; i < 8; ++i) {
        const float4 v = p[i];
        s += (v.x + v.y) + (v.z + v.w);
    }
    g_rinv[r] = 1.0f / s;
}

// ---------------- split-K combine: out = p3[0] + p3[1] + bias ----------------
__global__ void __launch_bounds__(256) combine_kernel(const float* __restrict__ bias,
                                                      float* __restrict__ out)
{
    const size_t i = ((size_t)blockIdx.x * 256 + threadIdx.x) * 4;
    const int col = (int)(i & (FDIM - 1));
    const float4 a = *(const float4*)(g_p3 + i);
    const float4 b = *(const float4*)(g_p3 + (size_t)8192 * FDIM + i);
    const float4 bv = *(const float4*)(bias + col);
    float4 o;
    o.x = a.x + b.x + bv.x;
    o.y = a.y + b.y + bv.y;
    o.z = a.z + b.z + bv.z;
    o.w = a.w + b.w + bv.w;
    *(float4*)(out + i) = o;
}

// ---------------- input split: x -> bf16 h/l + fp16 ----------------
__global__ void __launch_bounds__(256) split_x_kernel(const float* __restrict__ x)
{
    const size_t i = ((size_t)blockIdx.x * 256 + threadIdx.x) * 4;
    const float4 v = *(const float4*)(x + i);
    uint32_t h0, l0, h1, l1;
    split_pair(make_float2(v.x, v.y), h0, l0);
    split_pair(make_float2(v.z, v.w), h1, l1);
    *(uint32_t*)(g_xh + i)     = h0;
    *(uint32_t*)(g_xh + i + 2) = h1;
    *(uint32_t*)(g_xl + i)     = l0;
    *(uint32_t*)(g_xl + i + 2) = l1;
    *(uint32_t*)(g_xf + i)     = pack_f16(v.x, v.y);
    *(uint32_t*)(g_xf + i + 2) = pack_f16(v.z, v.w);
}

// ---------------- W_qkv transpose + column permutation + split (bf16 h+l, fp16) ----------------
__global__ void __launch_bounds__(256) wqkv_prep_kernel(const float* __restrict__ in)
{
    __shared__ float t[32][33];
    const int c0 = blockIdx.x * 32;
    const int r0 = blockIdx.y * 32;
    const int tx = threadIdx.x, ty = threadIdx.y;
    #pragma unroll
    for (int i = 0; i < 32; i += 8)
        t[ty + i][tx] = in[(size_t)(r0 + ty + i) * (NHEAD * FDIM * 3) + c0 + tx];
    __syncthreads();
    #pragma unroll
    for (int i = 0; i < 32; i += 8) {
        const int corig = c0 + ty + i;
        const int hh  = corig / (FDIM * 3);
        const int rem = corig - hh * (FDIM * 3);
        const int f   = rem / 3;
        const int prt = rem - f * 3;
        const int cnew = prt * (NHEAD * FDIM) + hh * FDIM + f;
        const float val = t[tx][ty + i];
        bf16 vh, vl;
        split1(val, vh, vl);
        g_Wqh[(size_t)cnew * FDIM + r0 + tx] = vh;
        g_Wql[(size_t)cnew * FDIM + r0 + tx] = vl;
        g_Wqf[(size_t)cnew * FDIM + r0 + tx] = __float2half(val);
    }
}

// ---------------- W_proj transpose -> fp16: [2048][256] -> [256][2048] ----------------
__global__ void __launch_bounds__(256) wproj_prep_kernel(const float* __restrict__ in)
{
    __shared__ float t[32][33];
    const int c0 = blockIdx.x * 32;
    const int r0 = blockIdx.y * 32;
    const int tx = threadIdx.x, ty = threadIdx.y;
    #pragma unroll
    for (int i = 0; i < 32; i += 8)
        t[ty + i][tx] = in[(size_t)(r0 + ty + i) * FDIM + c0 + tx];
    __syncthreads();
    #pragma unroll
    for (int i = 0; i < 32; i += 8)
        g_Wp[(size_t)(c0 + ty + i) * (NHEAD * FDIM) + r0 + tx] = __float2half(t[tx][ty + i]);
}

// ---------------- V transpose: [bh][t][f] -> [bh][f][t] (fp16) ----------------
__global__ void __launch_bounds__(256) vtrans_kernel()
{
    __shared__ fp16 th[32][33];
    const int bh = blockIdx.z;
    const int f0 = blockIdx.x * 32;
    const int t0 = blockIdx.y * 32;
    const int tx = threadIdx.x, ty = threadIdx.y;
    const size_t inb = ((size_t)bh * TLEN + t0) * FDIM + f0;
    #pragma unroll
    for (int i = 0; i < 32; i += 8)
        th[ty + i][tx] = g_Vn[inb + (size_t)(ty + i) * FDIM + tx];
    __syncthreads();
    const size_t outb = ((size_t)bh * FDIM + f0) * TLEN + t0;
    #pragma unroll
    for (int i = 0; i < 32; i += 8)
        g_Vt[outb + (size_t)(ty + i) * TLEN + tx] = th[tx][ty + i];
}

// ---------------- launch ----------------
extern "C" void kernel_launch(void* const* d_in, const int* in_sizes, int n_in,
                              void* d_out, int out_size)
{
    const float* x     = (const float*)d_in[0];
    const float* Wqkv  = (const float*)d_in[1];
    const float* bqkv  = (const float*)d_in[2];
    const float* Wproj = (const float*)d_in[3];
    const float* bproj = (const float*)d_in[4];
    float* out = (float*)d_out;

    // one-time host-side setup (no device memory allocation)
    static cudaStream_t s2 = nullptr;
    static cudaEvent_t evFork = nullptr, evJoin = nullptr;
    if (!s2) {
        cudaStreamCreateWithFlags(&s2, cudaStreamNonBlocking);
        cudaEventCreateWithFlags(&evFork, cudaEventDisableTiming);
        cudaEventCreateWithFlags(&evJoin, cudaEventDisableTiming);
        cudaFuncSetAttribute(mma_gemm<0,1>, cudaFuncAttributeMaxDynamicSharedMemorySize, SMEM_NEED);
        cudaFuncSetAttribute(mma_gemm<0,3>, cudaFuncAttributeMaxDynamicSharedMemorySize, SMEM_NEED);
        cudaFuncSetAttribute(mma_gemm<1,1>, cudaFuncAttributeMaxDynamicSharedMemorySize, SMEM_NEED);
        cudaFuncSetAttribute(mma_gemm<2,1>, cudaFuncAttributeMaxDynamicSharedMemorySize, SMEM_NEED);
        cudaFuncSetAttribute(mma_gemm<3,1>, cudaFuncAttributeMaxDynamicSharedMemorySize, SMEM_NEED);
    }

    // prep (main stream): split x; W_qkv transpose/permute/split
    split_x_kernel<<<(NBATCH * TLEN * FDIM) / 1024, 256>>>(x);
    wqkv_prep_kernel<<<dim3(6144 / 32, 256 / 32), dim3(32, 8)>>>(Wqkv);

    // fork side stream (chain B: V path + Wproj prep)
    cudaEventRecord(evFork, 0);
    cudaStreamWaitEvent(s2, evFork, 0);

    // chain B (side stream): V GEMM (bf16 3-term) -> Vn, transpose -> Vt, Wproj prep
    mma_gemm<0,3><<<dim3(2048 / BN, 8192 / BM, 1), 256, SMEM_NEED, s2>>>(bqkv, nullptr, 4096);
    vtrans_kernel<<<dim3(FDIM / 32, TLEN / 32, NBH), dim3(32, 8), 0, s2>>>();
    wproj_prep_kernel<<<dim3(256 / 32, 2048 / 32), dim3(32, 8), 0, s2>>>(Wproj);
    cudaEventRecord(evJoin, s2);

    // chain A (main stream): QK GEMM -> Q/K, P = exp(QK^T), rowsum inverse
    mma_gemm<0,1><<<dim3(4096 / BN, 8192 / BM, 1), 256, SMEM_NEED>>>(bqkv, nullptr, 0);
    mma_gemm<1,1><<<dim3(TLEN / BN, TLEN / BM, NBH), 256, SMEM_NEED>>>(nullptr, nullptr, 0);
    rinv_kernel<<<(NBH * TLEN) / 256, 256>>>();

    // join: mode-2 needs P + rinv (chain A) and Vt (chain B)
    cudaStreamWaitEvent(0, evJoin, 0);

    // attn = (P V) * rinv -> fp16
    mma_gemm<2,1><<<dim3(FDIM / BN, TLEN / BM, NBH), 256, SMEM_NEED>>>(nullptr, nullptr, 0);
    // proj split-K x2 -> fp32 partials
    mma_gemm<3,1><<<dim3(FDIM / BN, 8192 / BM, 2), 256, SMEM_NEED>>>(nullptr, nullptr, 0);
    // combine + bias -> fp32 out
    combine_kernel<<<(8192 * FDIM) / 1024, 256>>>(bproj, out);
}